// round 1
// baseline (speedup 1.0000x reference)
#include <cuda_runtime.h>
#include <math.h>

// Problem constants
#define S_LEN 2048
#define D_DIM 2048
#define B_SZ  2
#define NH    16
#define HD    128
#define M_FF  8192
#define ROWS  (B_SZ * S_LEN)   // 4096

// -------------------- scratch (device globals; no allocation allowed) -----
__device__ float g_h   [ROWS * D_DIM];   // LN output (reused for ln1 and ln2)
__device__ float g_q   [ROWS * D_DIM];
__device__ float g_k   [ROWS * D_DIM];
__device__ float g_v   [ROWS * D_DIM];
__device__ float g_attn[ROWS * D_DIM];
__device__ float g_x2  [ROWS * D_DIM];   // x + attn@Wo
__device__ float g_ff  [ROWS * M_FF];    // relu(h2@W1+b1)

// ===========================================================================
// LayerNorm: one block per row, 256 threads, 8 elems/thread (D=2048)
// ===========================================================================
__global__ __launch_bounds__(256)
void ln_kernel(const float* __restrict__ x, const float* __restrict__ gam,
               const float* __restrict__ bet, float* __restrict__ out)
{
    __shared__ float red[8];
    const int row = blockIdx.x;
    const int tid = threadIdx.x;
    const float* xr = x + (size_t)row * D_DIM;
    float* orow = out + (size_t)row * D_DIM;

    float v[8];
    float s = 0.f;
#pragma unroll
    for (int i = 0; i < 8; ++i) { v[i] = xr[tid + 256 * i]; s += v[i]; }

#pragma unroll
    for (int d = 16; d > 0; d >>= 1) s += __shfl_xor_sync(0xffffffffu, s, d);
    if ((tid & 31) == 0) red[tid >> 5] = s;
    __syncthreads();
    float tot = 0.f;
#pragma unroll
    for (int i = 0; i < 8; ++i) tot += red[i];
    const float mean = tot * (1.0f / (float)D_DIM);

    float s2 = 0.f;
#pragma unroll
    for (int i = 0; i < 8; ++i) { float d = v[i] - mean; s2 += d * d; }
    __syncthreads();   // protect red[] reuse
#pragma unroll
    for (int d = 16; d > 0; d >>= 1) s2 += __shfl_xor_sync(0xffffffffu, s2, d);
    if ((tid & 31) == 0) red[tid >> 5] = s2;
    __syncthreads();
    tot = 0.f;
#pragma unroll
    for (int i = 0; i < 8; ++i) tot += red[i];
    const float rstd = rsqrtf(tot * (1.0f / (float)D_DIM) + 1e-5f);

#pragma unroll
    for (int i = 0; i < 8; ++i) {
        int c = tid + 256 * i;
        orow[c] = (v[i] - mean) * rstd * gam[c] + bet[c];
    }
}

// ===========================================================================
// SGEMM: C[M,N] = A[M,K] @ B[K,N] (+bias, relu, +residual)
// 128x128 block tile, BK=8, 256 threads, 8x8 per-thread, reg prefetch.
// All dims are multiples of 128 / K multiple of 8 in this problem.
// ===========================================================================
template<bool RELU, bool HAS_BIAS, bool HAS_RES>
__global__ __launch_bounds__(256, 2)
void sgemm_kernel(const float* __restrict__ A, const float* __restrict__ B,
                  const float* __restrict__ bias, const float* __restrict__ res,
                  float* __restrict__ C, int Md, int Nd, int Kd)
{
    __shared__ float As[8][132];   // transposed A tile (k-major), padded
    __shared__ float Bs[8][132];   // B tile, padded (132 floats = 528B, 16B aligned)

    const int tid = threadIdx.x;
    const int tx = tid & 15;       // 0..15 -> N
    const int ty = tid >> 4;       // 0..15 -> M
    const int bx = blockIdx.x, by = blockIdx.y;

    const int arow = tid >> 1;          // 0..127
    const int acol = (tid & 1) << 2;    // 0 or 4
    const int brow = tid >> 5;          // 0..7
    const int bcol = (tid & 31) << 2;   // 0..124

    const float* Aptr = A + (by * 128 + arow) * Kd + acol;
    const float* Bptr = B + brow * Nd + bx * 128 + bcol;

    float4 aReg = *(const float4*)Aptr;
    float4 bReg = *(const float4*)Bptr;

    float acc[8][8];
#pragma unroll
    for (int i = 0; i < 8; ++i)
#pragma unroll
        for (int j = 0; j < 8; ++j) acc[i][j] = 0.f;

    const int ktiles = Kd >> 3;
    for (int t = 0; t < ktiles; ++t) {
        // store staged regs -> smem (transposed A store is conflict-free w/ pad)
        As[acol + 0][arow] = aReg.x;
        As[acol + 1][arow] = aReg.y;
        As[acol + 2][arow] = aReg.z;
        As[acol + 3][arow] = aReg.w;
        *(float4*)&Bs[brow][bcol] = bReg;
        __syncthreads();

        if (t + 1 < ktiles) {   // prefetch next tile into regs (hides gmem lat)
            aReg = *(const float4*)(Aptr + (t + 1) * 8);
            bReg = *(const float4*)(Bptr + (t + 1) * 8 * Nd);
        }

#pragma unroll
        for (int kk = 0; kk < 8; ++kk) {
            float4 m0 = *(const float4*)&As[kk][ty * 8];
            float4 m1 = *(const float4*)&As[kk][ty * 8 + 4];
            float4 n0 = *(const float4*)&Bs[kk][tx * 8];
            float4 n1 = *(const float4*)&Bs[kk][tx * 8 + 4];
            float rm[8] = {m0.x, m0.y, m0.z, m0.w, m1.x, m1.y, m1.z, m1.w};
            float rn[8] = {n0.x, n0.y, n0.z, n0.w, n1.x, n1.y, n1.z, n1.w};
#pragma unroll
            for (int i = 0; i < 8; ++i)
#pragma unroll
                for (int j = 0; j < 8; ++j)
                    acc[i][j] += rm[i] * rn[j];
        }
        __syncthreads();
    }

    // epilogue
    const int row0 = by * 128 + ty * 8;
    const int col0 = bx * 128 + tx * 8;
    float bv[8];
#pragma unroll
    for (int j = 0; j < 8; ++j) bv[j] = HAS_BIAS ? bias[col0 + j] : 0.f;

#pragma unroll
    for (int i = 0; i < 8; ++i) {
        const int row = row0 + i;
        float outv[8];
#pragma unroll
        for (int j = 0; j < 8; ++j) {
            float vv = acc[i][j];
            if (HAS_BIAS) vv += bv[j];
            if (RELU)     vv = fmaxf(vv, 0.f);
            outv[j] = vv;
        }
        if (HAS_RES) {
            float4 r0 = *(const float4*)(res + (size_t)row * Nd + col0);
            float4 r1 = *(const float4*)(res + (size_t)row * Nd + col0 + 4);
            outv[0] += r0.x; outv[1] += r0.y; outv[2] += r0.z; outv[3] += r0.w;
            outv[4] += r1.x; outv[5] += r1.y; outv[6] += r1.z; outv[7] += r1.w;
        }
        float4 w0 = make_float4(outv[0], outv[1], outv[2], outv[3]);
        float4 w1 = make_float4(outv[4], outv[5], outv[6], outv[7]);
        *(float4*)(C + (size_t)row * Nd + col0)     = w0;
        *(float4*)(C + (size_t)row * Nd + col0 + 4) = w1;
    }
}

// ===========================================================================
// Flash attention (fp32). Reshape quirk: head h of batch b is the contiguous
// (2048 x 128) block at offset ((b*16+h)*2048*128) of Q/K/V.
// Causal mask in that index space; masked entries get -1e9 *then* /sqrt(d).
// Output written as out[b, i, h*128 + c]  (standard head concat).
// Block: one (qtile=64 rows, head, batch). 256 threads = 16x16.
// ===========================================================================
#define ATT_QSTF (128 * 68)
#define ATT_KSTF (128 * 68)
#define ATT_VSF  (64 * 132)
#define ATT_PSTF (64 * 68)
#define ATT_SMEM_BYTES ((ATT_QSTF + ATT_KSTF + ATT_VSF + ATT_PSTF) * 4)

__global__ __launch_bounds__(256)
void attn_kernel(const float* __restrict__ Q, const float* __restrict__ K,
                 const float* __restrict__ V, float* __restrict__ O)
{
    extern __shared__ float sm[];
    float* QsT = sm;                            // [k=128][row pad 68]
    float* KsT = sm + ATT_QSTF;                 // [k=128][row pad 68]
    float* Vs  = sm + ATT_QSTF + ATT_KSTF;      // [row=64][col pad 132]
    float* PsT = sm + ATT_QSTF + ATT_KSTF + ATT_VSF; // [j=64][i pad 68]

    const int qt   = blockIdx.x;   // 0..31
    const int head = blockIdx.y;   // 0..15
    const int b    = blockIdx.z;   // 0..1
    const int tid  = threadIdx.x;
    const int tx   = tid & 15;     // cols
    const int ty   = tid >> 4;     // rows

    const int hoff = (b * NH + head) * (S_LEN * HD);
    const float* Qh = Q + hoff;
    const float* Kh = K + hoff;
    const float* Vh = V + hoff;
    const int i0 = qt * 64;

    // Load Q tile (64x128) transposed into QsT
#pragma unroll
    for (int r = 0; r < 8; ++r) {
        int f4  = tid + r * 256;        // 0..2047
        int row = f4 >> 5;              // 0..63
        int col = (f4 & 31) << 2;       // 0..124
        float4 v4 = *(const float4*)(Qh + (i0 + row) * HD + col);
        QsT[(col + 0) * 68 + row] = v4.x;
        QsT[(col + 1) * 68 + row] = v4.y;
        QsT[(col + 2) * 68 + row] = v4.z;
        QsT[(col + 3) * 68 + row] = v4.w;
    }

    float o_acc[4][8];
#pragma unroll
    for (int i = 0; i < 4; ++i)
#pragma unroll
        for (int c = 0; c < 8; ++c) o_acc[i][c] = 0.f;
    float m_run[4] = {-1e30f, -1e30f, -1e30f, -1e30f};
    float l_run[4] = {0.f, 0.f, 0.f, 0.f};

    const float inv_sqrt_d = 0.08838834764831845f;  // 1/sqrt(128)

    for (int jt = 0; jt <= qt; ++jt) {
        const int j0 = jt * 64;
        // Load K (transposed) and V tiles
#pragma unroll
        for (int r = 0; r < 8; ++r) {
            int f4  = tid + r * 256;
            int row = f4 >> 5;
            int col = (f4 & 31) << 2;
            float4 kv = *(const float4*)(Kh + (j0 + row) * HD + col);
            KsT[(col + 0) * 68 + row] = kv.x;
            KsT[(col + 1) * 68 + row] = kv.y;
            KsT[(col + 2) * 68 + row] = kv.z;
            KsT[(col + 3) * 68 + row] = kv.w;
            float4 vv = *(const float4*)(Vh + (j0 + row) * HD + col);
            *(float4*)&Vs[row * 132 + col] = vv;
        }
        __syncthreads();

        // S = Q K^T  (64x64 tile; 4x4 per thread)
        float sacc[4][4];
#pragma unroll
        for (int i = 0; i < 4; ++i)
#pragma unroll
            for (int j = 0; j < 4; ++j) sacc[i][j] = 0.f;

#pragma unroll 4
        for (int kk = 0; kk < 128; ++kk) {
            float4 qr = *(const float4*)&QsT[kk * 68 + ty * 4];
            float4 kr = *(const float4*)&KsT[kk * 68 + tx * 4];
            float qa[4] = {qr.x, qr.y, qr.z, qr.w};
            float ka[4] = {kr.x, kr.y, kr.z, kr.w};
#pragma unroll
            for (int i = 0; i < 4; ++i)
#pragma unroll
                for (int j = 0; j < 4; ++j)
                    sacc[i][j] += qa[i] * ka[j];
        }

        const bool diag = (jt == qt);
#pragma unroll
        for (int ii = 0; ii < 4; ++ii) {
            const int gi = i0 + ty * 4 + ii;
            float rowm = -1e30f;
#pragma unroll
            for (int jj = 0; jj < 4; ++jj) {
                float sv = sacc[ii][jj];
                if (diag && (j0 + tx * 4 + jj) > gi) sv = -1e9f;  // mask BEFORE scale
                sv *= inv_sqrt_d;
                sacc[ii][jj] = sv;
                rowm = fmaxf(rowm, sv);
            }
#pragma unroll
            for (int d = 1; d < 16; d <<= 1)
                rowm = fmaxf(rowm, __shfl_xor_sync(0xffffffffu, rowm, d));
            float mnew = fmaxf(m_run[ii], rowm);
            float corr = __expf(m_run[ii] - mnew);
            m_run[ii] = mnew;
            float rs = 0.f;
#pragma unroll
            for (int jj = 0; jj < 4; ++jj) {
                float p = __expf(sacc[ii][jj] - mnew);
                sacc[ii][jj] = p;
                rs += p;
            }
#pragma unroll
            for (int d = 1; d < 16; d <<= 1)
                rs += __shfl_xor_sync(0xffffffffu, rs, d);
            l_run[ii] = l_run[ii] * corr + rs;
#pragma unroll
            for (int cc = 0; cc < 8; ++cc) o_acc[ii][cc] *= corr;
        }

        // store P transposed for conflict-light PV
#pragma unroll
        for (int ii = 0; ii < 4; ++ii)
#pragma unroll
            for (int jj = 0; jj < 4; ++jj)
                PsT[(tx * 4 + jj) * 68 + (ty * 4 + ii)] = sacc[ii][jj];
        __syncthreads();

        // O += P V   (k = 64 kv positions)
#pragma unroll 2
        for (int jk = 0; jk < 64; ++jk) {
            float4 pr = *(const float4*)&PsT[jk * 68 + ty * 4];
            float4 v0 = *(const float4*)&Vs[jk * 132 + tx * 8];
            float4 v1 = *(const float4*)&Vs[jk * 132 + tx * 8 + 4];
            float pa[4] = {pr.x, pr.y, pr.z, pr.w};
            float va[8] = {v0.x, v0.y, v0.z, v0.w, v1.x, v1.y, v1.z, v1.w};
#pragma unroll
            for (int ii = 0; ii < 4; ++ii)
#pragma unroll
                for (int cc = 0; cc < 8; ++cc)
                    o_acc[ii][cc] += pa[ii] * va[cc];
        }
        __syncthreads();
    }

    // normalize + write: out[b, i, head*128 + c]
#pragma unroll
    for (int ii = 0; ii < 4; ++ii) {
        const float linv = 1.0f / l_run[ii];
        const int row = i0 + ty * 4 + ii;
        float* op = O + ((size_t)b * S_LEN + row) * D_DIM + head * HD + tx * 8;
        float4 w0 = make_float4(o_acc[ii][0] * linv, o_acc[ii][1] * linv,
                                o_acc[ii][2] * linv, o_acc[ii][3] * linv);
        float4 w1 = make_float4(o_acc[ii][4] * linv, o_acc[ii][5] * linv,
                                o_acc[ii][6] * linv, o_acc[ii][7] * linv);
        *(float4*)op       = w0;
        *(float4*)(op + 4) = w1;
    }
}

// ===========================================================================
// Launch
// ===========================================================================
extern "C" void kernel_launch(void* const* d_in, const int* in_sizes, int n_in,
                              void* d_out, int out_size)
{
    (void)in_sizes; (void)n_in; (void)out_size;
    const float* x    = (const float*)d_in[0];
    // d_in[1] = causal mask (bool) — structure is known, ignored
    const float* Wq   = (const float*)d_in[2];
    const float* Wk   = (const float*)d_in[3];
    const float* Wv   = (const float*)d_in[4];
    const float* Wo   = (const float*)d_in[5];
    const float* ln1g = (const float*)d_in[6];
    const float* ln1b = (const float*)d_in[7];
    const float* W1   = (const float*)d_in[8];
    const float* b1   = (const float*)d_in[9];
    const float* W2   = (const float*)d_in[10];
    const float* b2   = (const float*)d_in[11];
    const float* ln2g = (const float*)d_in[12];
    const float* ln2b = (const float*)d_in[13];
    float* out = (float*)d_out;

    float *h, *q, *k, *v, *attn, *x2, *ff;
    cudaGetSymbolAddress((void**)&h,    g_h);
    cudaGetSymbolAddress((void**)&q,    g_q);
    cudaGetSymbolAddress((void**)&k,    g_k);
    cudaGetSymbolAddress((void**)&v,    g_v);
    cudaGetSymbolAddress((void**)&attn, g_attn);
    cudaGetSymbolAddress((void**)&x2,   g_x2);
    cudaGetSymbolAddress((void**)&ff,   g_ff);

    cudaFuncSetAttribute(attn_kernel,
                         cudaFuncAttributeMaxDynamicSharedMemorySize,
                         ATT_SMEM_BYTES);

    const dim3 blk(256);
    const dim3 gDD(D_DIM / 128, ROWS / 128);   // (16, 32)
    const dim3 gDM(M_FF / 128,  ROWS / 128);   // (64, 32)

    // h = LN1(x)
    ln_kernel<<<ROWS, blk>>>(x, ln1g, ln1b, h);
    // q/k/v = h @ W{q,k,v}
    sgemm_kernel<false, false, false><<<gDD, blk>>>(h, Wq, nullptr, nullptr, q, ROWS, D_DIM, D_DIM);
    sgemm_kernel<false, false, false><<<gDD, blk>>>(h, Wk, nullptr, nullptr, k, ROWS, D_DIM, D_DIM);
    sgemm_kernel<false, false, false><<<gDD, blk>>>(h, Wv, nullptr, nullptr, v, ROWS, D_DIM, D_DIM);
    // attention
    attn_kernel<<<dim3(S_LEN / 64, NH, B_SZ), blk, ATT_SMEM_BYTES>>>(q, k, v, attn);
    // x2 = x + attn @ Wo
    sgemm_kernel<false, false, true><<<gDD, blk>>>(attn, Wo, nullptr, x, x2, ROWS, D_DIM, D_DIM);
    // h = LN2(x2)
    ln_kernel<<<ROWS, blk>>>(x2, ln2g, ln2b, h);
    // ff = relu(h @ W1 + b1)
    sgemm_kernel<true, true, false><<<gDM, blk>>>(h, W1, b1, nullptr, ff, ROWS, M_FF, D_DIM);
    // out = x2 + ff @ W2 + b2
    sgemm_kernel<false, true, true><<<gDD, blk>>>(ff, W2, b2, x2, out, ROWS, D_DIM, M_FF);
}

// round 2
// speedup vs baseline: 1.2211x; 1.2211x over previous
#include <cuda_runtime.h>
#include <cstdint>
#include <math.h>

// Problem constants
#define S_LEN 2048
#define D_DIM 2048
#define B_SZ  2
#define NH    16
#define HD    128
#define M_FF  8192
#define ROWS  (B_SZ * S_LEN)   // 4096

// -------------------- scratch (device globals; no allocation allowed) -----
__device__ float g_h   [ROWS * D_DIM];
__device__ float g_q   [ROWS * D_DIM];
__device__ float g_k   [ROWS * D_DIM];
__device__ float g_v   [ROWS * D_DIM];
__device__ float g_attn[ROWS * D_DIM];
__device__ float g_x2  [ROWS * D_DIM];
__device__ float g_ff  [ROWS * M_FF];

// ===========================================================================
// LayerNorm: one block per row, 256 threads, 8 elems/thread (D=2048)
// ===========================================================================
__global__ __launch_bounds__(256)
void ln_kernel(const float* __restrict__ x, const float* __restrict__ gam,
               const float* __restrict__ bet, float* __restrict__ out)
{
    __shared__ float red[8];
    const int row = blockIdx.x;
    const int tid = threadIdx.x;
    const float* xr = x + (size_t)row * D_DIM;
    float* orow = out + (size_t)row * D_DIM;

    float v[8];
    float s = 0.f;
#pragma unroll
    for (int i = 0; i < 8; ++i) { v[i] = xr[tid + 256 * i]; s += v[i]; }

#pragma unroll
    for (int d = 16; d > 0; d >>= 1) s += __shfl_xor_sync(0xffffffffu, s, d);
    if ((tid & 31) == 0) red[tid >> 5] = s;
    __syncthreads();
    float tot = 0.f;
#pragma unroll
    for (int i = 0; i < 8; ++i) tot += red[i];
    const float mean = tot * (1.0f / (float)D_DIM);

    float s2 = 0.f;
#pragma unroll
    for (int i = 0; i < 8; ++i) { float d = v[i] - mean; s2 += d * d; }
    __syncthreads();
#pragma unroll
    for (int d = 16; d > 0; d >>= 1) s2 += __shfl_xor_sync(0xffffffffu, s2, d);
    if ((tid & 31) == 0) red[tid >> 5] = s2;
    __syncthreads();
    tot = 0.f;
#pragma unroll
    for (int i = 0; i < 8; ++i) tot += red[i];
    const float rstd = rsqrtf(tot * (1.0f / (float)D_DIM) + 1e-5f);

#pragma unroll
    for (int i = 0; i < 8; ++i) {
        int c = tid + 256 * i;
        orow[c] = (v[i] - mean) * rstd * gam[c] + bet[c];
    }
}

// ===========================================================================
// 3xTF32 tensor-core SGEMM: C = A @ B (+bias, relu, +residual)
// fp32 in/out, fp32-grade accuracy via hi/lo tf32 split (3 mma passes).
// 128x128 CTA tile, BK=32, 256 threads, 8 warps (2M x 4N), warp tile 64x32.
// ===========================================================================
#define BKT 32
#define APAD 36     // floats per A smem row (BK=32 + pad), mult of 4
#define BPAD 136    // floats per B smem row (BN=128 + pad), mult of 4
#define SMEM_AF (128 * APAD)
#define SMEM_BF (BKT * BPAD)
#define GEMM_SMEM_BYTES ((2 * SMEM_AF + 2 * SMEM_BF) * 4)   // ~70 KB

__device__ __forceinline__ uint32_t f2tf32(float x) {
    uint32_t r;
    asm("cvt.rna.tf32.f32 %0, %1;" : "=r"(r) : "f"(x));
    return r;
}

__device__ __forceinline__ void mma1688(float* d, const uint32_t* a, const uint32_t* b) {
    asm volatile(
        "mma.sync.aligned.m16n8k8.row.col.f32.tf32.tf32.f32 "
        "{%0,%1,%2,%3}, {%4,%5,%6,%7}, {%8,%9}, {%0,%1,%2,%3};"
        : "+f"(d[0]), "+f"(d[1]), "+f"(d[2]), "+f"(d[3])
        : "r"(a[0]), "r"(a[1]), "r"(a[2]), "r"(a[3]), "r"(b[0]), "r"(b[1]));
}

template<bool RELU, bool HAS_BIAS, bool HAS_RES>
__global__ __launch_bounds__(256, 2)
void sgemm_tc_kernel(const float* __restrict__ A, const float* __restrict__ B,
                     const float* __restrict__ bias, const float* __restrict__ res,
                     float* __restrict__ C, int Nd, int Kd)
{
    extern __shared__ float sm[];
    float* Ah = sm;
    float* Al = sm + SMEM_AF;
    float* Bh = sm + 2 * SMEM_AF;
    float* Bl = sm + 2 * SMEM_AF + SMEM_BF;

    const int tid  = threadIdx.x;
    const int lane = tid & 31;
    const int warp = tid >> 5;
    const int wm   = warp & 1;       // 0..1  (M)
    const int wn   = warp >> 1;      // 0..3  (N)
    const int gid  = lane >> 2;      // 0..7
    const int tig  = lane & 3;       // 0..3
    const int bx = blockIdx.x, by = blockIdx.y;

    // gmem load mapping (float4 granularity)
    const int arow = tid >> 1;            // not used; per-r mapping below
    (void)arow;

    float4 aSt[4], bSt[4];
    // A: tile 128 x 32 -> 1024 float4; id = tid + 256*r; row=id>>3, col4=(id&7)*4
    // B: tile 32 x 128 -> 1024 float4; id = tid + 256*r; row=id>>5, col4=(id&31)*4
#pragma unroll
    for (int r = 0; r < 4; ++r) {
        int id = tid + 256 * r;
        int ar = id >> 3, ac = (id & 7) << 2;
        int br = id >> 5, bc = (id & 31) << 2;
        aSt[r] = *(const float4*)(A + (size_t)(by * 128 + ar) * Kd + ac);
        bSt[r] = *(const float4*)(B + (size_t)br * Nd + bx * 128 + bc);
    }

    float acc[4][4][4];
#pragma unroll
    for (int mt = 0; mt < 4; ++mt)
#pragma unroll
        for (int nt = 0; nt < 4; ++nt)
#pragma unroll
            for (int e = 0; e < 4; ++e) acc[mt][nt][e] = 0.f;

    const int ktiles = Kd / BKT;
    for (int t = 0; t < ktiles; ++t) {
        // split staged regs into hi/lo tf32 and store to smem (float4 STS)
#pragma unroll
        for (int r = 0; r < 4; ++r) {
            int id = tid + 256 * r;
            int ar = id >> 3, ac = (id & 7) << 2;
            int br = id >> 5, bc = (id & 31) << 2;
            float av[4] = {aSt[r].x, aSt[r].y, aSt[r].z, aSt[r].w};
            float bv[4] = {bSt[r].x, bSt[r].y, bSt[r].z, bSt[r].w};
            float4 ah4, al4, bh4, bl4;
            float* ahp = &ah4.x; float* alp = &al4.x;
            float* bhp = &bh4.x; float* blp = &bl4.x;
#pragma unroll
            for (int e = 0; e < 4; ++e) {
                uint32_t hb = f2tf32(av[e]);
                float hf = __uint_as_float(hb);
                ahp[e] = hf;
                alp[e] = __uint_as_float(f2tf32(av[e] - hf));
                uint32_t hb2 = f2tf32(bv[e]);
                float hf2 = __uint_as_float(hb2);
                bhp[e] = hf2;
                blp[e] = __uint_as_float(f2tf32(bv[e] - hf2));
            }
            *(float4*)&Ah[ar * APAD + ac] = ah4;
            *(float4*)&Al[ar * APAD + ac] = al4;
            *(float4*)&Bh[br * BPAD + bc] = bh4;
            *(float4*)&Bl[br * BPAD + bc] = bl4;
        }
        __syncthreads();

        if (t + 1 < ktiles) {
#pragma unroll
            for (int r = 0; r < 4; ++r) {
                int id = tid + 256 * r;
                int ar = id >> 3, ac = (id & 7) << 2;
                int br = id >> 5, bc = (id & 31) << 2;
                aSt[r] = *(const float4*)(A + (size_t)(by * 128 + ar) * Kd + (t + 1) * BKT + ac);
                bSt[r] = *(const float4*)(B + (size_t)((t + 1) * BKT + br) * Nd + bx * 128 + bc);
            }
        }

#pragma unroll
        for (int ks = 0; ks < 4; ++ks) {
            const int k0 = ks * 8;
            // B fragments for all 4 N tiles
            uint32_t bhF[4][2], blF[4][2];
#pragma unroll
            for (int nt = 0; nt < 4; ++nt) {
                int nc = wn * 32 + nt * 8 + gid;
                bhF[nt][0] = __float_as_uint(Bh[(k0 + tig) * BPAD + nc]);
                bhF[nt][1] = __float_as_uint(Bh[(k0 + tig + 4) * BPAD + nc]);
                blF[nt][0] = __float_as_uint(Bl[(k0 + tig) * BPAD + nc]);
                blF[nt][1] = __float_as_uint(Bl[(k0 + tig + 4) * BPAD + nc]);
            }
#pragma unroll
            for (int mt = 0; mt < 4; ++mt) {
                int r0 = wm * 64 + mt * 16;
                uint32_t ahF[4], alF[4];
                ahF[0] = __float_as_uint(Ah[(r0 + gid) * APAD + k0 + tig]);
                ahF[1] = __float_as_uint(Ah[(r0 + gid + 8) * APAD + k0 + tig]);
                ahF[2] = __float_as_uint(Ah[(r0 + gid) * APAD + k0 + tig + 4]);
                ahF[3] = __float_as_uint(Ah[(r0 + gid + 8) * APAD + k0 + tig + 4]);
                alF[0] = __float_as_uint(Al[(r0 + gid) * APAD + k0 + tig]);
                alF[1] = __float_as_uint(Al[(r0 + gid + 8) * APAD + k0 + tig]);
                alF[2] = __float_as_uint(Al[(r0 + gid) * APAD + k0 + tig + 4]);
                alF[3] = __float_as_uint(Al[(r0 + gid + 8) * APAD + k0 + tig + 4]);
#pragma unroll
                for (int nt = 0; nt < 4; ++nt) {
                    mma1688(acc[mt][nt], ahF, bhF[nt]);   // hi*hi
                    mma1688(acc[mt][nt], alF, bhF[nt]);   // lo*hi
                    mma1688(acc[mt][nt], ahF, blF[nt]);   // hi*lo
                }
            }
        }
        __syncthreads();
    }

    // epilogue: c0,c1 at (row, 2*tig .. +1); c2,c3 at (row+8, same cols)
#pragma unroll
    for (int nt = 0; nt < 4; ++nt) {
        const int col = bx * 128 + wn * 32 + nt * 8 + 2 * tig;
        float2 bv = make_float2(0.f, 0.f);
        if (HAS_BIAS) bv = *(const float2*)(bias + col);
#pragma unroll
        for (int mt = 0; mt < 4; ++mt) {
            const int row = by * 128 + wm * 64 + mt * 16 + gid;
#pragma unroll
            for (int half = 0; half < 2; ++half) {
                const int rr = row + half * 8;
                float o0 = acc[mt][nt][half * 2 + 0];
                float o1 = acc[mt][nt][half * 2 + 1];
                if (HAS_BIAS) { o0 += bv.x; o1 += bv.y; }
                if (RELU) { o0 = fmaxf(o0, 0.f); o1 = fmaxf(o1, 0.f); }
                if (HAS_RES) {
                    float2 rv = *(const float2*)(res + (size_t)rr * Nd + col);
                    o0 += rv.x; o1 += rv.y;
                }
                *(float2*)(C + (size_t)rr * Nd + col) = make_float2(o0, o1);
            }
        }
    }
}

// ===========================================================================
// Flash attention (fp32 FFMA). Head h of batch b is the contiguous
// (2048 x 128) block at offset ((b*16+h)*2048*128) of Q/K/V (reshape quirk).
// Mask applied BEFORE the 1/sqrt(d) scale, matching reference.
// ===========================================================================
#define ATT_QSTF (128 * 68)
#define ATT_KSTF (128 * 68)
#define ATT_VSF  (64 * 132)
#define ATT_PSTF (64 * 68)
#define ATT_SMEM_BYTES ((ATT_QSTF + ATT_KSTF + ATT_VSF + ATT_PSTF) * 4)

__global__ __launch_bounds__(256)
void attn_kernel(const float* __restrict__ Q, const float* __restrict__ K,
                 const float* __restrict__ V, float* __restrict__ O)
{
    extern __shared__ float sm[];
    float* QsT = sm;
    float* KsT = sm + ATT_QSTF;
    float* Vs  = sm + ATT_QSTF + ATT_KSTF;
    float* PsT = sm + ATT_QSTF + ATT_KSTF + ATT_VSF;

    const int qt   = blockIdx.x;
    const int head = blockIdx.y;
    const int b    = blockIdx.z;
    const int tid  = threadIdx.x;
    const int tx   = tid & 15;
    const int ty   = tid >> 4;

    const int hoff = (b * NH + head) * (S_LEN * HD);
    const float* Qh = Q + hoff;
    const float* Kh = K + hoff;
    const float* Vh = V + hoff;
    const int i0 = qt * 64;

#pragma unroll
    for (int r = 0; r < 8; ++r) {
        int f4  = tid + r * 256;
        int row = f4 >> 5;
        int col = (f4 & 31) << 2;
        float4 v4 = *(const float4*)(Qh + (i0 + row) * HD + col);
        QsT[(col + 0) * 68 + row] = v4.x;
        QsT[(col + 1) * 68 + row] = v4.y;
        QsT[(col + 2) * 68 + row] = v4.z;
        QsT[(col + 3) * 68 + row] = v4.w;
    }

    float o_acc[4][8];
#pragma unroll
    for (int i = 0; i < 4; ++i)
#pragma unroll
        for (int c = 0; c < 8; ++c) o_acc[i][c] = 0.f;
    float m_run[4] = {-1e30f, -1e30f, -1e30f, -1e30f};
    float l_run[4] = {0.f, 0.f, 0.f, 0.f};

    const float inv_sqrt_d = 0.08838834764831845f;

    for (int jt = 0; jt <= qt; ++jt) {
        const int j0 = jt * 64;
#pragma unroll
        for (int r = 0; r < 8; ++r) {
            int f4  = tid + r * 256;
            int row = f4 >> 5;
            int col = (f4 & 31) << 2;
            float4 kv = *(const float4*)(Kh + (j0 + row) * HD + col);
            KsT[(col + 0) * 68 + row] = kv.x;
            KsT[(col + 1) * 68 + row] = kv.y;
            KsT[(col + 2) * 68 + row] = kv.z;
            KsT[(col + 3) * 68 + row] = kv.w;
            float4 vv = *(const float4*)(Vh + (j0 + row) * HD + col);
            *(float4*)&Vs[row * 132 + col] = vv;
        }
        __syncthreads();

        float sacc[4][4];
#pragma unroll
        for (int i = 0; i < 4; ++i)
#pragma unroll
            for (int j = 0; j < 4; ++j) sacc[i][j] = 0.f;

#pragma unroll 4
        for (int kk = 0; kk < 128; ++kk) {
            float4 qr = *(const float4*)&QsT[kk * 68 + ty * 4];
            float4 kr = *(const float4*)&KsT[kk * 68 + tx * 4];
            float qa[4] = {qr.x, qr.y, qr.z, qr.w};
            float ka[4] = {kr.x, kr.y, kr.z, kr.w};
#pragma unroll
            for (int i = 0; i < 4; ++i)
#pragma unroll
                for (int j = 0; j < 4; ++j)
                    sacc[i][j] += qa[i] * ka[j];
        }

        const bool diag = (jt == qt);
#pragma unroll
        for (int ii = 0; ii < 4; ++ii) {
            const int gi = i0 + ty * 4 + ii;
            float rowm = -1e30f;
#pragma unroll
            for (int jj = 0; jj < 4; ++jj) {
                float sv = sacc[ii][jj];
                if (diag && (j0 + tx * 4 + jj) > gi) sv = -1e9f;
                sv *= inv_sqrt_d;
                sacc[ii][jj] = sv;
                rowm = fmaxf(rowm, sv);
            }
#pragma unroll
            for (int d = 1; d < 16; d <<= 1)
                rowm = fmaxf(rowm, __shfl_xor_sync(0xffffffffu, rowm, d));
            float mnew = fmaxf(m_run[ii], rowm);
            float corr = __expf(m_run[ii] - mnew);
            m_run[ii] = mnew;
            float rs = 0.f;
#pragma unroll
            for (int jj = 0; jj < 4; ++jj) {
                float p = __expf(sacc[ii][jj] - mnew);
                sacc[ii][jj] = p;
                rs += p;
            }
#pragma unroll
            for (int d = 1; d < 16; d <<= 1)
                rs += __shfl_xor_sync(0xffffffffu, rs, d);
            l_run[ii] = l_run[ii] * corr + rs;
#pragma unroll
            for (int cc = 0; cc < 8; ++cc) o_acc[ii][cc] *= corr;
        }

#pragma unroll
        for (int ii = 0; ii < 4; ++ii)
#pragma unroll
            for (int jj = 0; jj < 4; ++jj)
                PsT[(tx * 4 + jj) * 68 + (ty * 4 + ii)] = sacc[ii][jj];
        __syncthreads();

#pragma unroll 2
        for (int jk = 0; jk < 64; ++jk) {
            float4 pr = *(const float4*)&PsT[jk * 68 + ty * 4];
            float4 v0 = *(const float4*)&Vs[jk * 132 + tx * 8];
            float4 v1 = *(const float4*)&Vs[jk * 132 + tx * 8 + 4];
            float pa[4] = {pr.x, pr.y, pr.z, pr.w};
            float va[8] = {v0.x, v0.y, v0.z, v0.w, v1.x, v1.y, v1.z, v1.w};
#pragma unroll
            for (int ii = 0; ii < 4; ++ii)
#pragma unroll
                for (int cc = 0; cc < 8; ++cc)
                    o_acc[ii][cc] += pa[ii] * va[cc];
        }
        __syncthreads();
    }

#pragma unroll
    for (int ii = 0; ii < 4; ++ii) {
        const float linv = 1.0f / l_run[ii];
        const int row = i0 + ty * 4 + ii;
        float* op = O + ((size_t)b * S_LEN + row) * D_DIM + head * HD + tx * 8;
        float4 w0 = make_float4(o_acc[ii][0] * linv, o_acc[ii][1] * linv,
                                o_acc[ii][2] * linv, o_acc[ii][3] * linv);
        float4 w1 = make_float4(o_acc[ii][4] * linv, o_acc[ii][5] * linv,
                                o_acc[ii][6] * linv, o_acc[ii][7] * linv);
        *(float4*)op       = w0;
        *(float4*)(op + 4) = w1;
    }
}

// ===========================================================================
// Launch
// ===========================================================================
extern "C" void kernel_launch(void* const* d_in, const int* in_sizes, int n_in,
                              void* d_out, int out_size)
{
    (void)in_sizes; (void)n_in; (void)out_size;
    const float* x    = (const float*)d_in[0];
    const float* Wq   = (const float*)d_in[2];
    const float* Wk   = (const float*)d_in[3];
    const float* Wv   = (const float*)d_in[4];
    const float* Wo   = (const float*)d_in[5];
    const float* ln1g = (const float*)d_in[6];
    const float* ln1b = (const float*)d_in[7];
    const float* W1   = (const float*)d_in[8];
    const float* b1   = (const float*)d_in[9];
    const float* W2   = (const float*)d_in[10];
    const float* b2   = (const float*)d_in[11];
    const float* ln2g = (const float*)d_in[12];
    const float* ln2b = (const float*)d_in[13];
    float* out = (float*)d_out;

    float *h, *q, *k, *v, *attn, *x2, *ff;
    cudaGetSymbolAddress((void**)&h,    g_h);
    cudaGetSymbolAddress((void**)&q,    g_q);
    cudaGetSymbolAddress((void**)&k,    g_k);
    cudaGetSymbolAddress((void**)&v,    g_v);
    cudaGetSymbolAddress((void**)&attn, g_attn);
    cudaGetSymbolAddress((void**)&x2,   g_x2);
    cudaGetSymbolAddress((void**)&ff,   g_ff);

    cudaFuncSetAttribute(attn_kernel,
                         cudaFuncAttributeMaxDynamicSharedMemorySize,
                         ATT_SMEM_BYTES);
    cudaFuncSetAttribute(sgemm_tc_kernel<false, false, false>,
                         cudaFuncAttributeMaxDynamicSharedMemorySize, GEMM_SMEM_BYTES);
    cudaFuncSetAttribute(sgemm_tc_kernel<false, false, true>,
                         cudaFuncAttributeMaxDynamicSharedMemorySize, GEMM_SMEM_BYTES);
    cudaFuncSetAttribute(sgemm_tc_kernel<true, true, false>,
                         cudaFuncAttributeMaxDynamicSharedMemorySize, GEMM_SMEM_BYTES);
    cudaFuncSetAttribute(sgemm_tc_kernel<false, true, true>,
                         cudaFuncAttributeMaxDynamicSharedMemorySize, GEMM_SMEM_BYTES);

    const dim3 blk(256);
    const dim3 gDD(D_DIM / 128, ROWS / 128);   // (16, 32)
    const dim3 gDM(M_FF / 128,  ROWS / 128);   // (64, 32)

    ln_kernel<<<ROWS, blk>>>(x, ln1g, ln1b, h);
    sgemm_tc_kernel<false, false, false><<<gDD, blk, GEMM_SMEM_BYTES>>>(h, Wq, nullptr, nullptr, q, D_DIM, D_DIM);
    sgemm_tc_kernel<false, false, false><<<gDD, blk, GEMM_SMEM_BYTES>>>(h, Wk, nullptr, nullptr, k, D_DIM, D_DIM);
    sgemm_tc_kernel<false, false, false><<<gDD, blk, GEMM_SMEM_BYTES>>>(h, Wv, nullptr, nullptr, v, D_DIM, D_DIM);
    attn_kernel<<<dim3(S_LEN / 64, NH, B_SZ), blk, ATT_SMEM_BYTES>>>(q, k, v, attn);
    sgemm_tc_kernel<false, false, true><<<gDD, blk, GEMM_SMEM_BYTES>>>(attn, Wo, nullptr, x, x2, D_DIM, D_DIM);
    ln_kernel<<<ROWS, blk>>>(x2, ln2g, ln2b, h);
    sgemm_tc_kernel<true, true, false><<<gDM, blk, GEMM_SMEM_BYTES>>>(h, W1, b1, nullptr, ff, M_FF, D_DIM);
    sgemm_tc_kernel<false, true, true><<<gDD, blk, GEMM_SMEM_BYTES>>>(ff, W2, b2, x2, out, D_DIM, M_FF);
}

// round 6
// speedup vs baseline: 1.9343x; 1.5841x over previous
#include <cuda_runtime.h>
#include <cuda_bf16.h>
#include <cstdint>
#include <math.h>

// Problem constants
#define S_LEN 2048
#define D_DIM 2048
#define B_SZ  2
#define NH    16
#define HD    128
#define M_FF  8192
#define ROWS  (B_SZ * S_LEN)   // 4096

typedef __nv_bfloat16 bf16;

// -------------------- scratch (device globals; no allocation allowed) -----
__device__ __align__(16) bf16  g_h_hi  [ROWS * D_DIM];
__device__ __align__(16) bf16  g_h_lo  [ROWS * D_DIM];
__device__ __align__(16) float g_q     [ROWS * D_DIM];
__device__ __align__(16) float g_k     [ROWS * D_DIM];
__device__ __align__(16) float g_v     [ROWS * D_DIM];
__device__ __align__(16) bf16  g_at_hi [ROWS * D_DIM];
__device__ __align__(16) bf16  g_at_lo [ROWS * D_DIM];
__device__ __align__(16) float g_x2    [ROWS * D_DIM];
__device__ __align__(16) bf16  g_ff_hi [ROWS * M_FF];
__device__ __align__(16) bf16  g_ff_lo [ROWS * M_FF];
// transposed, split weights: [N][K] bf16
__device__ __align__(16) bf16  g_wqT_h [D_DIM * D_DIM];
__device__ __align__(16) bf16  g_wqT_l [D_DIM * D_DIM];
__device__ __align__(16) bf16  g_wkT_h [D_DIM * D_DIM];
__device__ __align__(16) bf16  g_wkT_l [D_DIM * D_DIM];
__device__ __align__(16) bf16  g_wvT_h [D_DIM * D_DIM];
__device__ __align__(16) bf16  g_wvT_l [D_DIM * D_DIM];
__device__ __align__(16) bf16  g_woT_h [D_DIM * D_DIM];
__device__ __align__(16) bf16  g_woT_l [D_DIM * D_DIM];
__device__ __align__(16) bf16  g_w1T_h [M_FF * D_DIM];
__device__ __align__(16) bf16  g_w1T_l [M_FF * D_DIM];
__device__ __align__(16) bf16  g_w2T_h [D_DIM * M_FF];
__device__ __align__(16) bf16  g_w2T_l [D_DIM * M_FF];

// ===========================================================================
// helpers
// ===========================================================================
__device__ __forceinline__ uint32_t smem_u32(const void* p) {
    uint32_t a;
    asm("{ .reg .u64 t; cvta.to.shared.u64 t, %1; cvt.u32.u64 %0, t; }" : "=r"(a) : "l"(p));
    return a;
}
__device__ __forceinline__ void cpa16(uint32_t dst, const void* src) {
    asm volatile("cp.async.cg.shared.global [%0], [%1], 16;" :: "r"(dst), "l"(src));
}
#define CP_COMMIT() asm volatile("cp.async.commit_group;" ::: "memory")
#define CP_WAIT1()  asm volatile("cp.async.wait_group 1;" ::: "memory")

__device__ __forceinline__ void ldmx4(uint32_t* r, uint32_t addr) {
    asm volatile("ldmatrix.sync.aligned.m8n8.x4.shared.b16 {%0,%1,%2,%3}, [%4];"
        : "=r"(r[0]), "=r"(r[1]), "=r"(r[2]), "=r"(r[3]) : "r"(addr));
}
__device__ __forceinline__ void mma_bf16(float* d, const uint32_t* a, uint32_t b0, uint32_t b1) {
    asm volatile(
        "mma.sync.aligned.m16n8k16.row.col.f32.bf16.bf16.f32 "
        "{%0,%1,%2,%3},{%4,%5,%6,%7},{%8,%9},{%0,%1,%2,%3};"
        : "+f"(d[0]), "+f"(d[1]), "+f"(d[2]), "+f"(d[3])
        : "r"(a[0]), "r"(a[1]), "r"(a[2]), "r"(a[3]), "r"(b0), "r"(b1));
}
__device__ __forceinline__ void split_bf(float v, bf16& h, bf16& l) {
    h = __float2bfloat16_rn(v);
    l = __float2bfloat16_rn(v - __bfloat162float(h));
}

// ===========================================================================
// transpose + split: in[R][C] fp32 -> out_hi/lo[C][R] bf16
// ===========================================================================
__global__ __launch_bounds__(256)
void transpose_split(const float* __restrict__ in, bf16* __restrict__ oh,
                     bf16* __restrict__ ol, int R, int C)
{
    __shared__ float tile[32][33];
    const int tx = threadIdx.x & 31;
    const int ty = threadIdx.x >> 5;
    const int bx = blockIdx.x * 32, by = blockIdx.y * 32;
#pragma unroll
    for (int j = 0; j < 32; j += 8)
        tile[ty + j][tx] = in[(size_t)(by + ty + j) * C + bx + tx];
    __syncthreads();
#pragma unroll
    for (int j = 0; j < 32; j += 8) {
        float v = tile[tx][ty + j];
        bf16 h, l; split_bf(v, h, l);
        size_t o = (size_t)(bx + ty + j) * R + by + tx;
        oh[o] = h; ol[o] = l;
    }
}

// ===========================================================================
// LayerNorm + split: fp32 in -> bf16 hi/lo out
// ===========================================================================
__global__ __launch_bounds__(256)
void ln_split(const float* __restrict__ x, const float* __restrict__ gam,
              const float* __restrict__ bet, bf16* __restrict__ oh, bf16* __restrict__ ol)
{
    __shared__ float red[8];
    const int row = blockIdx.x;
    const int tid = threadIdx.x;
    const float* xr = x + (size_t)row * D_DIM;

    float v[8];
    float s = 0.f;
#pragma unroll
    for (int i = 0; i < 8; ++i) { v[i] = xr[tid + 256 * i]; s += v[i]; }
#pragma unroll
    for (int d = 16; d > 0; d >>= 1) s += __shfl_xor_sync(0xffffffffu, s, d);
    if ((tid & 31) == 0) red[tid >> 5] = s;
    __syncthreads();
    float tot = 0.f;
#pragma unroll
    for (int i = 0; i < 8; ++i) tot += red[i];
    const float mean = tot * (1.0f / (float)D_DIM);

    float s2 = 0.f;
#pragma unroll
    for (int i = 0; i < 8; ++i) { float d = v[i] - mean; s2 += d * d; }
    __syncthreads();
#pragma unroll
    for (int d = 16; d > 0; d >>= 1) s2 += __shfl_xor_sync(0xffffffffu, s2, d);
    if ((tid & 31) == 0) red[tid >> 5] = s2;
    __syncthreads();
    tot = 0.f;
#pragma unroll
    for (int i = 0; i < 8; ++i) tot += red[i];
    const float rstd = rsqrtf(tot * (1.0f / (float)D_DIM) + 1e-5f);

#pragma unroll
    for (int i = 0; i < 8; ++i) {
        int c = tid + 256 * i;
        float o = (v[i] - mean) * rstd * gam[c] + bet[c];
        bf16 h, l; split_bf(o, h, l);
        size_t off = (size_t)row * D_DIM + c;
        oh[off] = h; ol[off] = l;
    }
}

// ===========================================================================
// 3xBF16 tensor-core GEMM: C[M,N] = A @ B^T from pre-split bf16 hi/lo.
// A_hi/lo [M][K], B_hi/lo [N][K] (K-contiguous). CTA 128x128, BK=32,
// 3-stage cp.async pipeline, ldmatrix feeds, mma.m16n8k16.
// smem stage: Ah(8K) Al(8K) Bh(8K) Bl(8K) = 32KB; rows 64B; chunk swizzle
// phys_chunk = (c + (row>>1)) & 3  (conflict-free ldmatrix phases).
// ===========================================================================
#define GSTAGE 32768
#define GSM_A_LO 8192
#define GSM_B_HI 16384
#define GSM_B_LO 24576
#define GEMM_SMEM (3 * GSTAGE)   // 98304

template<bool RELU, bool HAS_BIAS, bool HAS_RES, bool OUT_SPLIT>
__global__ __launch_bounds__(256, 2)
void gemm_bf16(const bf16* __restrict__ Ah, const bf16* __restrict__ Al,
               const bf16* __restrict__ Bh, const bf16* __restrict__ Bl,
               const float* __restrict__ bias, const float* __restrict__ res,
               float* __restrict__ Cf, bf16* __restrict__ Chi, bf16* __restrict__ Clo,
               int Nd, int Kd)
{
    extern __shared__ char smem[];
    const uint32_t sb = smem_u32(smem);
    const int tid  = threadIdx.x;
    const int warp = tid >> 5;
    const int lane = tid & 31;
    const int wm   = warp & 1;    // 0..1 (M)
    const int wn   = warp >> 1;   // 0..3 (N)
    const int bx = blockIdx.x, by = blockIdx.y;
    const int ktiles = Kd >> 5;

    // ---- producer (cp.async) mapping: 16B chunks, rows 64B ----
    const int r0 = tid >> 2;          // 0..63
    const int cc = tid & 3;           // chunk 0..3
    const int pc = (cc + (r0 >> 1)) & 3;
    const size_t gA0 = (size_t)(by * 128 + r0) * Kd + cc * 8;
    const size_t gB0 = (size_t)(bx * 128 + r0) * Kd + cc * 8;
    const size_t step64 = (size_t)64 * Kd;
    const bf16* pAh = Ah + gA0;  const bf16* pAl = Al + gA0;
    const bf16* pBh = Bh + gB0;  const bf16* pBl = Bl + gB0;
    const uint32_t dA0 = (uint32_t)(r0 * 64 + pc * 16);
    const uint32_t dA1 = dA0 + 64 * 64;   // row r0+64, same phys chunk

#define ISSUE_STAGE(slot, u) do { \
    uint32_t s0_ = sb + (slot) * GSTAGE; int ko_ = (u) * 32; \
    cpa16(s0_ + dA0,            pAh + ko_); cpa16(s0_ + dA1,            pAh + step64 + ko_); \
    cpa16(s0_ + dA0 + GSM_A_LO, pAl + ko_); cpa16(s0_ + dA1 + GSM_A_LO, pAl + step64 + ko_); \
    cpa16(s0_ + dA0 + GSM_B_HI, pBh + ko_); cpa16(s0_ + dA1 + GSM_B_HI, pBh + step64 + ko_); \
    cpa16(s0_ + dA0 + GSM_B_LO, pBl + ko_); cpa16(s0_ + dA1 + GSM_B_LO, pBl + step64 + ko_); \
} while (0)

    // ---- consumer (ldmatrix) per-lane offsets ----
    const int l15   = lane & 15;
    const int chalf = lane >> 4;
    const uint32_t pc0 = (uint32_t)((chalf + (l15 >> 1)) & 3);          // kstep j=0
    const uint32_t pc1 = (uint32_t)((2 + chalf + (l15 >> 1)) & 3);      // kstep j=1
    const uint32_t offA[2] = { (uint32_t)((wm * 64 + l15) * 64) + pc0 * 16,
                               (uint32_t)((wm * 64 + l15) * 64) + pc1 * 16 };
    const uint32_t offB0[2] = { (uint32_t)((wn * 32 + l15) * 64) + pc0 * 16,
                                (uint32_t)((wn * 32 + l15) * 64) + pc1 * 16 };
    const uint32_t offB1[2] = { (uint32_t)((wn * 32 + 16 + l15) * 64) + pc0 * 16,
                                (uint32_t)((wn * 32 + 16 + l15) * 64) + pc1 * 16 };

    float acc[4][4][4];
#pragma unroll
    for (int mt = 0; mt < 4; ++mt)
#pragma unroll
        for (int nt = 0; nt < 4; ++nt)
#pragma unroll
            for (int e = 0; e < 4; ++e) acc[mt][nt][e] = 0.f;

    // prologue: stages 0,1
    ISSUE_STAGE(0, 0); CP_COMMIT();
    ISSUE_STAGE(1, 1); CP_COMMIT();

    for (int t = 0; t < ktiles; ++t) {
        CP_WAIT1();
        __syncthreads();
        {
            const int u = t + 2;
            if (u < ktiles) { ISSUE_STAGE(u % 3, u); }
            CP_COMMIT();
        }
        const uint32_t st = sb + (t % 3) * GSTAGE;
#pragma unroll
        for (int j = 0; j < 2; ++j) {
            uint32_t bhF[8], blF[8];
            ldmx4(&bhF[0], st + GSM_B_HI + offB0[j]);
            ldmx4(&bhF[4], st + GSM_B_HI + offB1[j]);
            ldmx4(&blF[0], st + GSM_B_LO + offB0[j]);
            ldmx4(&blF[4], st + GSM_B_LO + offB1[j]);
#pragma unroll
            for (int mt = 0; mt < 4; ++mt) {
                uint32_t ahF[4], alF[4];
                ldmx4(ahF, st + mt * 1024 + offA[j]);
                ldmx4(alF, st + GSM_A_LO + mt * 1024 + offA[j]);
#pragma unroll
                for (int nt = 0; nt < 4; ++nt) {
                    const int p = (nt >> 1) * 4 + (nt & 1);
                    const uint32_t b0h = bhF[p], b1h = bhF[p + 2];
                    const uint32_t b0l = blF[p], b1l = blF[p + 2];
                    mma_bf16(acc[mt][nt], ahF, b0h, b1h);   // hi*hi
                    mma_bf16(acc[mt][nt], alF, b0h, b1h);   // lo*hi
                    mma_bf16(acc[mt][nt], ahF, b0l, b1l);   // hi*lo
                }
            }
        }
    }

    // ---- epilogue ----
    const int g  = lane >> 2;
    const int tg = lane & 3;
#pragma unroll
    for (int mt = 0; mt < 4; ++mt) {
        const int row = by * 128 + wm * 64 + mt * 16 + g;
#pragma unroll
        for (int nt = 0; nt < 4; ++nt) {
            const int col = bx * 128 + wn * 32 + nt * 8 + 2 * tg;
            float v0 = acc[mt][nt][0], v1 = acc[mt][nt][1];
            float v2 = acc[mt][nt][2], v3 = acc[mt][nt][3];
            if (HAS_BIAS) {
                float2 b2 = *(const float2*)(bias + col);
                v0 += b2.x; v1 += b2.y; v2 += b2.x; v3 += b2.y;
            }
            if (RELU) {
                v0 = fmaxf(v0, 0.f); v1 = fmaxf(v1, 0.f);
                v2 = fmaxf(v2, 0.f); v3 = fmaxf(v3, 0.f);
            }
            if (HAS_RES) {
                float2 ra = *(const float2*)(res + (size_t)row * Nd + col);
                float2 rb = *(const float2*)(res + (size_t)(row + 8) * Nd + col);
                v0 += ra.x; v1 += ra.y; v2 += rb.x; v3 += rb.y;
            }
            if (OUT_SPLIT) {
                bf16 h0, l0, h1, l1;
                split_bf(v0, h0, l0); split_bf(v1, h1, l1);
                *(__nv_bfloat162*)(Chi + (size_t)row * Nd + col) = __nv_bfloat162(h0, h1);
                *(__nv_bfloat162*)(Clo + (size_t)row * Nd + col) = __nv_bfloat162(l0, l1);
                split_bf(v2, h0, l0); split_bf(v3, h1, l1);
                *(__nv_bfloat162*)(Chi + (size_t)(row + 8) * Nd + col) = __nv_bfloat162(h0, h1);
                *(__nv_bfloat162*)(Clo + (size_t)(row + 8) * Nd + col) = __nv_bfloat162(l0, l1);
            } else {
                *(float2*)(Cf + (size_t)row * Nd + col)       = make_float2(v0, v1);
                *(float2*)(Cf + (size_t)(row + 8) * Nd + col) = make_float2(v2, v3);
            }
        }
    }
#undef ISSUE_STAGE
}

// ===========================================================================
// Flash attention (fp32 FFMA), epilogue writes split bf16 hi/lo.
// Head h of batch b = contiguous (2048x128) block at ((b*16+h)*2048*128).
// Mask applied BEFORE 1/sqrt(d) scale (reference quirk).
// ===========================================================================
#define ATT_QSTF (128 * 68)
#define ATT_KSTF (128 * 68)
#define ATT_VSF  (64 * 132)
#define ATT_PSTF (64 * 68)
#define ATT_SMEM_BYTES ((ATT_QSTF + ATT_KSTF + ATT_VSF + ATT_PSTF) * 4)

__global__ __launch_bounds__(256)
void attn_kernel(const float* __restrict__ Q, const float* __restrict__ K,
                 const float* __restrict__ V, bf16* __restrict__ Ohi,
                 bf16* __restrict__ Olo)
{
    extern __shared__ float sm[];
    float* QsT = sm;
    float* KsT = sm + ATT_QSTF;
    float* Vs  = sm + ATT_QSTF + ATT_KSTF;
    float* PsT = sm + ATT_QSTF + ATT_KSTF + ATT_VSF;

    const int qt   = blockIdx.x;
    const int head = blockIdx.y;
    const int b    = blockIdx.z;
    const int tid  = threadIdx.x;
    const int tx   = tid & 15;
    const int ty   = tid >> 4;

    const int hoff = (b * NH + head) * (S_LEN * HD);
    const float* Qh = Q + hoff;
    const float* Kh = K + hoff;
    const float* Vh = V + hoff;
    const int i0 = qt * 64;

#pragma unroll
    for (int r = 0; r < 8; ++r) {
        int f4  = tid + r * 256;
        int row = f4 >> 5;
        int col = (f4 & 31) << 2;
        float4 v4 = *(const float4*)(Qh + (i0 + row) * HD + col);
        QsT[(col + 0) * 68 + row] = v4.x;
        QsT[(col + 1) * 68 + row] = v4.y;
        QsT[(col + 2) * 68 + row] = v4.z;
        QsT[(col + 3) * 68 + row] = v4.w;
    }

    float o_acc[4][8];
#pragma unroll
    for (int i = 0; i < 4; ++i)
#pragma unroll
        for (int c = 0; c < 8; ++c) o_acc[i][c] = 0.f;
    float m_run[4] = {-1e30f, -1e30f, -1e30f, -1e30f};
    float l_run[4] = {0.f, 0.f, 0.f, 0.f};

    const float inv_sqrt_d = 0.08838834764831845f;

    for (int jt = 0; jt <= qt; ++jt) {
        const int j0 = jt * 64;
#pragma unroll
        for (int r = 0; r < 8; ++r) {
            int f4  = tid + r * 256;
            int row = f4 >> 5;
            int col = (f4 & 31) << 2;
            float4 kv = *(const float4*)(Kh + (j0 + row) * HD + col);
            KsT[(col + 0) * 68 + row] = kv.x;
            KsT[(col + 1) * 68 + row] = kv.y;
            KsT[(col + 2) * 68 + row] = kv.z;
            KsT[(col + 3) * 68 + row] = kv.w;
            float4 vv = *(const float4*)(Vh + (j0 + row) * HD + col);
            *(float4*)&Vs[row * 132 + col] = vv;
        }
        __syncthreads();

        float sacc[4][4];
#pragma unroll
        for (int i = 0; i < 4; ++i)
#pragma unroll
            for (int j = 0; j < 4; ++j) sacc[i][j] = 0.f;

#pragma unroll 4
        for (int kk = 0; kk < 128; ++kk) {
            float4 qr = *(const float4*)&QsT[kk * 68 + ty * 4];
            float4 kr = *(const float4*)&KsT[kk * 68 + tx * 4];
            float qa[4] = {qr.x, qr.y, qr.z, qr.w};
            float ka[4] = {kr.x, kr.y, kr.z, kr.w};
#pragma unroll
            for (int i = 0; i < 4; ++i)
#pragma unroll
                for (int j = 0; j < 4; ++j)
                    sacc[i][j] += qa[i] * ka[j];
        }

        const bool diag = (jt == qt);
#pragma unroll
        for (int ii = 0; ii < 4; ++ii) {
            const int gi = i0 + ty * 4 + ii;
            float rowm = -1e30f;
#pragma unroll
            for (int jj = 0; jj < 4; ++jj) {
                float sv = sacc[ii][jj];
                if (diag && (j0 + tx * 4 + jj) > gi) sv = -1e9f;
                sv *= inv_sqrt_d;
                sacc[ii][jj] = sv;
                rowm = fmaxf(rowm, sv);
            }
#pragma unroll
            for (int d = 1; d < 16; d <<= 1)
                rowm = fmaxf(rowm, __shfl_xor_sync(0xffffffffu, rowm, d));
            float mnew = fmaxf(m_run[ii], rowm);
            float corr = __expf(m_run[ii] - mnew);
            m_run[ii] = mnew;
            float rs = 0.f;
#pragma unroll
            for (int jj = 0; jj < 4; ++jj) {
                float p = __expf(sacc[ii][jj] - mnew);
                sacc[ii][jj] = p;
                rs += p;
            }
#pragma unroll
            for (int d = 1; d < 16; d <<= 1)
                rs += __shfl_xor_sync(0xffffffffu, rs, d);
            l_run[ii] = l_run[ii] * corr + rs;
#pragma unroll
            for (int cc = 0; cc < 8; ++cc) o_acc[ii][cc] *= corr;
        }

#pragma unroll
        for (int ii = 0; ii < 4; ++ii)
#pragma unroll
            for (int jj = 0; jj < 4; ++jj)
                PsT[(tx * 4 + jj) * 68 + (ty * 4 + ii)] = sacc[ii][jj];
        __syncthreads();

#pragma unroll 2
        for (int jk = 0; jk < 64; ++jk) {
            float4 pr = *(const float4*)&PsT[jk * 68 + ty * 4];
            float4 v0 = *(const float4*)&Vs[jk * 132 + tx * 8];
            float4 v1 = *(const float4*)&Vs[jk * 132 + tx * 8 + 4];
            float pa[4] = {pr.x, pr.y, pr.z, pr.w};
            float va[8] = {v0.x, v0.y, v0.z, v0.w, v1.x, v1.y, v1.z, v1.w};
#pragma unroll
            for (int ii = 0; ii < 4; ++ii)
#pragma unroll
                for (int cc = 0; cc < 8; ++cc)
                    o_acc[ii][cc] += pa[ii] * va[cc];
        }
        __syncthreads();
    }

#pragma unroll
    for (int ii = 0; ii < 4; ++ii) {
        const float linv = 1.0f / l_run[ii];
        const int row = i0 + ty * 4 + ii;
        const size_t base = ((size_t)b * S_LEN + row) * D_DIM + head * HD + tx * 8;
#pragma unroll
        for (int cc = 0; cc < 8; cc += 2) {
            float a0 = o_acc[ii][cc] * linv;
            float a1 = o_acc[ii][cc + 1] * linv;
            bf16 h0, l0, h1, l1;
            split_bf(a0, h0, l0); split_bf(a1, h1, l1);
            *(__nv_bfloat162*)(Ohi + base + cc) = __nv_bfloat162(h0, h1);
            *(__nv_bfloat162*)(Olo + base + cc) = __nv_bfloat162(l0, l1);
        }
    }
}

// ===========================================================================
// Launch
// ===========================================================================
extern "C" void kernel_launch(void* const* d_in, const int* in_sizes, int n_in,
                              void* d_out, int out_size)
{
    (void)in_sizes; (void)n_in; (void)out_size;
    const float* x    = (const float*)d_in[0];
    const float* Wq   = (const float*)d_in[2];
    const float* Wk   = (const float*)d_in[3];
    const float* Wv   = (const float*)d_in[4];
    const float* Wo   = (const float*)d_in[5];
    const float* ln1g = (const float*)d_in[6];
    const float* ln1b = (const float*)d_in[7];
    const float* W1   = (const float*)d_in[8];
    const float* b1   = (const float*)d_in[9];
    const float* W2   = (const float*)d_in[10];
    const float* b2   = (const float*)d_in[11];
    const float* ln2g = (const float*)d_in[12];
    const float* ln2b = (const float*)d_in[13];
    float* out = (float*)d_out;

    bf16 *h_hi, *h_lo, *at_hi, *at_lo, *ff_hi, *ff_lo;
    float *q, *k, *v, *x2;
    bf16 *wqh, *wql, *wkh, *wkl, *wvh, *wvl, *woh, *wol, *w1h, *w1l, *w2h, *w2l;
    cudaGetSymbolAddress((void**)&h_hi,  g_h_hi);
    cudaGetSymbolAddress((void**)&h_lo,  g_h_lo);
    cudaGetSymbolAddress((void**)&q,     g_q);
    cudaGetSymbolAddress((void**)&k,     g_k);
    cudaGetSymbolAddress((void**)&v,     g_v);
    cudaGetSymbolAddress((void**)&at_hi, g_at_hi);
    cudaGetSymbolAddress((void**)&at_lo, g_at_lo);
    cudaGetSymbolAddress((void**)&x2,    g_x2);
    cudaGetSymbolAddress((void**)&ff_hi, g_ff_hi);
    cudaGetSymbolAddress((void**)&ff_lo, g_ff_lo);
    cudaGetSymbolAddress((void**)&wqh,   g_wqT_h);
    cudaGetSymbolAddress((void**)&wql,   g_wqT_l);
    cudaGetSymbolAddress((void**)&wkh,   g_wkT_h);
    cudaGetSymbolAddress((void**)&wkl,   g_wkT_l);
    cudaGetSymbolAddress((void**)&wvh,   g_wvT_h);
    cudaGetSymbolAddress((void**)&wvl,   g_wvT_l);
    cudaGetSymbolAddress((void**)&woh,   g_woT_h);
    cudaGetSymbolAddress((void**)&wol,   g_woT_l);
    cudaGetSymbolAddress((void**)&w1h,   g_w1T_h);
    cudaGetSymbolAddress((void**)&w1l,   g_w1T_l);
    cudaGetSymbolAddress((void**)&w2h,   g_w2T_h);
    cudaGetSymbolAddress((void**)&w2l,   g_w2T_l);

    cudaFuncSetAttribute(attn_kernel,
                         cudaFuncAttributeMaxDynamicSharedMemorySize, ATT_SMEM_BYTES);
    cudaFuncSetAttribute(gemm_bf16<false, false, false, false>,
                         cudaFuncAttributeMaxDynamicSharedMemorySize, GEMM_SMEM);
    cudaFuncSetAttribute(gemm_bf16<false, false, true, false>,
                         cudaFuncAttributeMaxDynamicSharedMemorySize, GEMM_SMEM);
    cudaFuncSetAttribute(gemm_bf16<true, true, false, true>,
                         cudaFuncAttributeMaxDynamicSharedMemorySize, GEMM_SMEM);
    cudaFuncSetAttribute(gemm_bf16<false, true, true, false>,
                         cudaFuncAttributeMaxDynamicSharedMemorySize, GEMM_SMEM);

    const dim3 blk(256);

    // weight transpose + split (K-major hi/lo bf16)
    transpose_split<<<dim3(64, 64),  blk>>>(Wq, wqh, wql, D_DIM, D_DIM);
    transpose_split<<<dim3(64, 64),  blk>>>(Wk, wkh, wkl, D_DIM, D_DIM);
    transpose_split<<<dim3(64, 64),  blk>>>(Wv, wvh, wvl, D_DIM, D_DIM);
    transpose_split<<<dim3(64, 64),  blk>>>(Wo, woh, wol, D_DIM, D_DIM);
    transpose_split<<<dim3(256, 64), blk>>>(W1, w1h, w1l, D_DIM, M_FF);   // -> [8192][2048]
    transpose_split<<<dim3(64, 256), blk>>>(W2, w2h, w2l, M_FF, D_DIM);   // -> [2048][8192]

    const dim3 gDD(D_DIM / 128, ROWS / 128);   // (16, 32)
    const dim3 gDM(M_FF / 128,  ROWS / 128);   // (64, 32)

    // h = LN1(x), split
    ln_split<<<ROWS, blk>>>(x, ln1g, ln1b, h_hi, h_lo);
    // q/k/v
    gemm_bf16<false, false, false, false><<<gDD, blk, GEMM_SMEM>>>(
        h_hi, h_lo, wqh, wql, nullptr, nullptr, q, nullptr, nullptr, D_DIM, D_DIM);
    gemm_bf16<false, false, false, false><<<gDD, blk, GEMM_SMEM>>>(
        h_hi, h_lo, wkh, wkl, nullptr, nullptr, k, nullptr, nullptr, D_DIM, D_DIM);
    gemm_bf16<false, false, false, false><<<gDD, blk, GEMM_SMEM>>>(
        h_hi, h_lo, wvh, wvl, nullptr, nullptr, v, nullptr, nullptr, D_DIM, D_DIM);
    // attention -> split bf16
    attn_kernel<<<dim3(S_LEN / 64, NH, B_SZ), blk, ATT_SMEM_BYTES>>>(q, k, v, at_hi, at_lo);
    // x2 = x + attn @ Wo
    gemm_bf16<false, false, true, false><<<gDD, blk, GEMM_SMEM>>>(
        at_hi, at_lo, woh, wol, nullptr, x, x2, nullptr, nullptr, D_DIM, D_DIM);
    // h = LN2(x2), split
    ln_split<<<ROWS, blk>>>(x2, ln2g, ln2b, h_hi, h_lo);
    // ff = relu(h @ W1 + b1) -> split bf16
    gemm_bf16<true, true, false, true><<<gDM, blk, GEMM_SMEM>>>(
        h_hi, h_lo, w1h, w1l, b1, nullptr, nullptr, ff_hi, ff_lo, M_FF, D_DIM);
    // out = x2 + ff @ W2 + b2
    gemm_bf16<false, true, true, false><<<gDD, blk, GEMM_SMEM>>>(
        ff_hi, ff_lo, w2h, w2l, b2, x2, out, nullptr, nullptr, D_DIM, M_FF);
}

// round 7
// speedup vs baseline: 2.3822x; 1.2315x over previous
#include <cuda_runtime.h>
#include <cuda_bf16.h>
#include <cstdint>
#include <math.h>

// Problem constants
#define S_LEN 2048
#define D_DIM 2048
#define B_SZ  2
#define NH    16
#define HD    128
#define M_FF  8192
#define ROWS  (B_SZ * S_LEN)   // 4096

typedef __nv_bfloat16 bf16;

// -------------------- scratch (device globals; no allocation allowed) -----
__device__ __align__(16) bf16  g_h_hi  [ROWS * D_DIM];
__device__ __align__(16) bf16  g_h_lo  [ROWS * D_DIM];
__device__ __align__(16) float g_q     [ROWS * D_DIM];
__device__ __align__(16) float g_k     [ROWS * D_DIM];
__device__ __align__(16) float g_v     [ROWS * D_DIM];
__device__ __align__(16) bf16  g_at_hi [ROWS * D_DIM];
__device__ __align__(16) bf16  g_at_lo [ROWS * D_DIM];
__device__ __align__(16) float g_x2    [ROWS * D_DIM];
__device__ __align__(16) float g_ff    [ROWS * M_FF];
// bf16 split weights (QKV, Wo)
__device__ __align__(16) bf16  g_wqT_h [D_DIM * D_DIM];
__device__ __align__(16) bf16  g_wqT_l [D_DIM * D_DIM];
__device__ __align__(16) bf16  g_wkT_h [D_DIM * D_DIM];
__device__ __align__(16) bf16  g_wkT_l [D_DIM * D_DIM];
__device__ __align__(16) bf16  g_wvT_h [D_DIM * D_DIM];
__device__ __align__(16) bf16  g_wvT_l [D_DIM * D_DIM];
__device__ __align__(16) bf16  g_woT_h [D_DIM * D_DIM];
__device__ __align__(16) bf16  g_woT_l [D_DIM * D_DIM];
// int8 2-limb FFN operands + scales
__device__ __align__(16) int8_t g_h2_q1 [ROWS * D_DIM];
__device__ __align__(16) int8_t g_h2_q2 [ROWS * D_DIM];
__device__            float  g_h2_s  [ROWS];
__device__ __align__(16) int8_t g_ff_q1 [ROWS * M_FF];
__device__ __align__(16) int8_t g_ff_q2 [ROWS * M_FF];
__device__            float  g_ff_s  [ROWS];
__device__ __align__(16) int8_t g_w1_q1 [M_FF * D_DIM];
__device__ __align__(16) int8_t g_w1_q2 [M_FF * D_DIM];
__device__            float  g_w1_am [M_FF];
__device__            float  g_w1_s  [M_FF];
__device__ __align__(16) int8_t g_w2_q1 [D_DIM * M_FF];
__device__ __align__(16) int8_t g_w2_q2 [D_DIM * M_FF];
__device__            float  g_w2_am [D_DIM];
__device__            float  g_w2_s  [D_DIM];

// ===========================================================================
// helpers
// ===========================================================================
__device__ __forceinline__ uint32_t smem_u32(const void* p) {
    uint32_t a;
    asm("{ .reg .u64 t; cvta.to.shared.u64 t, %1; cvt.u32.u64 %0, t; }" : "=r"(a) : "l"(p));
    return a;
}
__device__ __forceinline__ void cpa16(uint32_t dst, const void* src) {
    asm volatile("cp.async.cg.shared.global [%0], [%1], 16;" :: "r"(dst), "l"(src));
}
#define CP_COMMIT() asm volatile("cp.async.commit_group;" ::: "memory")
#define CP_WAIT1()  asm volatile("cp.async.wait_group 1;" ::: "memory")
#define CP_WAIT2()  asm volatile("cp.async.wait_group 2;" ::: "memory")

__device__ __forceinline__ void ldmx4(uint32_t* r, uint32_t addr) {
    asm volatile("ldmatrix.sync.aligned.m8n8.x4.shared.b16 {%0,%1,%2,%3}, [%4];"
        : "=r"(r[0]), "=r"(r[1]), "=r"(r[2]), "=r"(r[3]) : "r"(addr));
}
__device__ __forceinline__ void mma_bf16(float* d, const uint32_t* a, uint32_t b0, uint32_t b1) {
    asm volatile(
        "mma.sync.aligned.m16n8k16.row.col.f32.bf16.bf16.f32 "
        "{%0,%1,%2,%3},{%4,%5,%6,%7},{%8,%9},{%0,%1,%2,%3};"
        : "+f"(d[0]), "+f"(d[1]), "+f"(d[2]), "+f"(d[3])
        : "r"(a[0]), "r"(a[1]), "r"(a[2]), "r"(a[3]), "r"(b0), "r"(b1));
}
__device__ __forceinline__ void mma_s8(int* d, const uint32_t* a, uint32_t b0, uint32_t b1) {
    asm volatile(
        "mma.sync.aligned.m16n8k32.row.col.s32.s8.s8.s32 "
        "{%0,%1,%2,%3},{%4,%5,%6,%7},{%8,%9},{%0,%1,%2,%3};"
        : "+r"(d[0]), "+r"(d[1]), "+r"(d[2]), "+r"(d[3])
        : "r"(a[0]), "r"(a[1]), "r"(a[2]), "r"(a[3]), "r"(b0), "r"(b1));
}
__device__ __forceinline__ void split_bf(float v, bf16& h, bf16& l) {
    h = __float2bfloat16_rn(v);
    l = __float2bfloat16_rn(v - __bfloat162float(h));
}
__device__ __forceinline__ void quant2(float v, float inv_s, int8_t& h, int8_t& l) {
    float q  = v * inv_s;                 // |q| <= 127
    float q1 = rintf(q);
    float q2 = rintf((q - q1) * 256.0f);
    q2 = fminf(fmaxf(q2, -127.0f), 127.0f);
    h = (int8_t)(int)q1;
    l = (int8_t)(int)q2;
}

// ===========================================================================
// transpose + split (bf16): in[R][C] fp32 -> out_hi/lo[C][R]
// ===========================================================================
__global__ __launch_bounds__(256)
void transpose_split(const float* __restrict__ in, bf16* __restrict__ oh,
                     bf16* __restrict__ ol, int R, int C)
{
    __shared__ float tile[32][33];
    const int tx = threadIdx.x & 31;
    const int ty = threadIdx.x >> 5;
    const int bx = blockIdx.x * 32, by = blockIdx.y * 32;
#pragma unroll
    for (int j = 0; j < 32; j += 8)
        tile[ty + j][tx] = in[(size_t)(by + ty + j) * C + bx + tx];
    __syncthreads();
#pragma unroll
    for (int j = 0; j < 32; j += 8) {
        float v = tile[tx][ty + j];
        bf16 h, l; split_bf(v, h, l);
        size_t o = (size_t)(bx + ty + j) * R + by + tx;
        oh[o] = h; ol[o] = l;
    }
}

// ===========================================================================
// per-column absmax of in[R][C] -> amax[C] (atomicMax on float bits, >=0)
// ===========================================================================
__global__ __launch_bounds__(256)
void colamax_kernel(const float* __restrict__ in, int R, int C, float* __restrict__ amax)
{
    __shared__ float sm_[8][33];
    const int tx = threadIdx.x & 31;
    const int ty = threadIdx.x >> 5;
    const int bx = blockIdx.x * 32, by = blockIdx.y * 32;
    float m = 0.f;
#pragma unroll
    for (int j = 0; j < 4; ++j)
        m = fmaxf(m, fabsf(in[(size_t)(by + ty + 8 * j) * C + bx + tx]));
    sm_[ty][tx] = m;
    __syncthreads();
    if (ty == 0) {
        float mm = sm_[0][tx];
#pragma unroll
        for (int r = 1; r < 8; ++r) mm = fmaxf(mm, sm_[r][tx]);
        atomicMax((unsigned int*)&amax[bx + tx], __float_as_uint(mm));
    }
}

// ===========================================================================
// transpose + int8 2-limb quant: in[R][C] -> q1/q2[C][R], s[C] = amax/127
// ===========================================================================
__global__ __launch_bounds__(256)
void transpose_quant_i8(const float* __restrict__ in, const float* __restrict__ amax,
                        int8_t* __restrict__ q1o, int8_t* __restrict__ q2o,
                        float* __restrict__ sOut, int R, int C)
{
    __shared__ float tile[32][33];
    const int tx = threadIdx.x & 31;
    const int ty = threadIdx.x >> 5;
    const int bx = blockIdx.x * 32, by = blockIdx.y * 32;
#pragma unroll
    for (int j = 0; j < 32; j += 8)
        tile[ty + j][tx] = in[(size_t)(by + ty + j) * C + bx + tx];
    __syncthreads();
#pragma unroll
    for (int j = 0; j < 32; j += 8) {
        const int orow = bx + ty + j;                  // original column
        float am = fmaxf(amax[orow], 1e-20f);
        float s  = am * (1.0f / 127.0f);
        float inv = 127.0f / am;
        if (tx == 0) sOut[orow] = s;                   // duplicate-safe
        float v = tile[tx][ty + j];
        int8_t h, l; quant2(v, inv, h, l);
        size_t o = (size_t)orow * R + by + tx;
        q1o[o] = h; q2o[o] = l;
    }
}

// ===========================================================================
// per-row int8 2-limb quant of in[rows][Kd]
// ===========================================================================
__global__ __launch_bounds__(256)
void rowquant_i8(const float* __restrict__ in, int Kd,
                 int8_t* __restrict__ q1, int8_t* __restrict__ q2, float* __restrict__ s)
{
    __shared__ float red[9];
    const int row = blockIdx.x;
    const int tid = threadIdx.x;
    const float* r = in + (size_t)row * Kd;
    float m = 0.f;
    for (int c = tid; c < Kd; c += 256) m = fmaxf(m, fabsf(r[c]));
#pragma unroll
    for (int d = 16; d > 0; d >>= 1) m = fmaxf(m, __shfl_xor_sync(0xffffffffu, m, d));
    if ((tid & 31) == 0) red[tid >> 5] = m;
    __syncthreads();
    if (tid == 0) {
        float mm = red[0];
#pragma unroll
        for (int i = 1; i < 8; ++i) mm = fmaxf(mm, red[i]);
        mm = fmaxf(mm, 1e-20f);
        red[8] = mm;
        s[row] = mm * (1.0f / 127.0f);
    }
    __syncthreads();
    const float inv = 127.0f / red[8];
    for (int c = tid; c < Kd; c += 256) {
        int8_t h, l; quant2(r[c], inv, h, l);
        q1[(size_t)row * Kd + c] = h;
        q2[(size_t)row * Kd + c] = l;
    }
}

// ===========================================================================
// LayerNorm + split bf16 (for LN1)
// ===========================================================================
__global__ __launch_bounds__(256)
void ln_split(const float* __restrict__ x, const float* __restrict__ gam,
              const float* __restrict__ bet, bf16* __restrict__ oh, bf16* __restrict__ ol)
{
    __shared__ float red[8];
    const int row = blockIdx.x;
    const int tid = threadIdx.x;
    const float* xr = x + (size_t)row * D_DIM;

    float v[8];
    float sum = 0.f;
#pragma unroll
    for (int i = 0; i < 8; ++i) { v[i] = xr[tid + 256 * i]; sum += v[i]; }
#pragma unroll
    for (int d = 16; d > 0; d >>= 1) sum += __shfl_xor_sync(0xffffffffu, sum, d);
    if ((tid & 31) == 0) red[tid >> 5] = sum;
    __syncthreads();
    float tot = 0.f;
#pragma unroll
    for (int i = 0; i < 8; ++i) tot += red[i];
    const float mean = tot * (1.0f / (float)D_DIM);

    float s2 = 0.f;
#pragma unroll
    for (int i = 0; i < 8; ++i) { float d = v[i] - mean; s2 += d * d; }
    __syncthreads();
#pragma unroll
    for (int d = 16; d > 0; d >>= 1) s2 += __shfl_xor_sync(0xffffffffu, s2, d);
    if ((tid & 31) == 0) red[tid >> 5] = s2;
    __syncthreads();
    tot = 0.f;
#pragma unroll
    for (int i = 0; i < 8; ++i) tot += red[i];
    const float rstd = rsqrtf(tot * (1.0f / (float)D_DIM) + 1e-5f);

#pragma unroll
    for (int i = 0; i < 8; ++i) {
        int c = tid + 256 * i;
        float o = (v[i] - mean) * rstd * gam[c] + bet[c];
        bf16 h, l; split_bf(o, h, l);
        size_t off = (size_t)row * D_DIM + c;
        oh[off] = h; ol[off] = l;
    }
}

// ===========================================================================
// LayerNorm + int8 2-limb quant (for LN2 -> FFN1 input)
// ===========================================================================
__global__ __launch_bounds__(256)
void ln_quant_i8(const float* __restrict__ x, const float* __restrict__ gam,
                 const float* __restrict__ bet, int8_t* __restrict__ q1,
                 int8_t* __restrict__ q2, float* __restrict__ sArr)
{
    __shared__ float red[9];
    const int row = blockIdx.x;
    const int tid = threadIdx.x;
    const float* xr = x + (size_t)row * D_DIM;

    float v[8];
    float sum = 0.f;
#pragma unroll
    for (int i = 0; i < 8; ++i) { v[i] = xr[tid + 256 * i]; sum += v[i]; }
#pragma unroll
    for (int d = 16; d > 0; d >>= 1) sum += __shfl_xor_sync(0xffffffffu, sum, d);
    if ((tid & 31) == 0) red[tid >> 5] = sum;
    __syncthreads();
    float tot = 0.f;
#pragma unroll
    for (int i = 0; i < 8; ++i) tot += red[i];
    const float mean = tot * (1.0f / (float)D_DIM);

    float s2 = 0.f;
#pragma unroll
    for (int i = 0; i < 8; ++i) { float d = v[i] - mean; s2 += d * d; }
    __syncthreads();
#pragma unroll
    for (int d = 16; d > 0; d >>= 1) s2 += __shfl_xor_sync(0xffffffffu, s2, d);
    if ((tid & 31) == 0) red[tid >> 5] = s2;
    __syncthreads();
    tot = 0.f;
#pragma unroll
    for (int i = 0; i < 8; ++i) tot += red[i];
    const float rstd = rsqrtf(tot * (1.0f / (float)D_DIM) + 1e-5f);

    float o[8];
    float am = 0.f;
#pragma unroll
    for (int i = 0; i < 8; ++i) {
        int c = tid + 256 * i;
        o[i] = (v[i] - mean) * rstd * gam[c] + bet[c];
        am = fmaxf(am, fabsf(o[i]));
    }
    __syncthreads();
#pragma unroll
    for (int d = 16; d > 0; d >>= 1) am = fmaxf(am, __shfl_xor_sync(0xffffffffu, am, d));
    if ((tid & 31) == 0) red[tid >> 5] = am;
    __syncthreads();
    if (tid == 0) {
        float mm = red[0];
#pragma unroll
        for (int i = 1; i < 8; ++i) mm = fmaxf(mm, red[i]);
        mm = fmaxf(mm, 1e-20f);
        red[8] = mm;
        sArr[row] = mm * (1.0f / 127.0f);
    }
    __syncthreads();
    const float inv = 127.0f / red[8];
#pragma unroll
    for (int i = 0; i < 8; ++i) {
        int c = tid + 256 * i;
        int8_t h, l; quant2(o[i], inv, h, l);
        q1[(size_t)row * D_DIM + c] = h;
        q2[(size_t)row * D_DIM + c] = l;
    }
}

// ===========================================================================
// 3xBF16 tensor-core GEMM (proven; QKV + Wo)
// ===========================================================================
#define GSTAGE 32768
#define GSM_A_LO 8192
#define GSM_B_HI 16384
#define GSM_B_LO 24576
#define GEMM_SMEM (3 * GSTAGE)   // 98304

template<bool HAS_RES>
__global__ __launch_bounds__(256, 2)
void gemm_bf16(const bf16* __restrict__ Ah, const bf16* __restrict__ Al,
               const bf16* __restrict__ Bh, const bf16* __restrict__ Bl,
               const float* __restrict__ res, float* __restrict__ Cf,
               int Nd, int Kd)
{
    extern __shared__ char smem[];
    const uint32_t sb = smem_u32(smem);
    const int tid  = threadIdx.x;
    const int warp = tid >> 5;
    const int lane = tid & 31;
    const int wm   = warp & 1;
    const int wn   = warp >> 1;
    const int bx = blockIdx.x, by = blockIdx.y;
    const int ktiles = Kd >> 5;

    const int r0 = tid >> 2;
    const int cc = tid & 3;
    const int pc = (cc + (r0 >> 1)) & 3;
    const size_t gA0 = (size_t)(by * 128 + r0) * Kd + cc * 8;
    const size_t gB0 = (size_t)(bx * 128 + r0) * Kd + cc * 8;
    const size_t step64 = (size_t)64 * Kd;
    const bf16* pAh = Ah + gA0;  const bf16* pAl = Al + gA0;
    const bf16* pBh = Bh + gB0;  const bf16* pBl = Bl + gB0;
    const uint32_t dA0 = (uint32_t)(r0 * 64 + pc * 16);
    const uint32_t dA1 = dA0 + 64 * 64;

#define ISSUE_STAGE(slot, u) do { \
    uint32_t s0_ = sb + (slot) * GSTAGE; int ko_ = (u) * 32; \
    cpa16(s0_ + dA0,            pAh + ko_); cpa16(s0_ + dA1,            pAh + step64 + ko_); \
    cpa16(s0_ + dA0 + GSM_A_LO, pAl + ko_); cpa16(s0_ + dA1 + GSM_A_LO, pAl + step64 + ko_); \
    cpa16(s0_ + dA0 + GSM_B_HI, pBh + ko_); cpa16(s0_ + dA1 + GSM_B_HI, pBh + step64 + ko_); \
    cpa16(s0_ + dA0 + GSM_B_LO, pBl + ko_); cpa16(s0_ + dA1 + GSM_B_LO, pBl + step64 + ko_); \
} while (0)

    const int l15   = lane & 15;
    const int chalf = lane >> 4;
    const uint32_t pc0 = (uint32_t)((chalf + (l15 >> 1)) & 3);
    const uint32_t pc1 = (uint32_t)((2 + chalf + (l15 >> 1)) & 3);
    const uint32_t offA[2] = { (uint32_t)((wm * 64 + l15) * 64) + pc0 * 16,
                               (uint32_t)((wm * 64 + l15) * 64) + pc1 * 16 };
    const uint32_t offB0[2] = { (uint32_t)((wn * 32 + l15) * 64) + pc0 * 16,
                                (uint32_t)((wn * 32 + l15) * 64) + pc1 * 16 };
    const uint32_t offB1[2] = { (uint32_t)((wn * 32 + 16 + l15) * 64) + pc0 * 16,
                                (uint32_t)((wn * 32 + 16 + l15) * 64) + pc1 * 16 };

    float acc[4][4][4];
#pragma unroll
    for (int mt = 0; mt < 4; ++mt)
#pragma unroll
        for (int nt = 0; nt < 4; ++nt)
#pragma unroll
            for (int e = 0; e < 4; ++e) acc[mt][nt][e] = 0.f;

    ISSUE_STAGE(0, 0); CP_COMMIT();
    ISSUE_STAGE(1, 1); CP_COMMIT();

    for (int t = 0; t < ktiles; ++t) {
        CP_WAIT1();
        __syncthreads();
        {
            const int u = t + 2;
            if (u < ktiles) { ISSUE_STAGE(u % 3, u); }
            CP_COMMIT();
        }
        const uint32_t st = sb + (t % 3) * GSTAGE;
#pragma unroll
        for (int j = 0; j < 2; ++j) {
            uint32_t bhF[8], blF[8];
            ldmx4(&bhF[0], st + GSM_B_HI + offB0[j]);
            ldmx4(&bhF[4], st + GSM_B_HI + offB1[j]);
            ldmx4(&blF[0], st + GSM_B_LO + offB0[j]);
            ldmx4(&blF[4], st + GSM_B_LO + offB1[j]);
#pragma unroll
            for (int mt = 0; mt < 4; ++mt) {
                uint32_t ahF[4], alF[4];
                ldmx4(ahF, st + mt * 1024 + offA[j]);
                ldmx4(alF, st + GSM_A_LO + mt * 1024 + offA[j]);
#pragma unroll
                for (int nt = 0; nt < 4; ++nt) {
                    const int p = (nt >> 1) * 4 + (nt & 1);
                    const uint32_t b0h = bhF[p], b1h = bhF[p + 2];
                    const uint32_t b0l = blF[p], b1l = blF[p + 2];
                    mma_bf16(acc[mt][nt], ahF, b0h, b1h);
                    mma_bf16(acc[mt][nt], alF, b0h, b1h);
                    mma_bf16(acc[mt][nt], ahF, b0l, b1l);
                }
            }
        }
    }

    const int g  = lane >> 2;
    const int tg = lane & 3;
#pragma unroll
    for (int mt = 0; mt < 4; ++mt) {
        const int row = by * 128 + wm * 64 + mt * 16 + g;
#pragma unroll
        for (int nt = 0; nt < 4; ++nt) {
            const int col = bx * 128 + wn * 32 + nt * 8 + 2 * tg;
            float v0 = acc[mt][nt][0], v1 = acc[mt][nt][1];
            float v2 = acc[mt][nt][2], v3 = acc[mt][nt][3];
            if (HAS_RES) {
                float2 ra = *(const float2*)(res + (size_t)row * Nd + col);
                float2 rb = *(const float2*)(res + (size_t)(row + 8) * Nd + col);
                v0 += ra.x; v1 += ra.y; v2 += rb.x; v3 += rb.y;
            }
            *(float2*)(Cf + (size_t)row * Nd + col)       = make_float2(v0, v1);
            *(float2*)(Cf + (size_t)(row + 8) * Nd + col) = make_float2(v2, v3);
        }
    }
#undef ISSUE_STAGE
}

// ===========================================================================
// int8 2-limb tensor-core GEMM (FFN): C = sA[m]*sB[n]*(accH + accM/256)
// CTA 128x128, BK=64 int8, 4-stage cp.async. Byte layout identical to bf16.
// ===========================================================================
#define ISTAGE 32768
#define ISM_A2 8192
#define ISM_B1 16384
#define ISM_B2 24576
#define I8_SMEM (4 * ISTAGE)   // 131072

template<bool RELU, bool HAS_BIAS, bool HAS_RES>
__global__ __launch_bounds__(256, 1)
void gemm_i8(const int8_t* __restrict__ A1, const int8_t* __restrict__ A2,
             const int8_t* __restrict__ B1, const int8_t* __restrict__ B2,
             const float* __restrict__ sA, const float* __restrict__ sB,
             const float* __restrict__ bias, const float* __restrict__ res,
             float* __restrict__ Cf, int Nd, int Kd)
{
    extern __shared__ char smem[];
    const uint32_t sb = smem_u32(smem);
    const int tid  = threadIdx.x;
    const int warp = tid >> 5;
    const int lane = tid & 31;
    const int wm   = warp & 1;
    const int wn   = warp >> 1;
    const int bx = blockIdx.x, by = blockIdx.y;
    const int ktiles = Kd >> 6;    // BK = 64 int8 = 64 bytes/row

    const int r0 = tid >> 2;
    const int cc = tid & 3;
    const int pc = (cc + (r0 >> 1)) & 3;
    const size_t gA0 = (size_t)(by * 128 + r0) * Kd + cc * 16;
    const size_t gB0 = (size_t)(bx * 128 + r0) * Kd + cc * 16;
    const size_t step64 = (size_t)64 * Kd;
    const int8_t* pA1 = A1 + gA0;  const int8_t* pA2 = A2 + gA0;
    const int8_t* pB1 = B1 + gB0;  const int8_t* pB2 = B2 + gB0;
    const uint32_t dA0 = (uint32_t)(r0 * 64 + pc * 16);
    const uint32_t dA1 = dA0 + 64 * 64;

#define ISSUE_I8(slot, u) do { \
    uint32_t s0_ = sb + (slot) * ISTAGE; int ko_ = (u) * 64; \
    cpa16(s0_ + dA0,          pA1 + ko_); cpa16(s0_ + dA1,          pA1 + step64 + ko_); \
    cpa16(s0_ + dA0 + ISM_A2, pA2 + ko_); cpa16(s0_ + dA1 + ISM_A2, pA2 + step64 + ko_); \
    cpa16(s0_ + dA0 + ISM_B1, pB1 + ko_); cpa16(s0_ + dA1 + ISM_B1, pB1 + step64 + ko_); \
    cpa16(s0_ + dA0 + ISM_B2, pB2 + ko_); cpa16(s0_ + dA1 + ISM_B2, pB2 + step64 + ko_); \
} while (0)

    const int l15   = lane & 15;
    const int chalf = lane >> 4;
    const uint32_t pc0 = (uint32_t)((chalf + (l15 >> 1)) & 3);
    const uint32_t pc1 = (uint32_t)((2 + chalf + (l15 >> 1)) & 3);
    const uint32_t offA[2] = { (uint32_t)((wm * 64 + l15) * 64) + pc0 * 16,
                               (uint32_t)((wm * 64 + l15) * 64) + pc1 * 16 };
    const uint32_t offB0[2] = { (uint32_t)((wn * 32 + l15) * 64) + pc0 * 16,
                                (uint32_t)((wn * 32 + l15) * 64) + pc1 * 16 };
    const uint32_t offB1[2] = { (uint32_t)((wn * 32 + 16 + l15) * 64) + pc0 * 16,
                                (uint32_t)((wn * 32 + 16 + l15) * 64) + pc1 * 16 };

    int accH[4][4][4], accM[4][4][4];
#pragma unroll
    for (int mt = 0; mt < 4; ++mt)
#pragma unroll
        for (int nt = 0; nt < 4; ++nt)
#pragma unroll
            for (int e = 0; e < 4; ++e) { accH[mt][nt][e] = 0; accM[mt][nt][e] = 0; }

    ISSUE_I8(0, 0); CP_COMMIT();
    ISSUE_I8(1, 1); CP_COMMIT();
    ISSUE_I8(2, 2); CP_COMMIT();

    for (int t = 0; t < ktiles; ++t) {
        CP_WAIT2();
        __syncthreads();
        {
            const int u = t + 3;
            if (u < ktiles) { ISSUE_I8(u & 3, u); }
            CP_COMMIT();
        }
        const uint32_t st = sb + (t & 3) * ISTAGE;
#pragma unroll
        for (int j = 0; j < 2; ++j) {
            uint32_t b1F[8], b2F[8];
            ldmx4(&b1F[0], st + ISM_B1 + offB0[j]);
            ldmx4(&b1F[4], st + ISM_B1 + offB1[j]);
            ldmx4(&b2F[0], st + ISM_B2 + offB0[j]);
            ldmx4(&b2F[4], st + ISM_B2 + offB1[j]);
#pragma unroll
            for (int mt = 0; mt < 4; ++mt) {
                uint32_t a1F[4], a2F[4];
                ldmx4(a1F, st + mt * 1024 + offA[j]);
                ldmx4(a2F, st + ISM_A2 + mt * 1024 + offA[j]);
#pragma unroll
                for (int nt = 0; nt < 4; ++nt) {
                    const int p = (nt >> 1) * 4 + (nt & 1);
                    const uint32_t b0h = b1F[p], b1h = b1F[p + 2];
                    const uint32_t b0l = b2F[p], b1l = b2F[p + 2];
                    mma_s8(accH[mt][nt], a1F, b0h, b1h);   // q1*q1
                    mma_s8(accM[mt][nt], a2F, b0h, b1h);   // q2*q1
                    mma_s8(accM[mt][nt], a1F, b0l, b1l);   // q1*q2
                }
            }
        }
    }

    const int g  = lane >> 2;
    const int tg = lane & 3;
#pragma unroll
    for (int mt = 0; mt < 4; ++mt) {
        const int row = by * 128 + wm * 64 + mt * 16 + g;
        const float sa0 = sA[row], sa8 = sA[row + 8];
#pragma unroll
        for (int nt = 0; nt < 4; ++nt) {
            const int col = bx * 128 + wn * 32 + nt * 8 + 2 * tg;
            const float sb0 = sB[col], sb1 = sB[col + 1];
            float v0 = sa0 * sb0 * ((float)accH[mt][nt][0] + (float)accM[mt][nt][0] * 0.00390625f);
            float v1 = sa0 * sb1 * ((float)accH[mt][nt][1] + (float)accM[mt][nt][1] * 0.00390625f);
            float v2 = sa8 * sb0 * ((float)accH[mt][nt][2] + (float)accM[mt][nt][2] * 0.00390625f);
            float v3 = sa8 * sb1 * ((float)accH[mt][nt][3] + (float)accM[mt][nt][3] * 0.00390625f);
            if (HAS_BIAS) {
                float2 b2v = *(const float2*)(bias + col);
                v0 += b2v.x; v1 += b2v.y; v2 += b2v.x; v3 += b2v.y;
            }
            if (RELU) {
                v0 = fmaxf(v0, 0.f); v1 = fmaxf(v1, 0.f);
                v2 = fmaxf(v2, 0.f); v3 = fmaxf(v3, 0.f);
            }
            if (HAS_RES) {
                float2 ra = *(const float2*)(res + (size_t)row * Nd + col);
                float2 rb = *(const float2*)(res + (size_t)(row + 8) * Nd + col);
                v0 += ra.x; v1 += ra.y; v2 += rb.x; v3 += rb.y;
            }
            *(float2*)(Cf + (size_t)row * Nd + col)       = make_float2(v0, v1);
            *(float2*)(Cf + (size_t)(row + 8) * Nd + col) = make_float2(v2, v3);
        }
    }
#undef ISSUE_I8
}

// ===========================================================================
// Flash attention (fp32 FFMA), split bf16 hi/lo output (unchanged, proven)
// ===========================================================================
#define ATT_QSTF (128 * 68)
#define ATT_KSTF (128 * 68)
#define ATT_VSF  (64 * 132)
#define ATT_PSTF (64 * 68)
#define ATT_SMEM_BYTES ((ATT_QSTF + ATT_KSTF + ATT_VSF + ATT_PSTF) * 4)

__global__ __launch_bounds__(256)
void attn_kernel(const float* __restrict__ Q, const float* __restrict__ K,
                 const float* __restrict__ V, bf16* __restrict__ Ohi,
                 bf16* __restrict__ Olo)
{
    extern __shared__ float sm[];
    float* QsT = sm;
    float* KsT = sm + ATT_QSTF;
    float* Vs  = sm + ATT_QSTF + ATT_KSTF;
    float* PsT = sm + ATT_QSTF + ATT_KSTF + ATT_VSF;

    const int qt   = blockIdx.x;
    const int head = blockIdx.y;
    const int b    = blockIdx.z;
    const int tid  = threadIdx.x;
    const int tx   = tid & 15;
    const int ty   = tid >> 4;

    const int hoff = (b * NH + head) * (S_LEN * HD);
    const float* Qh = Q + hoff;
    const float* Kh = K + hoff;
    const float* Vh = V + hoff;
    const int i0 = qt * 64;

#pragma unroll
    for (int r = 0; r < 8; ++r) {
        int f4  = tid + r * 256;
        int row = f4 >> 5;
        int col = (f4 & 31) << 2;
        float4 v4 = *(const float4*)(Qh + (i0 + row) * HD + col);
        QsT[(col + 0) * 68 + row] = v4.x;
        QsT[(col + 1) * 68 + row] = v4.y;
        QsT[(col + 2) * 68 + row] = v4.z;
        QsT[(col + 3) * 68 + row] = v4.w;
    }

    float o_acc[4][8];
#pragma unroll
    for (int i = 0; i < 4; ++i)
#pragma unroll
        for (int c = 0; c < 8; ++c) o_acc[i][c] = 0.f;
    float m_run[4] = {-1e30f, -1e30f, -1e30f, -1e30f};
    float l_run[4] = {0.f, 0.f, 0.f, 0.f};

    const float inv_sqrt_d = 0.08838834764831845f;

    for (int jt = 0; jt <= qt; ++jt) {
        const int j0 = jt * 64;
#pragma unroll
        for (int r = 0; r < 8; ++r) {
            int f4  = tid + r * 256;
            int row = f4 >> 5;
            int col = (f4 & 31) << 2;
            float4 kv = *(const float4*)(Kh + (j0 + row) * HD + col);
            KsT[(col + 0) * 68 + row] = kv.x;
            KsT[(col + 1) * 68 + row] = kv.y;
            KsT[(col + 2) * 68 + row] = kv.z;
            KsT[(col + 3) * 68 + row] = kv.w;
            float4 vv = *(const float4*)(Vh + (j0 + row) * HD + col);
            *(float4*)&Vs[row * 132 + col] = vv;
        }
        __syncthreads();

        float sacc[4][4];
#pragma unroll
        for (int i = 0; i < 4; ++i)
#pragma unroll
            for (int j = 0; j < 4; ++j) sacc[i][j] = 0.f;

#pragma unroll 4
        for (int kk = 0; kk < 128; ++kk) {
            float4 qr = *(const float4*)&QsT[kk * 68 + ty * 4];
            float4 kr = *(const float4*)&KsT[kk * 68 + tx * 4];
            float qa[4] = {qr.x, qr.y, qr.z, qr.w};
            float ka[4] = {kr.x, kr.y, kr.z, kr.w};
#pragma unroll
            for (int i = 0; i < 4; ++i)
#pragma unroll
                for (int j = 0; j < 4; ++j)
                    sacc[i][j] += qa[i] * ka[j];
        }

        const bool diag = (jt == qt);
#pragma unroll
        for (int ii = 0; ii < 4; ++ii) {
            const int gi = i0 + ty * 4 + ii;
            float rowm = -1e30f;
#pragma unroll
            for (int jj = 0; jj < 4; ++jj) {
                float sv = sacc[ii][jj];
                if (diag && (j0 + tx * 4 + jj) > gi) sv = -1e9f;
                sv *= inv_sqrt_d;
                sacc[ii][jj] = sv;
                rowm = fmaxf(rowm, sv);
            }
#pragma unroll
            for (int d = 1; d < 16; d <<= 1)
                rowm = fmaxf(rowm, __shfl_xor_sync(0xffffffffu, rowm, d));
            float mnew = fmaxf(m_run[ii], rowm);
            float corr = __expf(m_run[ii] - mnew);
            m_run[ii] = mnew;
            float rs = 0.f;
#pragma unroll
            for (int jj = 0; jj < 4; ++jj) {
                float p = __expf(sacc[ii][jj] - mnew);
                sacc[ii][jj] = p;
                rs += p;
            }
#pragma unroll
            for (int d = 1; d < 16; d <<= 1)
                rs += __shfl_xor_sync(0xffffffffu, rs, d);
            l_run[ii] = l_run[ii] * corr + rs;
#pragma unroll
            for (int cc = 0; cc < 8; ++cc) o_acc[ii][cc] *= corr;
        }

#pragma unroll
        for (int ii = 0; ii < 4; ++ii)
#pragma unroll
            for (int jj = 0; jj < 4; ++jj)
                PsT[(tx * 4 + jj) * 68 + (ty * 4 + ii)] = sacc[ii][jj];
        __syncthreads();

#pragma unroll 2
        for (int jk = 0; jk < 64; ++jk) {
            float4 pr = *(const float4*)&PsT[jk * 68 + ty * 4];
            float4 v0 = *(const float4*)&Vs[jk * 132 + tx * 8];
            float4 v1 = *(const float4*)&Vs[jk * 132 + tx * 8 + 4];
            float pa[4] = {pr.x, pr.y, pr.z, pr.w};
            float va[8] = {v0.x, v0.y, v0.z, v0.w, v1.x, v1.y, v1.z, v1.w};
#pragma unroll
            for (int ii = 0; ii < 4; ++ii)
#pragma unroll
                for (int cc = 0; cc < 8; ++cc)
                    o_acc[ii][cc] += pa[ii] * va[cc];
        }
        __syncthreads();
    }

#pragma unroll
    for (int ii = 0; ii < 4; ++ii) {
        const float linv = 1.0f / l_run[ii];
        const int row = i0 + ty * 4 + ii;
        const size_t base = ((size_t)b * S_LEN + row) * D_DIM + head * HD + tx * 8;
#pragma unroll
        for (int cc = 0; cc < 8; cc += 2) {
            float a0 = o_acc[ii][cc] * linv;
            float a1 = o_acc[ii][cc + 1] * linv;
            bf16 h0, l0, h1, l1;
            split_bf(a0, h0, l0); split_bf(a1, h1, l1);
            *(__nv_bfloat162*)(Ohi + base + cc) = __nv_bfloat162(h0, h1);
            *(__nv_bfloat162*)(Olo + base + cc) = __nv_bfloat162(l0, l1);
        }
    }
}

// ===========================================================================
// Launch
// ===========================================================================
extern "C" void kernel_launch(void* const* d_in, const int* in_sizes, int n_in,
                              void* d_out, int out_size)
{
    (void)in_sizes; (void)n_in; (void)out_size;
    const float* x    = (const float*)d_in[0];
    const float* Wq   = (const float*)d_in[2];
    const float* Wk   = (const float*)d_in[3];
    const float* Wv   = (const float*)d_in[4];
    const float* Wo   = (const float*)d_in[5];
    const float* ln1g = (const float*)d_in[6];
    const float* ln1b = (const float*)d_in[7];
    const float* W1   = (const float*)d_in[8];
    const float* b1   = (const float*)d_in[9];
    const float* W2   = (const float*)d_in[10];
    const float* b2   = (const float*)d_in[11];
    const float* ln2g = (const float*)d_in[12];
    const float* ln2b = (const float*)d_in[13];
    float* out = (float*)d_out;

    bf16 *h_hi, *h_lo, *at_hi, *at_lo;
    float *q, *k, *v, *x2, *ff;
    bf16 *wqh, *wql, *wkh, *wkl, *wvh, *wvl, *woh, *wol;
    int8_t *h2q1, *h2q2, *ffq1, *ffq2, *w1q1, *w1q2, *w2q1, *w2q2;
    float *h2s, *ffs, *w1am, *w1s, *w2am, *w2s;
    cudaGetSymbolAddress((void**)&h_hi,  g_h_hi);
    cudaGetSymbolAddress((void**)&h_lo,  g_h_lo);
    cudaGetSymbolAddress((void**)&q,     g_q);
    cudaGetSymbolAddress((void**)&k,     g_k);
    cudaGetSymbolAddress((void**)&v,     g_v);
    cudaGetSymbolAddress((void**)&at_hi, g_at_hi);
    cudaGetSymbolAddress((void**)&at_lo, g_at_lo);
    cudaGetSymbolAddress((void**)&x2,    g_x2);
    cudaGetSymbolAddress((void**)&ff,    g_ff);
    cudaGetSymbolAddress((void**)&wqh,   g_wqT_h);
    cudaGetSymbolAddress((void**)&wql,   g_wqT_l);
    cudaGetSymbolAddress((void**)&wkh,   g_wkT_h);
    cudaGetSymbolAddress((void**)&wkl,   g_wkT_l);
    cudaGetSymbolAddress((void**)&wvh,   g_wvT_h);
    cudaGetSymbolAddress((void**)&wvl,   g_wvT_l);
    cudaGetSymbolAddress((void**)&woh,   g_woT_h);
    cudaGetSymbolAddress((void**)&wol,   g_woT_l);
    cudaGetSymbolAddress((void**)&h2q1,  g_h2_q1);
    cudaGetSymbolAddress((void**)&h2q2,  g_h2_q2);
    cudaGetSymbolAddress((void**)&h2s,   g_h2_s);
    cudaGetSymbolAddress((void**)&ffq1,  g_ff_q1);
    cudaGetSymbolAddress((void**)&ffq2,  g_ff_q2);
    cudaGetSymbolAddress((void**)&ffs,   g_ff_s);
    cudaGetSymbolAddress((void**)&w1q1,  g_w1_q1);
    cudaGetSymbolAddress((void**)&w1q2,  g_w1_q2);
    cudaGetSymbolAddress((void**)&w1am,  g_w1_am);
    cudaGetSymbolAddress((void**)&w1s,   g_w1_s);
    cudaGetSymbolAddress((void**)&w2q1,  g_w2_q1);
    cudaGetSymbolAddress((void**)&w2q2,  g_w2_q2);
    cudaGetSymbolAddress((void**)&w2am,  g_w2_am);
    cudaGetSymbolAddress((void**)&w2s,   g_w2_s);

    cudaFuncSetAttribute(attn_kernel,
                         cudaFuncAttributeMaxDynamicSharedMemorySize, ATT_SMEM_BYTES);
    cudaFuncSetAttribute(gemm_bf16<false>,
                         cudaFuncAttributeMaxDynamicSharedMemorySize, GEMM_SMEM);
    cudaFuncSetAttribute(gemm_bf16<true>,
                         cudaFuncAttributeMaxDynamicSharedMemorySize, GEMM_SMEM);
    cudaFuncSetAttribute(gemm_i8<true, true, false>,
                         cudaFuncAttributeMaxDynamicSharedMemorySize, I8_SMEM);
    cudaFuncSetAttribute(gemm_i8<false, true, true>,
                         cudaFuncAttributeMaxDynamicSharedMemorySize, I8_SMEM);

    const dim3 blk(256);

    // ---- weight prep ----
    cudaMemsetAsync(w1am, 0, M_FF * sizeof(float));
    cudaMemsetAsync(w2am, 0, D_DIM * sizeof(float));
    colamax_kernel<<<dim3(M_FF / 32,  D_DIM / 32), blk>>>(W1, D_DIM, M_FF, w1am);
    colamax_kernel<<<dim3(D_DIM / 32, M_FF / 32),  blk>>>(W2, M_FF, D_DIM, w2am);
    transpose_split<<<dim3(64, 64), blk>>>(Wq, wqh, wql, D_DIM, D_DIM);
    transpose_split<<<dim3(64, 64), blk>>>(Wk, wkh, wkl, D_DIM, D_DIM);
    transpose_split<<<dim3(64, 64), blk>>>(Wv, wvh, wvl, D_DIM, D_DIM);
    transpose_split<<<dim3(64, 64), blk>>>(Wo, woh, wol, D_DIM, D_DIM);
    transpose_quant_i8<<<dim3(256, 64), blk>>>(W1, w1am, w1q1, w1q2, w1s, D_DIM, M_FF);
    transpose_quant_i8<<<dim3(64, 256), blk>>>(W2, w2am, w2q1, w2q2, w2s, M_FF, D_DIM);

    const dim3 gDD(D_DIM / 128, ROWS / 128);   // (16, 32)
    const dim3 gDM(M_FF / 128,  ROWS / 128);   // (64, 32)

    // ---- layer ----
    ln_split<<<ROWS, blk>>>(x, ln1g, ln1b, h_hi, h_lo);
    gemm_bf16<false><<<gDD, blk, GEMM_SMEM>>>(h_hi, h_lo, wqh, wql, nullptr, q, D_DIM, D_DIM);
    gemm_bf16<false><<<gDD, blk, GEMM_SMEM>>>(h_hi, h_lo, wkh, wkl, nullptr, k, D_DIM, D_DIM);
    gemm_bf16<false><<<gDD, blk, GEMM_SMEM>>>(h_hi, h_lo, wvh, wvl, nullptr, v, D_DIM, D_DIM);
    attn_kernel<<<dim3(S_LEN / 64, NH, B_SZ), blk, ATT_SMEM_BYTES>>>(q, k, v, at_hi, at_lo);
    gemm_bf16<true><<<gDD, blk, GEMM_SMEM>>>(at_hi, at_lo, woh, wol, x, x2, D_DIM, D_DIM);
    ln_quant_i8<<<ROWS, blk>>>(x2, ln2g, ln2b, h2q1, h2q2, h2s);
    gemm_i8<true, true, false><<<gDM, blk, I8_SMEM>>>(
        h2q1, h2q2, w1q1, w1q2, h2s, w1s, b1, nullptr, ff, M_FF, D_DIM);
    rowquant_i8<<<ROWS, blk>>>(ff, M_FF, ffq1, ffq2, ffs);
    gemm_i8<false, true, true><<<gDD, blk, I8_SMEM>>>(
        ffq1, ffq2, w2q1, w2q2, ffs, w2s, b2, x2, out, D_DIM, M_FF);
}

// round 8
// speedup vs baseline: 2.6788x; 1.1245x over previous
#include <cuda_runtime.h>
#include <cuda_bf16.h>
#include <cstdint>
#include <math.h>

// Problem constants
#define S_LEN 2048
#define D_DIM 2048
#define B_SZ  2
#define NH    16
#define HD    128
#define M_FF  8192
#define ROWS  (B_SZ * S_LEN)   // 4096

// -------------------- scratch (device globals; no allocation allowed) -----
__device__ __align__(16) int8_t g_h_q1  [ROWS * D_DIM];   // LN1 / LN2 output (reused)
__device__ __align__(16) int8_t g_h_q2  [ROWS * D_DIM];
__device__            float  g_h_s   [ROWS];
__device__ __align__(16) float g_q     [ROWS * D_DIM];
__device__ __align__(16) float g_k     [ROWS * D_DIM];
__device__ __align__(16) float g_v     [ROWS * D_DIM];
__device__ __align__(16) float g_attn  [ROWS * D_DIM];
__device__ __align__(16) int8_t g_at_q1 [ROWS * D_DIM];
__device__ __align__(16) int8_t g_at_q2 [ROWS * D_DIM];
__device__            float  g_at_s  [ROWS];
__device__ __align__(16) float g_x2    [ROWS * D_DIM];
__device__ __align__(16) float g_ff    [ROWS * M_FF];
__device__ __align__(16) int8_t g_ff_q1 [ROWS * M_FF];
__device__ __align__(16) int8_t g_ff_q2 [ROWS * M_FF];
__device__            float  g_ff_s  [ROWS];
// int8 2-limb weights (all transposed to [N][K])
__device__ __align__(16) int8_t g_wq_q1 [D_DIM * D_DIM];
__device__ __align__(16) int8_t g_wq_q2 [D_DIM * D_DIM];
__device__            float  g_wq_am [D_DIM];
__device__            float  g_wq_s  [D_DIM];
__device__ __align__(16) int8_t g_wk_q1 [D_DIM * D_DIM];
__device__ __align__(16) int8_t g_wk_q2 [D_DIM * D_DIM];
__device__            float  g_wk_am [D_DIM];
__device__            float  g_wk_s  [D_DIM];
__device__ __align__(16) int8_t g_wv_q1 [D_DIM * D_DIM];
__device__ __align__(16) int8_t g_wv_q2 [D_DIM * D_DIM];
__device__            float  g_wv_am [D_DIM];
__device__            float  g_wv_s  [D_DIM];
__device__ __align__(16) int8_t g_wo_q1 [D_DIM * D_DIM];
__device__ __align__(16) int8_t g_wo_q2 [D_DIM * D_DIM];
__device__            float  g_wo_am [D_DIM];
__device__            float  g_wo_s  [D_DIM];
__device__ __align__(16) int8_t g_w1_q1 [M_FF * D_DIM];
__device__ __align__(16) int8_t g_w1_q2 [M_FF * D_DIM];
__device__            float  g_w1_am [M_FF];
__device__            float  g_w1_s  [M_FF];
__device__ __align__(16) int8_t g_w2_q1 [D_DIM * M_FF];
__device__ __align__(16) int8_t g_w2_q2 [D_DIM * M_FF];
__device__            float  g_w2_am [D_DIM];
__device__            float  g_w2_s  [D_DIM];

// ===========================================================================
// helpers
// ===========================================================================
__device__ __forceinline__ uint32_t smem_u32(const void* p) {
    uint32_t a;
    asm("{ .reg .u64 t; cvta.to.shared.u64 t, %1; cvt.u32.u64 %0, t; }" : "=r"(a) : "l"(p));
    return a;
}
__device__ __forceinline__ void cpa16(uint32_t dst, const void* src) {
    asm volatile("cp.async.cg.shared.global [%0], [%1], 16;" :: "r"(dst), "l"(src));
}
#define CP_COMMIT() asm volatile("cp.async.commit_group;" ::: "memory")
#define CP_WAIT1()  asm volatile("cp.async.wait_group 1;" ::: "memory")

__device__ __forceinline__ void ldmx4(uint32_t* r, uint32_t addr) {
    asm volatile("ldmatrix.sync.aligned.m8n8.x4.shared.b16 {%0,%1,%2,%3}, [%4];"
        : "=r"(r[0]), "=r"(r[1]), "=r"(r[2]), "=r"(r[3]) : "r"(addr));
}
__device__ __forceinline__ void mma_s8(int* d, const uint32_t* a, uint32_t b0, uint32_t b1) {
    asm volatile(
        "mma.sync.aligned.m16n8k32.row.col.s32.s8.s8.s32 "
        "{%0,%1,%2,%3},{%4,%5,%6,%7},{%8,%9},{%0,%1,%2,%3};"
        : "+r"(d[0]), "+r"(d[1]), "+r"(d[2]), "+r"(d[3])
        : "r"(a[0]), "r"(a[1]), "r"(a[2]), "r"(a[3]), "r"(b0), "r"(b1));
}
__device__ __forceinline__ void quant2(float v, float inv_s, int8_t& h, int8_t& l) {
    float q  = v * inv_s;                 // |q| <= 127
    float q1 = rintf(q);
    float q2 = rintf((q - q1) * 256.0f);
    q2 = fminf(fmaxf(q2, -127.0f), 127.0f);
    h = (int8_t)(int)q1;
    l = (int8_t)(int)q2;
}

// ===========================================================================
// per-column absmax of in[R][C] -> amax[C]
// ===========================================================================
__global__ __launch_bounds__(256)
void colamax_kernel(const float* __restrict__ in, int R, int C, float* __restrict__ amax)
{
    __shared__ float sm_[8][33];
    const int tx = threadIdx.x & 31;
    const int ty = threadIdx.x >> 5;
    const int bx = blockIdx.x * 32, by = blockIdx.y * 32;
    float m = 0.f;
#pragma unroll
    for (int j = 0; j < 4; ++j)
        m = fmaxf(m, fabsf(in[(size_t)(by + ty + 8 * j) * C + bx + tx]));
    sm_[ty][tx] = m;
    __syncthreads();
    if (ty == 0) {
        float mm = sm_[0][tx];
#pragma unroll
        for (int r = 1; r < 8; ++r) mm = fmaxf(mm, sm_[r][tx]);
        atomicMax((unsigned int*)&amax[bx + tx], __float_as_uint(mm));
    }
}

// ===========================================================================
// transpose + int8 2-limb quant: in[R][C] -> q1/q2[C][R], s[C]
// ===========================================================================
__global__ __launch_bounds__(256)
void transpose_quant_i8(const float* __restrict__ in, const float* __restrict__ amax,
                        int8_t* __restrict__ q1o, int8_t* __restrict__ q2o,
                        float* __restrict__ sOut, int R, int C)
{
    __shared__ float tile[32][33];
    const int tx = threadIdx.x & 31;
    const int ty = threadIdx.x >> 5;
    const int bx = blockIdx.x * 32, by = blockIdx.y * 32;
#pragma unroll
    for (int j = 0; j < 32; j += 8)
        tile[ty + j][tx] = in[(size_t)(by + ty + j) * C + bx + tx];
    __syncthreads();
#pragma unroll
    for (int j = 0; j < 32; j += 8) {
        const int orow = bx + ty + j;
        float am = fmaxf(amax[orow], 1e-20f);
        float s  = am * (1.0f / 127.0f);
        float inv = 127.0f / am;
        if (tx == 0) sOut[orow] = s;
        float v = tile[tx][ty + j];
        int8_t h, l; quant2(v, inv, h, l);
        size_t o = (size_t)orow * R + by + tx;
        q1o[o] = h; q2o[o] = l;
    }
}

// ===========================================================================
// per-row int8 2-limb quant of in[rows][Kd]
// ===========================================================================
__global__ __launch_bounds__(256)
void rowquant_i8(const float* __restrict__ in, int Kd,
                 int8_t* __restrict__ q1, int8_t* __restrict__ q2, float* __restrict__ s)
{
    __shared__ float red[9];
    const int row = blockIdx.x;
    const int tid = threadIdx.x;
    const float* r = in + (size_t)row * Kd;
    float m = 0.f;
    for (int c = tid; c < Kd; c += 256) m = fmaxf(m, fabsf(r[c]));
#pragma unroll
    for (int d = 16; d > 0; d >>= 1) m = fmaxf(m, __shfl_xor_sync(0xffffffffu, m, d));
    if ((tid & 31) == 0) red[tid >> 5] = m;
    __syncthreads();
    if (tid == 0) {
        float mm = red[0];
#pragma unroll
        for (int i = 1; i < 8; ++i) mm = fmaxf(mm, red[i]);
        mm = fmaxf(mm, 1e-20f);
        red[8] = mm;
        s[row] = mm * (1.0f / 127.0f);
    }
    __syncthreads();
    const float inv = 127.0f / red[8];
    for (int c = tid; c < Kd; c += 256) {
        int8_t h, l; quant2(r[c], inv, h, l);
        q1[(size_t)row * Kd + c] = h;
        q2[(size_t)row * Kd + c] = l;
    }
}

// ===========================================================================
// LayerNorm + int8 2-limb quant
// ===========================================================================
__global__ __launch_bounds__(256)
void ln_quant_i8(const float* __restrict__ x, const float* __restrict__ gam,
                 const float* __restrict__ bet, int8_t* __restrict__ q1,
                 int8_t* __restrict__ q2, float* __restrict__ sArr)
{
    __shared__ float red[9];
    const int row = blockIdx.x;
    const int tid = threadIdx.x;
    const float* xr = x + (size_t)row * D_DIM;

    float v[8];
    float sum = 0.f;
#pragma unroll
    for (int i = 0; i < 8; ++i) { v[i] = xr[tid + 256 * i]; sum += v[i]; }
#pragma unroll
    for (int d = 16; d > 0; d >>= 1) sum += __shfl_xor_sync(0xffffffffu, sum, d);
    if ((tid & 31) == 0) red[tid >> 5] = sum;
    __syncthreads();
    float tot = 0.f;
#pragma unroll
    for (int i = 0; i < 8; ++i) tot += red[i];
    const float mean = tot * (1.0f / (float)D_DIM);

    float s2 = 0.f;
#pragma unroll
    for (int i = 0; i < 8; ++i) { float d = v[i] - mean; s2 += d * d; }
    __syncthreads();
#pragma unroll
    for (int d = 16; d > 0; d >>= 1) s2 += __shfl_xor_sync(0xffffffffu, s2, d);
    if ((tid & 31) == 0) red[tid >> 5] = s2;
    __syncthreads();
    tot = 0.f;
#pragma unroll
    for (int i = 0; i < 8; ++i) tot += red[i];
    const float rstd = rsqrtf(tot * (1.0f / (float)D_DIM) + 1e-5f);

    float o[8];
    float am = 0.f;
#pragma unroll
    for (int i = 0; i < 8; ++i) {
        int c = tid + 256 * i;
        o[i] = (v[i] - mean) * rstd * gam[c] + bet[c];
        am = fmaxf(am, fabsf(o[i]));
    }
    __syncthreads();
#pragma unroll
    for (int d = 16; d > 0; d >>= 1) am = fmaxf(am, __shfl_xor_sync(0xffffffffu, am, d));
    if ((tid & 31) == 0) red[tid >> 5] = am;
    __syncthreads();
    if (tid == 0) {
        float mm = red[0];
#pragma unroll
        for (int i = 1; i < 8; ++i) mm = fmaxf(mm, red[i]);
        mm = fmaxf(mm, 1e-20f);
        red[8] = mm;
        sArr[row] = mm * (1.0f / 127.0f);
    }
    __syncthreads();
    const float inv = 127.0f / red[8];
#pragma unroll
    for (int i = 0; i < 8; ++i) {
        int c = tid + 256 * i;
        int8_t h, l; quant2(o[i], inv, h, l);
        q1[(size_t)row * D_DIM + c] = h;
        q2[(size_t)row * D_DIM + c] = l;
    }
}

// ===========================================================================
// int8 2-limb tensor-core GEMM: C = sA[m]*sB[n]*(accH + accM/256)
// CTA 128x128, BK=64 int8, 3-stage cp.async (96KB). All 6 GEMMs use this.
// ===========================================================================
#define ISTAGE 32768
#define ISM_A2 8192
#define ISM_B1 16384
#define ISM_B2 24576
#define I8_SMEM (3 * ISTAGE)   // 98304

template<bool RELU, bool HAS_BIAS, bool HAS_RES>
__global__ __launch_bounds__(256, 1)
void gemm_i8(const int8_t* __restrict__ A1, const int8_t* __restrict__ A2,
             const int8_t* __restrict__ B1, const int8_t* __restrict__ B2,
             const float* __restrict__ sA, const float* __restrict__ sB,
             const float* __restrict__ bias, const float* __restrict__ res,
             float* __restrict__ Cf, int Nd, int Kd)
{
    extern __shared__ char smem[];
    const uint32_t sb = smem_u32(smem);
    const int tid  = threadIdx.x;
    const int warp = tid >> 5;
    const int lane = tid & 31;
    const int wm   = warp & 1;
    const int wn   = warp >> 1;
    const int bx = blockIdx.x, by = blockIdx.y;
    const int ktiles = Kd >> 6;    // BK = 64 bytes/row

    const int r0 = tid >> 2;
    const int cc = tid & 3;
    const int pc = (cc + (r0 >> 1)) & 3;
    const size_t gA0 = (size_t)(by * 128 + r0) * Kd + cc * 16;
    const size_t gB0 = (size_t)(bx * 128 + r0) * Kd + cc * 16;
    const size_t step64 = (size_t)64 * Kd;
    const int8_t* pA1 = A1 + gA0;  const int8_t* pA2 = A2 + gA0;
    const int8_t* pB1 = B1 + gB0;  const int8_t* pB2 = B2 + gB0;
    const uint32_t dA0 = (uint32_t)(r0 * 64 + pc * 16);
    const uint32_t dA1 = dA0 + 64 * 64;

#define ISSUE_I8(slot, u) do { \
    uint32_t s0_ = sb + (slot) * ISTAGE; int ko_ = (u) * 64; \
    cpa16(s0_ + dA0,          pA1 + ko_); cpa16(s0_ + dA1,          pA1 + step64 + ko_); \
    cpa16(s0_ + dA0 + ISM_A2, pA2 + ko_); cpa16(s0_ + dA1 + ISM_A2, pA2 + step64 + ko_); \
    cpa16(s0_ + dA0 + ISM_B1, pB1 + ko_); cpa16(s0_ + dA1 + ISM_B1, pB1 + step64 + ko_); \
    cpa16(s0_ + dA0 + ISM_B2, pB2 + ko_); cpa16(s0_ + dA1 + ISM_B2, pB2 + step64 + ko_); \
} while (0)

    const int l15   = lane & 15;
    const int chalf = lane >> 4;
    const uint32_t pc0 = (uint32_t)((chalf + (l15 >> 1)) & 3);
    const uint32_t pc1 = (uint32_t)((2 + chalf + (l15 >> 1)) & 3);
    const uint32_t offA[2] = { (uint32_t)((wm * 64 + l15) * 64) + pc0 * 16,
                               (uint32_t)((wm * 64 + l15) * 64) + pc1 * 16 };
    const uint32_t offB0[2] = { (uint32_t)((wn * 32 + l15) * 64) + pc0 * 16,
                                (uint32_t)((wn * 32 + l15) * 64) + pc1 * 16 };
    const uint32_t offB1[2] = { (uint32_t)((wn * 32 + 16 + l15) * 64) + pc0 * 16,
                                (uint32_t)((wn * 32 + 16 + l15) * 64) + pc1 * 16 };

    int accH[4][4][4], accM[4][4][4];
#pragma unroll
    for (int mt = 0; mt < 4; ++mt)
#pragma unroll
        for (int nt = 0; nt < 4; ++nt)
#pragma unroll
            for (int e = 0; e < 4; ++e) { accH[mt][nt][e] = 0; accM[mt][nt][e] = 0; }

    ISSUE_I8(0, 0); CP_COMMIT();
    ISSUE_I8(1, 1); CP_COMMIT();

    for (int t = 0; t < ktiles; ++t) {
        CP_WAIT1();
        __syncthreads();
        {
            const int u = t + 2;
            if (u < ktiles) { ISSUE_I8(u % 3, u); }
            CP_COMMIT();
        }
        const uint32_t st = sb + (t % 3) * ISTAGE;
#pragma unroll
        for (int j = 0; j < 2; ++j) {
            uint32_t b1F[8], b2F[8];
            ldmx4(&b1F[0], st + ISM_B1 + offB0[j]);
            ldmx4(&b1F[4], st + ISM_B1 + offB1[j]);
            ldmx4(&b2F[0], st + ISM_B2 + offB0[j]);
            ldmx4(&b2F[4], st + ISM_B2 + offB1[j]);
#pragma unroll
            for (int mt = 0; mt < 4; ++mt) {
                uint32_t a1F[4], a2F[4];
                ldmx4(a1F, st + mt * 1024 + offA[j]);
                ldmx4(a2F, st + ISM_A2 + mt * 1024 + offA[j]);
#pragma unroll
                for (int nt = 0; nt < 4; ++nt) {
                    const int p = (nt >> 1) * 4 + (nt & 1);
                    const uint32_t b0h = b1F[p], b1h = b1F[p + 2];
                    const uint32_t b0l = b2F[p], b1l = b2F[p + 2];
                    mma_s8(accH[mt][nt], a1F, b0h, b1h);   // q1*q1
                    mma_s8(accM[mt][nt], a2F, b0h, b1h);   // q2*q1
                    mma_s8(accM[mt][nt], a1F, b0l, b1l);   // q1*q2
                }
            }
        }
    }

    const int g  = lane >> 2;
    const int tg = lane & 3;
#pragma unroll
    for (int mt = 0; mt < 4; ++mt) {
        const int row = by * 128 + wm * 64 + mt * 16 + g;
        const float sa0 = sA[row], sa8 = sA[row + 8];
#pragma unroll
        for (int nt = 0; nt < 4; ++nt) {
            const int col = bx * 128 + wn * 32 + nt * 8 + 2 * tg;
            const float sb0 = sB[col], sb1 = sB[col + 1];
            float v0 = sa0 * sb0 * ((float)accH[mt][nt][0] + (float)accM[mt][nt][0] * 0.00390625f);
            float v1 = sa0 * sb1 * ((float)accH[mt][nt][1] + (float)accM[mt][nt][1] * 0.00390625f);
            float v2 = sa8 * sb0 * ((float)accH[mt][nt][2] + (float)accM[mt][nt][2] * 0.00390625f);
            float v3 = sa8 * sb1 * ((float)accH[mt][nt][3] + (float)accM[mt][nt][3] * 0.00390625f);
            if (HAS_BIAS) {
                float2 b2v = *(const float2*)(bias + col);
                v0 += b2v.x; v1 += b2v.y; v2 += b2v.x; v3 += b2v.y;
            }
            if (RELU) {
                v0 = fmaxf(v0, 0.f); v1 = fmaxf(v1, 0.f);
                v2 = fmaxf(v2, 0.f); v3 = fmaxf(v3, 0.f);
            }
            if (HAS_RES) {
                float2 ra = *(const float2*)(res + (size_t)row * Nd + col);
                float2 rb = *(const float2*)(res + (size_t)(row + 8) * Nd + col);
                v0 += ra.x; v1 += ra.y; v2 += rb.x; v3 += rb.y;
            }
            *(float2*)(Cf + (size_t)row * Nd + col)       = make_float2(v0, v1);
            *(float2*)(Cf + (size_t)(row + 8) * Nd + col) = make_float2(v2, v3);
        }
    }
#undef ISSUE_I8
}

// ===========================================================================
// Flash attention (fp32 FFMA), fp32 output
// Head h of batch b = contiguous (2048x128) block (reshape quirk).
// Mask applied BEFORE 1/sqrt(d) scale (reference quirk).
// ===========================================================================
#define ATT_QSTF (128 * 68)
#define ATT_KSTF (128 * 68)
#define ATT_VSF  (64 * 132)
#define ATT_PSTF (64 * 68)
#define ATT_SMEM_BYTES ((ATT_QSTF + ATT_KSTF + ATT_VSF + ATT_PSTF) * 4)

__global__ __launch_bounds__(256)
void attn_kernel(const float* __restrict__ Q, const float* __restrict__ K,
                 const float* __restrict__ V, float* __restrict__ O)
{
    extern __shared__ float sm[];
    float* QsT = sm;
    float* KsT = sm + ATT_QSTF;
    float* Vs  = sm + ATT_QSTF + ATT_KSTF;
    float* PsT = sm + ATT_QSTF + ATT_KSTF + ATT_VSF;

    const int qt   = blockIdx.x;
    const int head = blockIdx.y;
    const int b    = blockIdx.z;
    const int tid  = threadIdx.x;
    const int tx   = tid & 15;
    const int ty   = tid >> 4;

    const int hoff = (b * NH + head) * (S_LEN * HD);
    const float* Qh = Q + hoff;
    const float* Kh = K + hoff;
    const float* Vh = V + hoff;
    const int i0 = qt * 64;

#pragma unroll
    for (int r = 0; r < 8; ++r) {
        int f4  = tid + r * 256;
        int row = f4 >> 5;
        int col = (f4 & 31) << 2;
        float4 v4 = *(const float4*)(Qh + (i0 + row) * HD + col);
        QsT[(col + 0) * 68 + row] = v4.x;
        QsT[(col + 1) * 68 + row] = v4.y;
        QsT[(col + 2) * 68 + row] = v4.z;
        QsT[(col + 3) * 68 + row] = v4.w;
    }

    float o_acc[4][8];
#pragma unroll
    for (int i = 0; i < 4; ++i)
#pragma unroll
        for (int c = 0; c < 8; ++c) o_acc[i][c] = 0.f;
    float m_run[4] = {-1e30f, -1e30f, -1e30f, -1e30f};
    float l_run[4] = {0.f, 0.f, 0.f, 0.f};

    const float inv_sqrt_d = 0.08838834764831845f;

    for (int jt = 0; jt <= qt; ++jt) {
        const int j0 = jt * 64;
#pragma unroll
        for (int r = 0; r < 8; ++r) {
            int f4  = tid + r * 256;
            int row = f4 >> 5;
            int col = (f4 & 31) << 2;
            float4 kv = *(const float4*)(Kh + (j0 + row) * HD + col);
            KsT[(col + 0) * 68 + row] = kv.x;
            KsT[(col + 1) * 68 + row] = kv.y;
            KsT[(col + 2) * 68 + row] = kv.z;
            KsT[(col + 3) * 68 + row] = kv.w;
            float4 vv = *(const float4*)(Vh + (j0 + row) * HD + col);
            *(float4*)&Vs[row * 132 + col] = vv;
        }
        __syncthreads();

        float sacc[4][4];
#pragma unroll
        for (int i = 0; i < 4; ++i)
#pragma unroll
            for (int j = 0; j < 4; ++j) sacc[i][j] = 0.f;

#pragma unroll 4
        for (int kk = 0; kk < 128; ++kk) {
            float4 qr = *(const float4*)&QsT[kk * 68 + ty * 4];
            float4 kr = *(const float4*)&KsT[kk * 68 + tx * 4];
            float qa[4] = {qr.x, qr.y, qr.z, qr.w};
            float ka[4] = {kr.x, kr.y, kr.z, kr.w};
#pragma unroll
            for (int i = 0; i < 4; ++i)
#pragma unroll
                for (int j = 0; j < 4; ++j)
                    sacc[i][j] += qa[i] * ka[j];
        }

        const bool diag = (jt == qt);
#pragma unroll
        for (int ii = 0; ii < 4; ++ii) {
            const int gi = i0 + ty * 4 + ii;
            float rowm = -1e30f;
#pragma unroll
            for (int jj = 0; jj < 4; ++jj) {
                float sv = sacc[ii][jj];
                if (diag && (j0 + tx * 4 + jj) > gi) sv = -1e9f;
                sv *= inv_sqrt_d;
                sacc[ii][jj] = sv;
                rowm = fmaxf(rowm, sv);
            }
#pragma unroll
            for (int d = 1; d < 16; d <<= 1)
                rowm = fmaxf(rowm, __shfl_xor_sync(0xffffffffu, rowm, d));
            float mnew = fmaxf(m_run[ii], rowm);
            float corr = __expf(m_run[ii] - mnew);
            m_run[ii] = mnew;
            float rs = 0.f;
#pragma unroll
            for (int jj = 0; jj < 4; ++jj) {
                float p = __expf(sacc[ii][jj] - mnew);
                sacc[ii][jj] = p;
                rs += p;
            }
#pragma unroll
            for (int d = 1; d < 16; d <<= 1)
                rs += __shfl_xor_sync(0xffffffffu, rs, d);
            l_run[ii] = l_run[ii] * corr + rs;
#pragma unroll
            for (int cc = 0; cc < 8; ++cc) o_acc[ii][cc] *= corr;
        }

#pragma unroll
        for (int ii = 0; ii < 4; ++ii)
#pragma unroll
            for (int jj = 0; jj < 4; ++jj)
                PsT[(tx * 4 + jj) * 68 + (ty * 4 + ii)] = sacc[ii][jj];
        __syncthreads();

#pragma unroll 2
        for (int jk = 0; jk < 64; ++jk) {
            float4 pr = *(const float4*)&PsT[jk * 68 + ty * 4];
            float4 v0 = *(const float4*)&Vs[jk * 132 + tx * 8];
            float4 v1 = *(const float4*)&Vs[jk * 132 + tx * 8 + 4];
            float pa[4] = {pr.x, pr.y, pr.z, pr.w};
            float va[8] = {v0.x, v0.y, v0.z, v0.w, v1.x, v1.y, v1.z, v1.w};
#pragma unroll
            for (int ii = 0; ii < 4; ++ii)
#pragma unroll
                for (int cc = 0; cc < 8; ++cc)
                    o_acc[ii][cc] += pa[ii] * va[cc];
        }
        __syncthreads();
    }

#pragma unroll
    for (int ii = 0; ii < 4; ++ii) {
        const float linv = 1.0f / l_run[ii];
        const int row = i0 + ty * 4 + ii;
        float* op = O + ((size_t)b * S_LEN + row) * D_DIM + head * HD + tx * 8;
        float4 w0 = make_float4(o_acc[ii][0] * linv, o_acc[ii][1] * linv,
                                o_acc[ii][2] * linv, o_acc[ii][3] * linv);
        float4 w1 = make_float4(o_acc[ii][4] * linv, o_acc[ii][5] * linv,
                                o_acc[ii][6] * linv, o_acc[ii][7] * linv);
        *(float4*)op       = w0;
        *(float4*)(op + 4) = w1;
    }
}

// ===========================================================================
// Launch
// ===========================================================================
extern "C" void kernel_launch(void* const* d_in, const int* in_sizes, int n_in,
                              void* d_out, int out_size)
{
    (void)in_sizes; (void)n_in; (void)out_size;
    const float* x    = (const float*)d_in[0];
    const float* Wq   = (const float*)d_in[2];
    const float* Wk   = (const float*)d_in[3];
    const float* Wv   = (const float*)d_in[4];
    const float* Wo   = (const float*)d_in[5];
    const float* ln1g = (const float*)d_in[6];
    const float* ln1b = (const float*)d_in[7];
    const float* W1   = (const float*)d_in[8];
    const float* b1   = (const float*)d_in[9];
    const float* W2   = (const float*)d_in[10];
    const float* b2   = (const float*)d_in[11];
    const float* ln2g = (const float*)d_in[12];
    const float* ln2b = (const float*)d_in[13];
    float* out = (float*)d_out;

    int8_t *hq1, *hq2, *atq1, *atq2, *ffq1, *ffq2;
    float *hs, *ats, *ffs;
    float *q, *k, *v, *attn, *x2, *ff;
    int8_t *wqq1, *wqq2, *wkq1, *wkq2, *wvq1, *wvq2, *woq1, *woq2, *w1q1, *w1q2, *w2q1, *w2q2;
    float *wqam, *wqs, *wkam, *wks, *wvam, *wvs, *woam, *wos, *w1am, *w1s, *w2am, *w2s;
    cudaGetSymbolAddress((void**)&hq1,  g_h_q1);
    cudaGetSymbolAddress((void**)&hq2,  g_h_q2);
    cudaGetSymbolAddress((void**)&hs,   g_h_s);
    cudaGetSymbolAddress((void**)&q,    g_q);
    cudaGetSymbolAddress((void**)&k,    g_k);
    cudaGetSymbolAddress((void**)&v,    g_v);
    cudaGetSymbolAddress((void**)&attn, g_attn);
    cudaGetSymbolAddress((void**)&atq1, g_at_q1);
    cudaGetSymbolAddress((void**)&atq2, g_at_q2);
    cudaGetSymbolAddress((void**)&ats,  g_at_s);
    cudaGetSymbolAddress((void**)&x2,   g_x2);
    cudaGetSymbolAddress((void**)&ff,   g_ff);
    cudaGetSymbolAddress((void**)&ffq1, g_ff_q1);
    cudaGetSymbolAddress((void**)&ffq2, g_ff_q2);
    cudaGetSymbolAddress((void**)&ffs,  g_ff_s);
    cudaGetSymbolAddress((void**)&wqq1, g_wq_q1);
    cudaGetSymbolAddress((void**)&wqq2, g_wq_q2);
    cudaGetSymbolAddress((void**)&wqam, g_wq_am);
    cudaGetSymbolAddress((void**)&wqs,  g_wq_s);
    cudaGetSymbolAddress((void**)&wkq1, g_wk_q1);
    cudaGetSymbolAddress((void**)&wkq2, g_wk_q2);
    cudaGetSymbolAddress((void**)&wkam, g_wk_am);
    cudaGetSymbolAddress((void**)&wks,  g_wk_s);
    cudaGetSymbolAddress((void**)&wvq1, g_wv_q1);
    cudaGetSymbolAddress((void**)&wvq2, g_wv_q2);
    cudaGetSymbolAddress((void**)&wvam, g_wv_am);
    cudaGetSymbolAddress((void**)&wvs,  g_wv_s);
    cudaGetSymbolAddress((void**)&woq1, g_wo_q1);
    cudaGetSymbolAddress((void**)&woq2, g_wo_q2);
    cudaGetSymbolAddress((void**)&woam, g_wo_am);
    cudaGetSymbolAddress((void**)&wos,  g_wo_s);
    cudaGetSymbolAddress((void**)&w1q1, g_w1_q1);
    cudaGetSymbolAddress((void**)&w1q2, g_w1_q2);
    cudaGetSymbolAddress((void**)&w1am, g_w1_am);
    cudaGetSymbolAddress((void**)&w1s,  g_w1_s);
    cudaGetSymbolAddress((void**)&w2q1, g_w2_q1);
    cudaGetSymbolAddress((void**)&w2q2, g_w2_q2);
    cudaGetSymbolAddress((void**)&w2am, g_w2_am);
    cudaGetSymbolAddress((void**)&w2s,  g_w2_s);

    cudaFuncSetAttribute(attn_kernel,
                         cudaFuncAttributeMaxDynamicSharedMemorySize, ATT_SMEM_BYTES);
    cudaFuncSetAttribute(gemm_i8<false, false, false>,
                         cudaFuncAttributeMaxDynamicSharedMemorySize, I8_SMEM);
    cudaFuncSetAttribute(gemm_i8<false, false, true>,
                         cudaFuncAttributeMaxDynamicSharedMemorySize, I8_SMEM);
    cudaFuncSetAttribute(gemm_i8<true, true, false>,
                         cudaFuncAttributeMaxDynamicSharedMemorySize, I8_SMEM);
    cudaFuncSetAttribute(gemm_i8<false, true, true>,
                         cudaFuncAttributeMaxDynamicSharedMemorySize, I8_SMEM);

    const dim3 blk(256);

    // ---- weight prep: colamax + transpose-quant (int8 2-limb, K-major) ----
    cudaMemsetAsync(wqam, 0, D_DIM * sizeof(float));
    cudaMemsetAsync(wkam, 0, D_DIM * sizeof(float));
    cudaMemsetAsync(wvam, 0, D_DIM * sizeof(float));
    cudaMemsetAsync(woam, 0, D_DIM * sizeof(float));
    cudaMemsetAsync(w1am, 0, M_FF * sizeof(float));
    cudaMemsetAsync(w2am, 0, D_DIM * sizeof(float));
    colamax_kernel<<<dim3(64, 64),  blk>>>(Wq, D_DIM, D_DIM, wqam);
    colamax_kernel<<<dim3(64, 64),  blk>>>(Wk, D_DIM, D_DIM, wkam);
    colamax_kernel<<<dim3(64, 64),  blk>>>(Wv, D_DIM, D_DIM, wvam);
    colamax_kernel<<<dim3(64, 64),  blk>>>(Wo, D_DIM, D_DIM, woam);
    colamax_kernel<<<dim3(M_FF / 32,  D_DIM / 32), blk>>>(W1, D_DIM, M_FF, w1am);
    colamax_kernel<<<dim3(D_DIM / 32, M_FF / 32),  blk>>>(W2, M_FF, D_DIM, w2am);
    transpose_quant_i8<<<dim3(64, 64),  blk>>>(Wq, wqam, wqq1, wqq2, wqs, D_DIM, D_DIM);
    transpose_quant_i8<<<dim3(64, 64),  blk>>>(Wk, wkam, wkq1, wkq2, wks, D_DIM, D_DIM);
    transpose_quant_i8<<<dim3(64, 64),  blk>>>(Wv, wvam, wvq1, wvq2, wvs, D_DIM, D_DIM);
    transpose_quant_i8<<<dim3(64, 64),  blk>>>(Wo, woam, woq1, woq2, wos, D_DIM, D_DIM);
    transpose_quant_i8<<<dim3(256, 64), blk>>>(W1, w1am, w1q1, w1q2, w1s, D_DIM, M_FF);
    transpose_quant_i8<<<dim3(64, 256), blk>>>(W2, w2am, w2q1, w2q2, w2s, M_FF, D_DIM);

    const dim3 gDD(D_DIM / 128, ROWS / 128);   // (16, 32)
    const dim3 gDM(M_FF / 128,  ROWS / 128);   // (64, 32)

    // ---- layer ----
    ln_quant_i8<<<ROWS, blk>>>(x, ln1g, ln1b, hq1, hq2, hs);
    gemm_i8<false, false, false><<<gDD, blk, I8_SMEM>>>(
        hq1, hq2, wqq1, wqq2, hs, wqs, nullptr, nullptr, q, D_DIM, D_DIM);
    gemm_i8<false, false, false><<<gDD, blk, I8_SMEM>>>(
        hq1, hq2, wkq1, wkq2, hs, wks, nullptr, nullptr, k, D_DIM, D_DIM);
    gemm_i8<false, false, false><<<gDD, blk, I8_SMEM>>>(
        hq1, hq2, wvq1, wvq2, hs, wvs, nullptr, nullptr, v, D_DIM, D_DIM);
    attn_kernel<<<dim3(S_LEN / 64, NH, B_SZ), blk, ATT_SMEM_BYTES>>>(q, k, v, attn);
    rowquant_i8<<<ROWS, blk>>>(attn, D_DIM, atq1, atq2, ats);
    gemm_i8<false, false, true><<<gDD, blk, I8_SMEM>>>(
        atq1, atq2, woq1, woq2, ats, wos, nullptr, x, x2, D_DIM, D_DIM);
    ln_quant_i8<<<ROWS, blk>>>(x2, ln2g, ln2b, hq1, hq2, hs);
    gemm_i8<true, true, false><<<gDM, blk, I8_SMEM>>>(
        hq1, hq2, w1q1, w1q2, hs, w1s, b1, nullptr, ff, M_FF, D_DIM);
    rowquant_i8<<<ROWS, blk>>>(ff, M_FF, ffq1, ffq2, ffs);
    gemm_i8<false, true, true><<<gDD, blk, I8_SMEM>>>(
        ffq1, ffq2, w2q1, w2q2, ffs, w2s, b2, x2, out, D_DIM, M_FF);
}

// round 10
// speedup vs baseline: 3.7883x; 1.4142x over previous
#include <cuda_runtime.h>
#include <cuda_bf16.h>
#include <cstdint>
#include <math.h>

// Problem constants
#define S_LEN 2048
#define D_DIM 2048
#define B_SZ  2
#define NH    16
#define HD    128
#define M_FF  8192
#define ROWS  (B_SZ * S_LEN)   // 4096

typedef __nv_bfloat16 bf16;

// -------------------- scratch (device globals; no allocation allowed) -----
__device__ __align__(16) int8_t g_h_q1  [ROWS * D_DIM];
__device__ __align__(16) int8_t g_h_q2  [ROWS * D_DIM];
__device__            float  g_h_s   [ROWS];
__device__ __align__(16) float g_q     [ROWS * D_DIM];
__device__ __align__(16) float g_k     [ROWS * D_DIM];
__device__ __align__(16) float g_v     [ROWS * D_DIM];
__device__ __align__(16) float g_attn  [ROWS * D_DIM];
__device__ __align__(16) int8_t g_at_q1 [ROWS * D_DIM];
__device__ __align__(16) int8_t g_at_q2 [ROWS * D_DIM];
__device__            float  g_at_s  [ROWS];
__device__ __align__(16) float g_x2    [ROWS * D_DIM];
__device__ __align__(16) float g_ff    [ROWS * M_FF];
__device__ __align__(16) int8_t g_ff_q1 [ROWS * M_FF];
__device__ __align__(16) int8_t g_ff_q2 [ROWS * M_FF];
__device__            float  g_ff_s  [ROWS];
// attention int8/bf16 operands (flat layout; per-(head,j) scales at [bh*S+j])
__device__ __align__(16) int8_t g_q_q1  [ROWS * D_DIM];
__device__ __align__(16) int8_t g_q_q2  [ROWS * D_DIM];
__device__            float  g_q_sc  [ROWS * NH];
__device__ __align__(16) int8_t g_k_q1  [ROWS * D_DIM];
__device__ __align__(16) int8_t g_k_q2  [ROWS * D_DIM];
__device__            float  g_k_sc  [ROWS * NH];
__device__ __align__(16) bf16  g_vt    [B_SZ * NH * HD * S_LEN];   // [bh][c][j]
// int8 2-limb weights ([N][K])
__device__ __align__(16) int8_t g_wq_q1 [D_DIM * D_DIM];
__device__ __align__(16) int8_t g_wq_q2 [D_DIM * D_DIM];
__device__            float  g_wq_am [D_DIM];
__device__            float  g_wq_s  [D_DIM];
__device__ __align__(16) int8_t g_wk_q1 [D_DIM * D_DIM];
__device__ __align__(16) int8_t g_wk_q2 [D_DIM * D_DIM];
__device__            float  g_wk_am [D_DIM];
__device__            float  g_wk_s  [D_DIM];
__device__ __align__(16) int8_t g_wv_q1 [D_DIM * D_DIM];
__device__ __align__(16) int8_t g_wv_q2 [D_DIM * D_DIM];
__device__            float  g_wv_am [D_DIM];
__device__            float  g_wv_s  [D_DIM];
__device__ __align__(16) int8_t g_wo_q1 [D_DIM * D_DIM];
__device__ __align__(16) int8_t g_wo_q2 [D_DIM * D_DIM];
__device__            float  g_wo_am [D_DIM];
__device__            float  g_wo_s  [D_DIM];
__device__ __align__(16) int8_t g_w1_q1 [M_FF * D_DIM];
__device__ __align__(16) int8_t g_w1_q2 [M_FF * D_DIM];
__device__            float  g_w1_am [M_FF];
__device__            float  g_w1_s  [M_FF];
__device__ __align__(16) int8_t g_w2_q1 [D_DIM * M_FF];
__device__ __align__(16) int8_t g_w2_q2 [D_DIM * M_FF];
__device__            float  g_w2_am [D_DIM];
__device__            float  g_w2_s  [D_DIM];

// ===========================================================================
// helpers
// ===========================================================================
__device__ __forceinline__ uint32_t smem_u32(const void* p) {
    uint32_t a;
    asm("{ .reg .u64 t; cvta.to.shared.u64 t, %1; cvt.u32.u64 %0, t; }" : "=r"(a) : "l"(p));
    return a;
}
__device__ __forceinline__ void cpa16(uint32_t dst, const void* src) {
    asm volatile("cp.async.cg.shared.global [%0], [%1], 16;" :: "r"(dst), "l"(src));
}
#define CP_COMMIT() asm volatile("cp.async.commit_group;" ::: "memory")
#define CP_WAIT1()  asm volatile("cp.async.wait_group 1;" ::: "memory")

__device__ __forceinline__ void ldmx4(uint32_t* r, uint32_t addr) {
    asm volatile("ldmatrix.sync.aligned.m8n8.x4.shared.b16 {%0,%1,%2,%3}, [%4];"
        : "=r"(r[0]), "=r"(r[1]), "=r"(r[2]), "=r"(r[3]) : "r"(addr));
}
__device__ __forceinline__ void mma_bf16(float* d, const uint32_t* a, uint32_t b0, uint32_t b1) {
    asm volatile(
        "mma.sync.aligned.m16n8k16.row.col.f32.bf16.bf16.f32 "
        "{%0,%1,%2,%3},{%4,%5,%6,%7},{%8,%9},{%0,%1,%2,%3};"
        : "+f"(d[0]), "+f"(d[1]), "+f"(d[2]), "+f"(d[3])
        : "r"(a[0]), "r"(a[1]), "r"(a[2]), "r"(a[3]), "r"(b0), "r"(b1));
}
__device__ __forceinline__ void mma_s8(int* d, const uint32_t* a, uint32_t b0, uint32_t b1) {
    asm volatile(
        "mma.sync.aligned.m16n8k32.row.col.s32.s8.s8.s32 "
        "{%0,%1,%2,%3},{%4,%5,%6,%7},{%8,%9},{%0,%1,%2,%3};"
        : "+r"(d[0]), "+r"(d[1]), "+r"(d[2]), "+r"(d[3])
        : "r"(a[0]), "r"(a[1]), "r"(a[2]), "r"(a[3]), "r"(b0), "r"(b1));
}
__device__ __forceinline__ void quant2(float v, float inv_s, int8_t& h, int8_t& l) {
    float q  = v * inv_s;
    float q1 = rintf(q);
    float q2 = rintf((q - q1) * 256.0f);
    q2 = fminf(fmaxf(q2, -127.0f), 127.0f);
    h = (int8_t)(int)q1;
    l = (int8_t)(int)q2;
}

// ===========================================================================
// per-column absmax
// ===========================================================================
__global__ __launch_bounds__(256)
void colamax_kernel(const float* __restrict__ in, int R, int C, float* __restrict__ amax)
{
    __shared__ float sm_[8][33];
    const int tx = threadIdx.x & 31;
    const int ty = threadIdx.x >> 5;
    const int bx = blockIdx.x * 32, by = blockIdx.y * 32;
    float m = 0.f;
#pragma unroll
    for (int j = 0; j < 4; ++j)
        m = fmaxf(m, fabsf(in[(size_t)(by + ty + 8 * j) * C + bx + tx]));
    sm_[ty][tx] = m;
    __syncthreads();
    if (ty == 0) {
        float mm = sm_[0][tx];
#pragma unroll
        for (int r = 1; r < 8; ++r) mm = fmaxf(mm, sm_[r][tx]);
        atomicMax((unsigned int*)&amax[bx + tx], __float_as_uint(mm));
    }
}

// ===========================================================================
// transpose + int8 2-limb quant (weights)
// ===========================================================================
__global__ __launch_bounds__(256)
void transpose_quant_i8(const float* __restrict__ in, const float* __restrict__ amax,
                        int8_t* __restrict__ q1o, int8_t* __restrict__ q2o,
                        float* __restrict__ sOut, int R, int C)
{
    __shared__ float tile[32][33];
    const int tx = threadIdx.x & 31;
    const int ty = threadIdx.x >> 5;
    const int bx = blockIdx.x * 32, by = blockIdx.y * 32;
#pragma unroll
    for (int j = 0; j < 32; j += 8)
        tile[ty + j][tx] = in[(size_t)(by + ty + j) * C + bx + tx];
    __syncthreads();
#pragma unroll
    for (int j = 0; j < 32; j += 8) {
        const int orow = bx + ty + j;
        float am = fmaxf(amax[orow], 1e-20f);
        float s  = am * (1.0f / 127.0f);
        float inv = 127.0f / am;
        if (tx == 0) sOut[orow] = s;
        float v = tile[tx][ty + j];
        int8_t h, l; quant2(v, inv, h, l);
        size_t o = (size_t)orow * R + by + tx;
        q1o[o] = h; q2o[o] = l;
    }
}

// ===========================================================================
// per-row int8 2-limb quant
// ===========================================================================
__global__ __launch_bounds__(256)
void rowquant_i8(const float* __restrict__ in, int Kd,
                 int8_t* __restrict__ q1, int8_t* __restrict__ q2, float* __restrict__ s)
{
    __shared__ float red[9];
    const int row = blockIdx.x;
    const int tid = threadIdx.x;
    const float* r = in + (size_t)row * Kd;
    float m = 0.f;
    for (int c = tid; c < Kd; c += 256) m = fmaxf(m, fabsf(r[c]));
#pragma unroll
    for (int d = 16; d > 0; d >>= 1) m = fmaxf(m, __shfl_xor_sync(0xffffffffu, m, d));
    if ((tid & 31) == 0) red[tid >> 5] = m;
    __syncthreads();
    if (tid == 0) {
        float mm = red[0];
#pragma unroll
        for (int i = 1; i < 8; ++i) mm = fmaxf(mm, red[i]);
        mm = fmaxf(mm, 1e-20f);
        red[8] = mm;
        s[row] = mm * (1.0f / 127.0f);
    }
    __syncthreads();
    const float inv = 127.0f / red[8];
    for (int c = tid; c < Kd; c += 256) {
        int8_t h, l; quant2(r[c], inv, h, l);
        q1[(size_t)row * Kd + c] = h;
        q2[(size_t)row * Kd + c] = l;
    }
}

// ===========================================================================
// per-128-segment int8 2-limb quant (Q/K). One flat row per block.
// Flat row r, segment s  <=>  quirk-space (bh = r/128 with head=(r%2048)/128,
// j = (r%128)*16 + s).  Scale stored at sArr[r*16+s] == sArr[bh*S_LEN + j].
// ===========================================================================
__global__ __launch_bounds__(256)
void quant_head_i8(const float* __restrict__ in, int8_t* __restrict__ q1,
                   int8_t* __restrict__ q2, float* __restrict__ sArr)
{
    const int row = blockIdx.x;
    const int t = threadIdx.x;
    const int c0 = t * 8;
    const int seg = t >> 4;
    float v[8];
    *(float4*)&v[0] = *(const float4*)(in + (size_t)row * D_DIM + c0);
    *(float4*)&v[4] = *(const float4*)(in + (size_t)row * D_DIM + c0 + 4);
    float am = 0.f;
#pragma unroll
    for (int i = 0; i < 8; ++i) am = fmaxf(am, fabsf(v[i]));
#pragma unroll
    for (int d = 1; d < 16; d <<= 1)
        am = fmaxf(am, __shfl_xor_sync(0xffffffffu, am, d));
    am = fmaxf(am, 1e-20f);
    if ((t & 15) == 0) sArr[row * NH + seg] = am * (1.0f / 127.0f);
    const float inv = 127.0f / am;
    int8_t h[8], l[8];
#pragma unroll
    for (int i = 0; i < 8; ++i) quant2(v[i], inv, h[i], l[i]);
    *(uint2*)(q1 + (size_t)row * D_DIM + c0) = *(uint2*)h;
    *(uint2*)(q2 + (size_t)row * D_DIM + c0) = *(uint2*)l;
}

// ===========================================================================
// V^T split (QUIRK layout): v flat block bh is (2048 j x 128 c);
// vt[bh][c][j] = bf16(v_flat[bh*262144 + j*128 + c])
// ===========================================================================
__global__ __launch_bounds__(256)
void vt_split(const float* __restrict__ v, bf16* __restrict__ vt)
{
    __shared__ float tile[32][33];
    const int tx = threadIdx.x & 31;
    const int ty = threadIdx.x >> 5;
    const int bh = blockIdx.z;
    const int j0 = blockIdx.x * 32, c0 = blockIdx.y * 32;
    const float* vb = v + (size_t)bh * S_LEN * HD;
#pragma unroll
    for (int jj = 0; jj < 32; jj += 8)
        tile[ty + jj][tx] = vb[(size_t)(j0 + ty + jj) * HD + c0 + tx];
    __syncthreads();
#pragma unroll
    for (int jj = 0; jj < 32; jj += 8)
        vt[((size_t)bh * HD + c0 + ty + jj) * S_LEN + j0 + tx] =
            __float2bfloat16_rn(tile[tx][ty + jj]);
}

// ===========================================================================
// LayerNorm + int8 2-limb quant
// ===========================================================================
__global__ __launch_bounds__(256)
void ln_quant_i8(const float* __restrict__ x, const float* __restrict__ gam,
                 const float* __restrict__ bet, int8_t* __restrict__ q1,
                 int8_t* __restrict__ q2, float* __restrict__ sArr)
{
    __shared__ float red[9];
    const int row = blockIdx.x;
    const int tid = threadIdx.x;
    const float* xr = x + (size_t)row * D_DIM;

    float v[8];
    float sum = 0.f;
#pragma unroll
    for (int i = 0; i < 8; ++i) { v[i] = xr[tid + 256 * i]; sum += v[i]; }
#pragma unroll
    for (int d = 16; d > 0; d >>= 1) sum += __shfl_xor_sync(0xffffffffu, sum, d);
    if ((tid & 31) == 0) red[tid >> 5] = sum;
    __syncthreads();
    float tot = 0.f;
#pragma unroll
    for (int i = 0; i < 8; ++i) tot += red[i];
    const float mean = tot * (1.0f / (float)D_DIM);

    float s2 = 0.f;
#pragma unroll
    for (int i = 0; i < 8; ++i) { float d = v[i] - mean; s2 += d * d; }
    __syncthreads();
#pragma unroll
    for (int d = 16; d > 0; d >>= 1) s2 += __shfl_xor_sync(0xffffffffu, s2, d);
    if ((tid & 31) == 0) red[tid >> 5] = s2;
    __syncthreads();
    tot = 0.f;
#pragma unroll
    for (int i = 0; i < 8; ++i) tot += red[i];
    const float rstd = rsqrtf(tot * (1.0f / (float)D_DIM) + 1e-5f);

    float o[8];
    float am = 0.f;
#pragma unroll
    for (int i = 0; i < 8; ++i) {
        int c = tid + 256 * i;
        o[i] = (v[i] - mean) * rstd * gam[c] + bet[c];
        am = fmaxf(am, fabsf(o[i]));
    }
    __syncthreads();
#pragma unroll
    for (int d = 16; d > 0; d >>= 1) am = fmaxf(am, __shfl_xor_sync(0xffffffffu, am, d));
    if ((tid & 31) == 0) red[tid >> 5] = am;
    __syncthreads();
    if (tid == 0) {
        float mm = red[0];
#pragma unroll
        for (int i = 1; i < 8; ++i) mm = fmaxf(mm, red[i]);
        mm = fmaxf(mm, 1e-20f);
        red[8] = mm;
        sArr[row] = mm * (1.0f / 127.0f);
    }
    __syncthreads();
    const float inv = 127.0f / red[8];
#pragma unroll
    for (int i = 0; i < 8; ++i) {
        int c = tid + 256 * i;
        int8_t h, l; quant2(o[i], inv, h, l);
        q1[(size_t)row * D_DIM + c] = h;
        q2[(size_t)row * D_DIM + c] = l;
    }
}

// ===========================================================================
// int8 2-limb tensor-core GEMM (all 6 GEMMs)
// ===========================================================================
#define ISTAGE 32768
#define ISM_A2 8192
#define ISM_B1 16384
#define ISM_B2 24576
#define I8_SMEM (3 * ISTAGE)

template<bool RELU, bool HAS_BIAS, bool HAS_RES>
__global__ __launch_bounds__(256, 1)
void gemm_i8(const int8_t* __restrict__ A1, const int8_t* __restrict__ A2,
             const int8_t* __restrict__ B1, const int8_t* __restrict__ B2,
             const float* __restrict__ sA, const float* __restrict__ sB,
             const float* __restrict__ bias, const float* __restrict__ res,
             float* __restrict__ Cf, int Nd, int Kd)
{
    extern __shared__ char smem[];
    const uint32_t sb = smem_u32(smem);
    const int tid  = threadIdx.x;
    const int warp = tid >> 5;
    const int lane = tid & 31;
    const int wm   = warp & 1;
    const int wn   = warp >> 1;
    const int bx = blockIdx.x, by = blockIdx.y;
    const int ktiles = Kd >> 6;

    const int r0 = tid >> 2;
    const int cc = tid & 3;
    const int pc = (cc + (r0 >> 1)) & 3;
    const size_t gA0 = (size_t)(by * 128 + r0) * Kd + cc * 16;
    const size_t gB0 = (size_t)(bx * 128 + r0) * Kd + cc * 16;
    const size_t step64 = (size_t)64 * Kd;
    const int8_t* pA1 = A1 + gA0;  const int8_t* pA2 = A2 + gA0;
    const int8_t* pB1 = B1 + gB0;  const int8_t* pB2 = B2 + gB0;
    const uint32_t dA0 = (uint32_t)(r0 * 64 + pc * 16);
    const uint32_t dA1 = dA0 + 64 * 64;

#define ISSUE_I8(slot, u) do { \
    uint32_t s0_ = sb + (slot) * ISTAGE; int ko_ = (u) * 64; \
    cpa16(s0_ + dA0,          pA1 + ko_); cpa16(s0_ + dA1,          pA1 + step64 + ko_); \
    cpa16(s0_ + dA0 + ISM_A2, pA2 + ko_); cpa16(s0_ + dA1 + ISM_A2, pA2 + step64 + ko_); \
    cpa16(s0_ + dA0 + ISM_B1, pB1 + ko_); cpa16(s0_ + dA1 + ISM_B1, pB1 + step64 + ko_); \
    cpa16(s0_ + dA0 + ISM_B2, pB2 + ko_); cpa16(s0_ + dA1 + ISM_B2, pB2 + step64 + ko_); \
} while (0)

    const int l15   = lane & 15;
    const int chalf = lane >> 4;
    const uint32_t pc0 = (uint32_t)((chalf + (l15 >> 1)) & 3);
    const uint32_t pc1 = (uint32_t)((2 + chalf + (l15 >> 1)) & 3);
    const uint32_t offA[2] = { (uint32_t)((wm * 64 + l15) * 64) + pc0 * 16,
                               (uint32_t)((wm * 64 + l15) * 64) + pc1 * 16 };
    const uint32_t offB0[2] = { (uint32_t)((wn * 32 + l15) * 64) + pc0 * 16,
                                (uint32_t)((wn * 32 + l15) * 64) + pc1 * 16 };
    const uint32_t offB1[2] = { (uint32_t)((wn * 32 + 16 + l15) * 64) + pc0 * 16,
                                (uint32_t)((wn * 32 + 16 + l15) * 64) + pc1 * 16 };

    int accH[4][4][4], accM[4][4][4];
#pragma unroll
    for (int mt = 0; mt < 4; ++mt)
#pragma unroll
        for (int nt = 0; nt < 4; ++nt)
#pragma unroll
            for (int e = 0; e < 4; ++e) { accH[mt][nt][e] = 0; accM[mt][nt][e] = 0; }

    ISSUE_I8(0, 0); CP_COMMIT();
    ISSUE_I8(1, 1); CP_COMMIT();

    for (int t = 0; t < ktiles; ++t) {
        CP_WAIT1();
        __syncthreads();
        {
            const int u = t + 2;
            if (u < ktiles) { ISSUE_I8(u % 3, u); }
            CP_COMMIT();
        }
        const uint32_t st = sb + (t % 3) * ISTAGE;
#pragma unroll
        for (int j = 0; j < 2; ++j) {
            uint32_t b1F[8], b2F[8];
            ldmx4(&b1F[0], st + ISM_B1 + offB0[j]);
            ldmx4(&b1F[4], st + ISM_B1 + offB1[j]);
            ldmx4(&b2F[0], st + ISM_B2 + offB0[j]);
            ldmx4(&b2F[4], st + ISM_B2 + offB1[j]);
#pragma unroll
            for (int mt = 0; mt < 4; ++mt) {
                uint32_t a1F[4], a2F[4];
                ldmx4(a1F, st + mt * 1024 + offA[j]);
                ldmx4(a2F, st + ISM_A2 + mt * 1024 + offA[j]);
#pragma unroll
                for (int nt = 0; nt < 4; ++nt) {
                    const int p = (nt >> 1) * 4 + (nt & 1);
                    const uint32_t b0h = b1F[p], b1h = b1F[p + 2];
                    const uint32_t b0l = b2F[p], b1l = b2F[p + 2];
                    mma_s8(accH[mt][nt], a1F, b0h, b1h);
                    mma_s8(accM[mt][nt], a2F, b0h, b1h);
                    mma_s8(accM[mt][nt], a1F, b0l, b1l);
                }
            }
        }
    }

    const int g  = lane >> 2;
    const int tg = lane & 3;
#pragma unroll
    for (int mt = 0; mt < 4; ++mt) {
        const int row = by * 128 + wm * 64 + mt * 16 + g;
        const float sa0 = sA[row], sa8 = sA[row + 8];
#pragma unroll
        for (int nt = 0; nt < 4; ++nt) {
            const int col = bx * 128 + wn * 32 + nt * 8 + 2 * tg;
            const float sb0 = sB[col], sb1 = sB[col + 1];
            float v0 = sa0 * sb0 * ((float)accH[mt][nt][0] + (float)accM[mt][nt][0] * 0.00390625f);
            float v1 = sa0 * sb1 * ((float)accH[mt][nt][1] + (float)accM[mt][nt][1] * 0.00390625f);
            float v2 = sa8 * sb0 * ((float)accH[mt][nt][2] + (float)accM[mt][nt][2] * 0.00390625f);
            float v3 = sa8 * sb1 * ((float)accH[mt][nt][3] + (float)accM[mt][nt][3] * 0.00390625f);
            if (HAS_BIAS) {
                float2 b2v = *(const float2*)(bias + col);
                v0 += b2v.x; v1 += b2v.y; v2 += b2v.x; v3 += b2v.y;
            }
            if (RELU) {
                v0 = fmaxf(v0, 0.f); v1 = fmaxf(v1, 0.f);
                v2 = fmaxf(v2, 0.f); v3 = fmaxf(v3, 0.f);
            }
            if (HAS_RES) {
                float2 ra = *(const float2*)(res + (size_t)row * Nd + col);
                float2 rb = *(const float2*)(res + (size_t)(row + 8) * Nd + col);
                v0 += ra.x; v1 += ra.y; v2 += rb.x; v3 += rb.y;
            }
            *(float2*)(Cf + (size_t)row * Nd + col)       = make_float2(v0, v1);
            *(float2*)(Cf + (size_t)(row + 8) * Nd + col) = make_float2(v2, v3);
        }
    }
#undef ISSUE_I8
}

// ===========================================================================
// Tensor-core flash attention (QUIRK layout):
// Q/K int8 blocks: base + bh*S*HD + j*HD + c ; scales at [bh*S + j].
// Output written standard: O[b, i, head*128 + c].
// ===========================================================================
#define AQ_H  0
#define AQ_L  18432
#define AK_H(bf) (36864 + (bf) * 18432)
#define AK_L(bf) (AK_H(bf) + 9216)
#define AVT(bf)  (73728 + (bf) * 18432)
#define APS_H 110592
#define APS_L 129024
#define ASQ   147456
#define ASK(bf) (147968 + (bf) * 256)
#define ATT_SMEM 148480

__global__ __launch_bounds__(256)
void attn_i8(const int8_t* __restrict__ Qq1, const int8_t* __restrict__ Qq2,
             const float* __restrict__ Qs,
             const int8_t* __restrict__ Kq1, const int8_t* __restrict__ Kq2,
             const float* __restrict__ Ks,
             const bf16* __restrict__ VT, float* __restrict__ O)
{
    extern __shared__ char smem[];
    const uint32_t sb = smem_u32(smem);
    float* sQf = (float*)(smem + ASQ);
    const int qt   = blockIdx.x;       // 0..15
    const int head = blockIdx.y;
    const int b    = blockIdx.z;
    const int tid  = threadIdx.x;
    const int warp = tid >> 5;
    const int lane = tid & 31;
    const int l15  = lane & 15;
    const int lhalf = lane >> 4;
    const int g  = lane >> 2;
    const int tg = lane & 3;
    const int mrow = warp * 16;
    const int ntiles = 2 * qt + 2;
    const int bh = b * NH + head;
    const size_t hbase = (size_t)bh * S_LEN * HD;      // flat head block
    const int i0 = qt * 128;                            // quirk seq base
    const bf16* vth = VT + (size_t)bh * HD * S_LEN;

    // Q scales
    if (tid < 128) sQf[tid] = Qs[(size_t)bh * S_LEN + i0 + tid];

    // Q tile (once): 128 rows x 128B per limb, quirk flat addressing
#pragma unroll
    for (int i = 0; i < 4; ++i) {
        int id = tid + 256 * i;
        int r = id >> 3, c = (id & 7) * 16;
        cpa16(sb + AQ_H + r * 144 + c, Qq1 + hbase + (size_t)(i0 + r) * HD + c);
        cpa16(sb + AQ_L + r * 144 + c, Qq2 + hbase + (size_t)(i0 + r) * HD + c);
    }

#define ATT_ISSUE(bf_, jt_) do { \
    const size_t kj0_ = (size_t)(jt_) * 64; \
    for (int i_ = tid; i_ < 512; i_ += 256) { \
        int r_ = i_ >> 3, c_ = (i_ & 7) * 16; \
        cpa16(sb + AK_H(bf_) + r_ * 144 + c_, Kq1 + hbase + (kj0_ + r_) * HD + c_); \
        cpa16(sb + AK_L(bf_) + r_ * 144 + c_, Kq2 + hbase + (kj0_ + r_) * HD + c_); \
    } \
    for (int i_ = tid; i_ < 1024; i_ += 256) { \
        int r_ = i_ >> 3, c_ = (i_ & 7) * 16; \
        cpa16(sb + AVT(bf_) + r_ * 144 + c_, \
              (const char*)(vth + (size_t)r_ * S_LEN + kj0_) + c_); \
    } \
    if (tid < 64) ((float*)(smem + ASK(bf_)))[tid] = Ks[(size_t)bh * S_LEN + kj0_ + tid]; \
} while (0)

    ATT_ISSUE(0, 0); CP_COMMIT();
    ATT_ISSUE(1, 1); CP_COMMIT();

    float o_acc[16][4];
#pragma unroll
    for (int ot = 0; ot < 16; ++ot)
#pragma unroll
        for (int e = 0; e < 4; ++e) o_acc[ot][e] = 0.f;
    float m0 = -1e30f, m1 = -1e30f, l0 = 0.f, l1 = 0.f;
    const float inv_sqrt_d = 0.08838834764831845f;
    const float inv256 = 0.00390625f;
    const int i_g0 = i0 + mrow + g;
    const int i_g1 = i_g0 + 8;

    const uint32_t qbH = sb + AQ_H + (mrow + l15) * 144 + lhalf * 16;
    const uint32_t qbL = sb + AQ_L + (mrow + l15) * 144 + lhalf * 16;
    const uint32_t pbH = sb + APS_H + (mrow + l15) * 144 + lhalf * 16;
    const uint32_t pbL = sb + APS_L + (mrow + l15) * 144 + lhalf * 16;

    for (int jt = 0; jt < ntiles; ++jt) {
        const int buf = jt & 1;
        CP_WAIT1();
        __syncthreads();
        const float* sKf = (const float*)(smem + ASK(buf));

        // ---- S = Q K^T (int8 2-limb), warp tile m16 x n64 ----
        int accH[8][4], accM[8][4];
#pragma unroll
        for (int nt = 0; nt < 8; ++nt)
#pragma unroll
            for (int e = 0; e < 4; ++e) { accH[nt][e] = 0; accM[nt][e] = 0; }

#pragma unroll
        for (int ks = 0; ks < 4; ++ks) {
            uint32_t aH[4], aL[4];
            ldmx4(aH, qbH + ks * 32);
            ldmx4(aL, qbL + ks * 32);
#pragma unroll
            for (int ng = 0; ng < 4; ++ng) {
                uint32_t bH4[4], bL4[4];
                const uint32_t kaddr = (uint32_t)((ng * 16 + l15) * 144) + lhalf * 16 + ks * 32;
                ldmx4(bH4, sb + AK_H(buf) + kaddr);
                ldmx4(bL4, sb + AK_L(buf) + kaddr);
                mma_s8(accH[2 * ng],     aH, bH4[0], bH4[2]);
                mma_s8(accM[2 * ng],     aL, bH4[0], bH4[2]);
                mma_s8(accM[2 * ng],     aH, bL4[0], bL4[2]);
                mma_s8(accH[2 * ng + 1], aH, bH4[1], bH4[3]);
                mma_s8(accM[2 * ng + 1], aL, bH4[1], bH4[3]);
                mma_s8(accM[2 * ng + 1], aH, bL4[1], bL4[3]);
            }
        }

        // ---- descale + mask + online softmax ----
        const float sq0 = sQf[mrow + g], sq1 = sQf[mrow + g + 8];
        const bool diag = (jt >= 2 * qt);
        float sv[8][4];
        float rm0 = -1e30f, rm1 = -1e30f;
#pragma unroll
        for (int nt = 0; nt < 8; ++nt) {
            const int col0 = nt * 8 + 2 * tg;
            const float sk0 = sKf[col0], sk1 = sKf[col0 + 1];
            float s00 = sq0 * sk0 * ((float)accH[nt][0] + (float)accM[nt][0] * inv256);
            float s01 = sq0 * sk1 * ((float)accH[nt][1] + (float)accM[nt][1] * inv256);
            float s10 = sq1 * sk0 * ((float)accH[nt][2] + (float)accM[nt][2] * inv256);
            float s11 = sq1 * sk1 * ((float)accH[nt][3] + (float)accM[nt][3] * inv256);
            if (diag) {
                const int j0g = jt * 64 + col0;
                if (j0g     > i_g0) s00 = -1e9f;
                if (j0g + 1 > i_g0) s01 = -1e9f;
                if (j0g     > i_g1) s10 = -1e9f;
                if (j0g + 1 > i_g1) s11 = -1e9f;
            }
            s00 *= inv_sqrt_d; s01 *= inv_sqrt_d; s10 *= inv_sqrt_d; s11 *= inv_sqrt_d;
            sv[nt][0] = s00; sv[nt][1] = s01; sv[nt][2] = s10; sv[nt][3] = s11;
            rm0 = fmaxf(rm0, fmaxf(s00, s01));
            rm1 = fmaxf(rm1, fmaxf(s10, s11));
        }
        rm0 = fmaxf(rm0, __shfl_xor_sync(0xffffffffu, rm0, 1));
        rm0 = fmaxf(rm0, __shfl_xor_sync(0xffffffffu, rm0, 2));
        rm1 = fmaxf(rm1, __shfl_xor_sync(0xffffffffu, rm1, 1));
        rm1 = fmaxf(rm1, __shfl_xor_sync(0xffffffffu, rm1, 2));
        const float mn0 = fmaxf(m0, rm0), mn1 = fmaxf(m1, rm1);
        const float cr0 = __expf(m0 - mn0), cr1 = __expf(m1 - mn1);
        m0 = mn0; m1 = mn1;
        float rs0 = 0.f, rs1 = 0.f;
#pragma unroll
        for (int nt = 0; nt < 8; ++nt) {
            float p00 = __expf(sv[nt][0] - mn0);
            float p01 = __expf(sv[nt][1] - mn0);
            float p10 = __expf(sv[nt][2] - mn1);
            float p11 = __expf(sv[nt][3] - mn1);
            rs0 += p00 + p01; rs1 += p10 + p11;
            bf16 h00 = __float2bfloat16_rn(p00), h01 = __float2bfloat16_rn(p01);
            bf16 h10 = __float2bfloat16_rn(p10), h11 = __float2bfloat16_rn(p11);
            bf16 l00b = __float2bfloat16_rn(p00 - __bfloat162float(h00));
            bf16 l01b = __float2bfloat16_rn(p01 - __bfloat162float(h01));
            bf16 l10b = __float2bfloat16_rn(p10 - __bfloat162float(h10));
            bf16 l11b = __float2bfloat16_rn(p11 - __bfloat162float(h11));
            const uint32_t cofs = (uint32_t)((nt * 8 + 2 * tg) * 2);
            *(__nv_bfloat162*)(smem + APS_H + (mrow + g) * 144 + cofs)     = __nv_bfloat162(h00, h01);
            *(__nv_bfloat162*)(smem + APS_H + (mrow + g + 8) * 144 + cofs) = __nv_bfloat162(h10, h11);
            *(__nv_bfloat162*)(smem + APS_L + (mrow + g) * 144 + cofs)     = __nv_bfloat162(l00b, l01b);
            *(__nv_bfloat162*)(smem + APS_L + (mrow + g + 8) * 144 + cofs) = __nv_bfloat162(l10b, l11b);
        }
        rs0 += __shfl_xor_sync(0xffffffffu, rs0, 1);
        rs0 += __shfl_xor_sync(0xffffffffu, rs0, 2);
        rs1 += __shfl_xor_sync(0xffffffffu, rs1, 1);
        rs1 += __shfl_xor_sync(0xffffffffu, rs1, 2);
        l0 = l0 * cr0 + rs0;
        l1 = l1 * cr1 + rs1;
#pragma unroll
        for (int ot = 0; ot < 16; ++ot) {
            o_acc[ot][0] *= cr0; o_acc[ot][1] *= cr0;
            o_acc[ot][2] *= cr1; o_acc[ot][3] *= cr1;
        }
        __syncwarp();

        // ---- O += P V (P 2-limb bf16, V bf16), warp tile m16 x n128 ----
#pragma unroll
        for (int ks = 0; ks < 4; ++ks) {
            uint32_t aH[4], aL[4];
            ldmx4(aH, pbH + ks * 32);
            ldmx4(aL, pbL + ks * 32);
#pragma unroll
            for (int vg = 0; vg < 8; ++vg) {
                uint32_t vb[4];
                ldmx4(vb, sb + AVT(buf) + (uint32_t)((vg * 16 + l15) * 144) + lhalf * 16 + ks * 32);
                mma_bf16(o_acc[2 * vg],     aH, vb[0], vb[2]);
                mma_bf16(o_acc[2 * vg],     aL, vb[0], vb[2]);
                mma_bf16(o_acc[2 * vg + 1], aH, vb[1], vb[3]);
                mma_bf16(o_acc[2 * vg + 1], aL, vb[1], vb[3]);
            }
        }
        __syncthreads();
        if (jt + 2 < ntiles) { ATT_ISSUE(buf, jt + 2); }
        CP_COMMIT();
    }

    // ---- normalize + write (standard output concat) ----
    const float li0 = 1.0f / l0, li1 = 1.0f / l1;
    float* orow0 = O + ((size_t)b * S_LEN + i0 + mrow + g)     * D_DIM + head * HD;
    float* orow1 = O + ((size_t)b * S_LEN + i0 + mrow + g + 8) * D_DIM + head * HD;
#pragma unroll
    for (int ot = 0; ot < 16; ++ot) {
        const int col = ot * 8 + 2 * tg;
        *(float2*)(orow0 + col) = make_float2(o_acc[ot][0] * li0, o_acc[ot][1] * li0);
        *(float2*)(orow1 + col) = make_float2(o_acc[ot][2] * li1, o_acc[ot][3] * li1);
    }
#undef ATT_ISSUE
}

// ===========================================================================
// Launch
// ===========================================================================
extern "C" void kernel_launch(void* const* d_in, const int* in_sizes, int n_in,
                              void* d_out, int out_size)
{
    (void)in_sizes; (void)n_in; (void)out_size;
    const float* x    = (const float*)d_in[0];
    const float* Wq   = (const float*)d_in[2];
    const float* Wk   = (const float*)d_in[3];
    const float* Wv   = (const float*)d_in[4];
    const float* Wo   = (const float*)d_in[5];
    const float* ln1g = (const float*)d_in[6];
    const float* ln1b = (const float*)d_in[7];
    const float* W1   = (const float*)d_in[8];
    const float* b1   = (const float*)d_in[9];
    const float* W2   = (const float*)d_in[10];
    const float* b2   = (const float*)d_in[11];
    const float* ln2g = (const float*)d_in[12];
    const float* ln2b = (const float*)d_in[13];
    float* out = (float*)d_out;

    int8_t *hq1, *hq2, *atq1, *atq2, *ffq1, *ffq2;
    float *hs, *ats, *ffs;
    float *q, *k, *v, *attn, *x2, *ff;
    int8_t *qq1, *qq2, *kq1, *kq2;
    float *qsc, *ksc;
    bf16 *vt;
    int8_t *wqq1, *wqq2, *wkq1, *wkq2, *wvq1, *wvq2, *woq1, *woq2, *w1q1, *w1q2, *w2q1, *w2q2;
    float *wqam, *wqs, *wkam, *wks, *wvam, *wvs, *woam, *wos, *w1am, *w1s, *w2am, *w2s;
    cudaGetSymbolAddress((void**)&hq1,  g_h_q1);
    cudaGetSymbolAddress((void**)&hq2,  g_h_q2);
    cudaGetSymbolAddress((void**)&hs,   g_h_s);
    cudaGetSymbolAddress((void**)&q,    g_q);
    cudaGetSymbolAddress((void**)&k,    g_k);
    cudaGetSymbolAddress((void**)&v,    g_v);
    cudaGetSymbolAddress((void**)&attn, g_attn);
    cudaGetSymbolAddress((void**)&atq1, g_at_q1);
    cudaGetSymbolAddress((void**)&atq2, g_at_q2);
    cudaGetSymbolAddress((void**)&ats,  g_at_s);
    cudaGetSymbolAddress((void**)&x2,   g_x2);
    cudaGetSymbolAddress((void**)&ff,   g_ff);
    cudaGetSymbolAddress((void**)&ffq1, g_ff_q1);
    cudaGetSymbolAddress((void**)&ffq2, g_ff_q2);
    cudaGetSymbolAddress((void**)&ffs,  g_ff_s);
    cudaGetSymbolAddress((void**)&qq1,  g_q_q1);
    cudaGetSymbolAddress((void**)&qq2,  g_q_q2);
    cudaGetSymbolAddress((void**)&qsc,  g_q_sc);
    cudaGetSymbolAddress((void**)&kq1,  g_k_q1);
    cudaGetSymbolAddress((void**)&kq2,  g_k_q2);
    cudaGetSymbolAddress((void**)&ksc,  g_k_sc);
    cudaGetSymbolAddress((void**)&vt,   g_vt);
    cudaGetSymbolAddress((void**)&wqq1, g_wq_q1);
    cudaGetSymbolAddress((void**)&wqq2, g_wq_q2);
    cudaGetSymbolAddress((void**)&wqam, g_wq_am);
    cudaGetSymbolAddress((void**)&wqs,  g_wq_s);
    cudaGetSymbolAddress((void**)&wkq1, g_wk_q1);
    cudaGetSymbolAddress((void**)&wkq2, g_wk_q2);
    cudaGetSymbolAddress((void**)&wkam, g_wk_am);
    cudaGetSymbolAddress((void**)&wks,  g_wk_s);
    cudaGetSymbolAddress((void**)&wvq1, g_wv_q1);
    cudaGetSymbolAddress((void**)&wvq2, g_wv_q2);
    cudaGetSymbolAddress((void**)&wvam, g_wv_am);
    cudaGetSymbolAddress((void**)&wvs,  g_wv_s);
    cudaGetSymbolAddress((void**)&woq1, g_wo_q1);
    cudaGetSymbolAddress((void**)&woq2, g_wo_q2);
    cudaGetSymbolAddress((void**)&woam, g_wo_am);
    cudaGetSymbolAddress((void**)&wos,  g_wo_s);
    cudaGetSymbolAddress((void**)&w1q1, g_w1_q1);
    cudaGetSymbolAddress((void**)&w1q2, g_w1_q2);
    cudaGetSymbolAddress((void**)&w1am, g_w1_am);
    cudaGetSymbolAddress((void**)&w1s,  g_w1_s);
    cudaGetSymbolAddress((void**)&w2q1, g_w2_q1);
    cudaGetSymbolAddress((void**)&w2q2, g_w2_q2);
    cudaGetSymbolAddress((void**)&w2am, g_w2_am);
    cudaGetSymbolAddress((void**)&w2s,  g_w2_s);

    cudaFuncSetAttribute(attn_i8,
                         cudaFuncAttributeMaxDynamicSharedMemorySize, ATT_SMEM);
    cudaFuncSetAttribute(gemm_i8<false, false, false>,
                         cudaFuncAttributeMaxDynamicSharedMemorySize, I8_SMEM);
    cudaFuncSetAttribute(gemm_i8<false, false, true>,
                         cudaFuncAttributeMaxDynamicSharedMemorySize, I8_SMEM);
    cudaFuncSetAttribute(gemm_i8<true, true, false>,
                         cudaFuncAttributeMaxDynamicSharedMemorySize, I8_SMEM);
    cudaFuncSetAttribute(gemm_i8<false, true, true>,
                         cudaFuncAttributeMaxDynamicSharedMemorySize, I8_SMEM);

    const dim3 blk(256);

    // ---- weight prep ----
    cudaMemsetAsync(wqam, 0, D_DIM * sizeof(float));
    cudaMemsetAsync(wkam, 0, D_DIM * sizeof(float));
    cudaMemsetAsync(wvam, 0, D_DIM * sizeof(float));
    cudaMemsetAsync(woam, 0, D_DIM * sizeof(float));
    cudaMemsetAsync(w1am, 0, M_FF * sizeof(float));
    cudaMemsetAsync(w2am, 0, D_DIM * sizeof(float));
    colamax_kernel<<<dim3(64, 64),  blk>>>(Wq, D_DIM, D_DIM, wqam);
    colamax_kernel<<<dim3(64, 64),  blk>>>(Wk, D_DIM, D_DIM, wkam);
    colamax_kernel<<<dim3(64, 64),  blk>>>(Wv, D_DIM, D_DIM, wvam);
    colamax_kernel<<<dim3(64, 64),  blk>>>(Wo, D_DIM, D_DIM, woam);
    colamax_kernel<<<dim3(M_FF / 32,  D_DIM / 32), blk>>>(W1, D_DIM, M_FF, w1am);
    colamax_kernel<<<dim3(D_DIM / 32, M_FF / 32),  blk>>>(W2, M_FF, D_DIM, w2am);
    transpose_quant_i8<<<dim3(64, 64),  blk>>>(Wq, wqam, wqq1, wqq2, wqs, D_DIM, D_DIM);
    transpose_quant_i8<<<dim3(64, 64),  blk>>>(Wk, wkam, wkq1, wkq2, wks, D_DIM, D_DIM);
    transpose_quant_i8<<<dim3(64, 64),  blk>>>(Wv, wvam, wvq1, wvq2, wvs, D_DIM, D_DIM);
    transpose_quant_i8<<<dim3(64, 64),  blk>>>(Wo, woam, woq1, woq2, wos, D_DIM, D_DIM);
    transpose_quant_i8<<<dim3(256, 64), blk>>>(W1, w1am, w1q1, w1q2, w1s, D_DIM, M_FF);
    transpose_quant_i8<<<dim3(64, 256), blk>>>(W2, w2am, w2q1, w2q2, w2s, M_FF, D_DIM);

    const dim3 gDD(D_DIM / 128, ROWS / 128);   // (16, 32)
    const dim3 gDM(M_FF / 128,  ROWS / 128);   // (64, 32)

    // ---- layer ----
    ln_quant_i8<<<ROWS, blk>>>(x, ln1g, ln1b, hq1, hq2, hs);
    gemm_i8<false, false, false><<<gDD, blk, I8_SMEM>>>(
        hq1, hq2, wqq1, wqq2, hs, wqs, nullptr, nullptr, q, D_DIM, D_DIM);
    gemm_i8<false, false, false><<<gDD, blk, I8_SMEM>>>(
        hq1, hq2, wkq1, wkq2, hs, wks, nullptr, nullptr, k, D_DIM, D_DIM);
    gemm_i8<false, false, false><<<gDD, blk, I8_SMEM>>>(
        hq1, hq2, wvq1, wvq2, hs, wvs, nullptr, nullptr, v, D_DIM, D_DIM);
    // attention operand prep (flat; scales land at [bh*S + j] by construction)
    quant_head_i8<<<ROWS, blk>>>(q, qq1, qq2, qsc);
    quant_head_i8<<<ROWS, blk>>>(k, kq1, kq2, ksc);
    vt_split<<<dim3(S_LEN / 32, HD / 32, B_SZ * NH), blk>>>(v, vt);
    // tensor-core attention (quirk addressing)
    attn_i8<<<dim3(S_LEN / 128, NH, B_SZ), blk, ATT_SMEM>>>(
        qq1, qq2, qsc, kq1, kq2, ksc, vt, attn);
    rowquant_i8<<<ROWS, blk>>>(attn, D_DIM, atq1, atq2, ats);
    gemm_i8<false, false, true><<<gDD, blk, I8_SMEM>>>(
        atq1, atq2, woq1, woq2, ats, wos, nullptr, x, x2, D_DIM, D_DIM);
    ln_quant_i8<<<ROWS, blk>>>(x2, ln2g, ln2b, hq1, hq2, hs);
    gemm_i8<true, true, false><<<gDM, blk, I8_SMEM>>>(
        hq1, hq2, w1q1, w1q2, hs, w1s, b1, nullptr, ff, M_FF, D_DIM);
    rowquant_i8<<<ROWS, blk>>>(ff, M_FF, ffq1, ffq2, ffs);
    gemm_i8<false, true, true><<<gDD, blk, I8_SMEM>>>(
        ffq1, ffq2, w2q1, w2q2, ffs, w2s, b2, x2, out, D_DIM, M_FF);
}

// round 11
// speedup vs baseline: 4.0109x; 1.0588x over previous
#include <cuda_runtime.h>
#include <cuda_bf16.h>
#include <cstdint>
#include <math.h>

// Problem constants
#define S_LEN 2048
#define D_DIM 2048
#define B_SZ  2
#define NH    16
#define HD    128
#define M_FF  8192
#define ROWS  (B_SZ * S_LEN)   // 4096

typedef __nv_bfloat16 bf16;

// -------------------- scratch (device globals; no allocation allowed) -----
__device__ __align__(16) int8_t g_h_q1  [ROWS * D_DIM];
__device__ __align__(16) int8_t g_h_q2  [ROWS * D_DIM];
__device__            float  g_h_s   [ROWS];
__device__ __align__(16) float g_q     [ROWS * D_DIM];
__device__ __align__(16) float g_k     [ROWS * D_DIM];
__device__ __align__(16) float g_v     [ROWS * D_DIM];
__device__ __align__(16) float g_attn  [ROWS * D_DIM];
__device__ __align__(16) int8_t g_at_q1 [ROWS * D_DIM];
__device__ __align__(16) int8_t g_at_q2 [ROWS * D_DIM];
__device__            float  g_at_s  [ROWS];
__device__ __align__(16) float g_x2    [ROWS * D_DIM];
__device__ __align__(16) float g_ff    [ROWS * M_FF];
__device__ __align__(16) int8_t g_ff_q1 [ROWS * M_FF];
__device__ __align__(16) int8_t g_ff_q2 [ROWS * M_FF];
__device__            float  g_ff_s  [ROWS];
// attention int8/bf16 operands (flat quirk layout; scales at [bh*S+j])
__device__ __align__(16) int8_t g_q_q1  [ROWS * D_DIM];
__device__ __align__(16) int8_t g_q_q2  [ROWS * D_DIM];
__device__            float  g_q_sc  [ROWS * NH];
__device__ __align__(16) int8_t g_k_q1  [ROWS * D_DIM];
__device__ __align__(16) int8_t g_k_q2  [ROWS * D_DIM];
__device__            float  g_k_sc  [ROWS * NH];
__device__ __align__(16) bf16  g_vt    [B_SZ * NH * HD * S_LEN];   // [bh][c][j]
// int8 2-limb weights ([N][K])
__device__ __align__(16) int8_t g_wq_q1 [D_DIM * D_DIM];
__device__ __align__(16) int8_t g_wq_q2 [D_DIM * D_DIM];
__device__            float  g_wq_am [D_DIM];
__device__            float  g_wq_s  [D_DIM];
__device__ __align__(16) int8_t g_wk_q1 [D_DIM * D_DIM];
__device__ __align__(16) int8_t g_wk_q2 [D_DIM * D_DIM];
__device__            float  g_wk_am [D_DIM];
__device__            float  g_wk_s  [D_DIM];
__device__ __align__(16) int8_t g_wv_q1 [D_DIM * D_DIM];
__device__ __align__(16) int8_t g_wv_q2 [D_DIM * D_DIM];
__device__            float  g_wv_am [D_DIM];
__device__            float  g_wv_s  [D_DIM];
__device__ __align__(16) int8_t g_wo_q1 [D_DIM * D_DIM];
__device__ __align__(16) int8_t g_wo_q2 [D_DIM * D_DIM];
__device__            float  g_wo_am [D_DIM];
__device__            float  g_wo_s  [D_DIM];
__device__ __align__(16) int8_t g_w1_q1 [M_FF * D_DIM];
__device__ __align__(16) int8_t g_w1_q2 [M_FF * D_DIM];
__device__            float  g_w1_am [M_FF];
__device__            float  g_w1_s  [M_FF];
__device__ __align__(16) int8_t g_w2_q1 [D_DIM * M_FF];
__device__ __align__(16) int8_t g_w2_q2 [D_DIM * M_FF];
__device__            float  g_w2_am [D_DIM];
__device__            float  g_w2_s  [D_DIM];

// ===========================================================================
// helpers
// ===========================================================================
__device__ __forceinline__ uint32_t smem_u32(const void* p) {
    uint32_t a;
    asm("{ .reg .u64 t; cvta.to.shared.u64 t, %1; cvt.u32.u64 %0, t; }" : "=r"(a) : "l"(p));
    return a;
}
__device__ __forceinline__ void cpa16(uint32_t dst, const void* src) {
    asm volatile("cp.async.cg.shared.global [%0], [%1], 16;" :: "r"(dst), "l"(src));
}
#define CP_COMMIT() asm volatile("cp.async.commit_group;" ::: "memory")
#define CP_WAIT1()  asm volatile("cp.async.wait_group 1;" ::: "memory")

__device__ __forceinline__ void ldmx4(uint32_t* r, uint32_t addr) {
    asm volatile("ldmatrix.sync.aligned.m8n8.x4.shared.b16 {%0,%1,%2,%3}, [%4];"
        : "=r"(r[0]), "=r"(r[1]), "=r"(r[2]), "=r"(r[3]) : "r"(addr));
}
__device__ __forceinline__ void mma_bf16(float* d, const uint32_t* a, uint32_t b0, uint32_t b1) {
    asm volatile(
        "mma.sync.aligned.m16n8k16.row.col.f32.bf16.bf16.f32 "
        "{%0,%1,%2,%3},{%4,%5,%6,%7},{%8,%9},{%0,%1,%2,%3};"
        : "+f"(d[0]), "+f"(d[1]), "+f"(d[2]), "+f"(d[3])
        : "r"(a[0]), "r"(a[1]), "r"(a[2]), "r"(a[3]), "r"(b0), "r"(b1));
}
__device__ __forceinline__ void mma_s8(int* d, const uint32_t* a, uint32_t b0, uint32_t b1) {
    asm volatile(
        "mma.sync.aligned.m16n8k32.row.col.s32.s8.s8.s32 "
        "{%0,%1,%2,%3},{%4,%5,%6,%7},{%8,%9},{%0,%1,%2,%3};"
        : "+r"(d[0]), "+r"(d[1]), "+r"(d[2]), "+r"(d[3])
        : "r"(a[0]), "r"(a[1]), "r"(a[2]), "r"(a[3]), "r"(b0), "r"(b1));
}
__device__ __forceinline__ void quant2(float v, float inv_s, int8_t& h, int8_t& l) {
    float q  = v * inv_s;
    float q1 = rintf(q);
    float q2 = rintf((q - q1) * 256.0f);
    q2 = fminf(fmaxf(q2, -127.0f), 127.0f);
    h = (int8_t)(int)q1;
    l = (int8_t)(int)q2;
}

// ===========================================================================
// per-column absmax
// ===========================================================================
__global__ __launch_bounds__(256)
void colamax_kernel(const float* __restrict__ in, int R, int C, float* __restrict__ amax)
{
    __shared__ float sm_[8][33];
    const int tx = threadIdx.x & 31;
    const int ty = threadIdx.x >> 5;
    const int bx = blockIdx.x * 32, by = blockIdx.y * 32;
    float m = 0.f;
#pragma unroll
    for (int j = 0; j < 4; ++j)
        m = fmaxf(m, fabsf(in[(size_t)(by + ty + 8 * j) * C + bx + tx]));
    sm_[ty][tx] = m;
    __syncthreads();
    if (ty == 0) {
        float mm = sm_[0][tx];
#pragma unroll
        for (int r = 1; r < 8; ++r) mm = fmaxf(mm, sm_[r][tx]);
        atomicMax((unsigned int*)&amax[bx + tx], __float_as_uint(mm));
    }
}

// ===========================================================================
// transpose + int8 2-limb quant (weights)
// ===========================================================================
__global__ __launch_bounds__(256)
void transpose_quant_i8(const float* __restrict__ in, const float* __restrict__ amax,
                        int8_t* __restrict__ q1o, int8_t* __restrict__ q2o,
                        float* __restrict__ sOut, int R, int C)
{
    __shared__ float tile[32][33];
    const int tx = threadIdx.x & 31;
    const int ty = threadIdx.x >> 5;
    const int bx = blockIdx.x * 32, by = blockIdx.y * 32;
#pragma unroll
    for (int j = 0; j < 32; j += 8)
        tile[ty + j][tx] = in[(size_t)(by + ty + j) * C + bx + tx];
    __syncthreads();
#pragma unroll
    for (int j = 0; j < 32; j += 8) {
        const int orow = bx + ty + j;
        float am = fmaxf(amax[orow], 1e-20f);
        float s  = am * (1.0f / 127.0f);
        float inv = 127.0f / am;
        if (tx == 0) sOut[orow] = s;
        float v = tile[tx][ty + j];
        int8_t h, l; quant2(v, inv, h, l);
        size_t o = (size_t)orow * R + by + tx;
        q1o[o] = h; q2o[o] = l;
    }
}

// ===========================================================================
// per-row int8 2-limb quant
// ===========================================================================
__global__ __launch_bounds__(256)
void rowquant_i8(const float* __restrict__ in, int Kd,
                 int8_t* __restrict__ q1, int8_t* __restrict__ q2, float* __restrict__ s)
{
    __shared__ float red[9];
    const int row = blockIdx.x;
    const int tid = threadIdx.x;
    const float* r = in + (size_t)row * Kd;
    float m = 0.f;
    for (int c = tid; c < Kd; c += 256) m = fmaxf(m, fabsf(r[c]));
#pragma unroll
    for (int d = 16; d > 0; d >>= 1) m = fmaxf(m, __shfl_xor_sync(0xffffffffu, m, d));
    if ((tid & 31) == 0) red[tid >> 5] = m;
    __syncthreads();
    if (tid == 0) {
        float mm = red[0];
#pragma unroll
        for (int i = 1; i < 8; ++i) mm = fmaxf(mm, red[i]);
        mm = fmaxf(mm, 1e-20f);
        red[8] = mm;
        s[row] = mm * (1.0f / 127.0f);
    }
    __syncthreads();
    const float inv = 127.0f / red[8];
    for (int c = tid; c < Kd; c += 256) {
        int8_t h, l; quant2(r[c], inv, h, l);
        q1[(size_t)row * Kd + c] = h;
        q2[(size_t)row * Kd + c] = l;
    }
}

// ===========================================================================
// per-128-segment int8 2-limb quant (Q/K). One flat row per block.
// ===========================================================================
__global__ __launch_bounds__(256)
void quant_head_i8(const float* __restrict__ in, int8_t* __restrict__ q1,
                   int8_t* __restrict__ q2, float* __restrict__ sArr)
{
    const int row = blockIdx.x;
    const int t = threadIdx.x;
    const int c0 = t * 8;
    const int seg = t >> 4;
    float v[8];
    *(float4*)&v[0] = *(const float4*)(in + (size_t)row * D_DIM + c0);
    *(float4*)&v[4] = *(const float4*)(in + (size_t)row * D_DIM + c0 + 4);
    float am = 0.f;
#pragma unroll
    for (int i = 0; i < 8; ++i) am = fmaxf(am, fabsf(v[i]));
#pragma unroll
    for (int d = 1; d < 16; d <<= 1)
        am = fmaxf(am, __shfl_xor_sync(0xffffffffu, am, d));
    am = fmaxf(am, 1e-20f);
    if ((t & 15) == 0) sArr[row * NH + seg] = am * (1.0f / 127.0f);
    const float inv = 127.0f / am;
    int8_t h[8], l[8];
#pragma unroll
    for (int i = 0; i < 8; ++i) quant2(v[i], inv, h[i], l[i]);
    *(uint2*)(q1 + (size_t)row * D_DIM + c0) = *(uint2*)h;
    *(uint2*)(q2 + (size_t)row * D_DIM + c0) = *(uint2*)l;
}

// ===========================================================================
// V^T split (QUIRK layout): vt[bh][c][j] = bf16(v_flat[bh*262144 + j*128 + c])
// ===========================================================================
__global__ __launch_bounds__(256)
void vt_split(const float* __restrict__ v, bf16* __restrict__ vt)
{
    __shared__ float tile[32][33];
    const int tx = threadIdx.x & 31;
    const int ty = threadIdx.x >> 5;
    const int bh = blockIdx.z;
    const int j0 = blockIdx.x * 32, c0 = blockIdx.y * 32;
    const float* vb = v + (size_t)bh * S_LEN * HD;
#pragma unroll
    for (int jj = 0; jj < 32; jj += 8)
        tile[ty + jj][tx] = vb[(size_t)(j0 + ty + jj) * HD + c0 + tx];
    __syncthreads();
#pragma unroll
    for (int jj = 0; jj < 32; jj += 8)
        vt[((size_t)bh * HD + c0 + ty + jj) * S_LEN + j0 + tx] =
            __float2bfloat16_rn(tile[tx][ty + jj]);
}

// ===========================================================================
// LayerNorm + int8 2-limb quant
// ===========================================================================
__global__ __launch_bounds__(256)
void ln_quant_i8(const float* __restrict__ x, const float* __restrict__ gam,
                 const float* __restrict__ bet, int8_t* __restrict__ q1,
                 int8_t* __restrict__ q2, float* __restrict__ sArr)
{
    __shared__ float red[9];
    const int row = blockIdx.x;
    const int tid = threadIdx.x;
    const float* xr = x + (size_t)row * D_DIM;

    float v[8];
    float sum = 0.f;
#pragma unroll
    for (int i = 0; i < 8; ++i) { v[i] = xr[tid + 256 * i]; sum += v[i]; }
#pragma unroll
    for (int d = 16; d > 0; d >>= 1) sum += __shfl_xor_sync(0xffffffffu, sum, d);
    if ((tid & 31) == 0) red[tid >> 5] = sum;
    __syncthreads();
    float tot = 0.f;
#pragma unroll
    for (int i = 0; i < 8; ++i) tot += red[i];
    const float mean = tot * (1.0f / (float)D_DIM);

    float s2 = 0.f;
#pragma unroll
    for (int i = 0; i < 8; ++i) { float d = v[i] - mean; s2 += d * d; }
    __syncthreads();
#pragma unroll
    for (int d = 16; d > 0; d >>= 1) s2 += __shfl_xor_sync(0xffffffffu, s2, d);
    if ((tid & 31) == 0) red[tid >> 5] = s2;
    __syncthreads();
    tot = 0.f;
#pragma unroll
    for (int i = 0; i < 8; ++i) tot += red[i];
    const float rstd = rsqrtf(tot * (1.0f / (float)D_DIM) + 1e-5f);

    float o[8];
    float am = 0.f;
#pragma unroll
    for (int i = 0; i < 8; ++i) {
        int c = tid + 256 * i;
        o[i] = (v[i] - mean) * rstd * gam[c] + bet[c];
        am = fmaxf(am, fabsf(o[i]));
    }
    __syncthreads();
#pragma unroll
    for (int d = 16; d > 0; d >>= 1) am = fmaxf(am, __shfl_xor_sync(0xffffffffu, am, d));
    if ((tid & 31) == 0) red[tid >> 5] = am;
    __syncthreads();
    if (tid == 0) {
        float mm = red[0];
#pragma unroll
        for (int i = 1; i < 8; ++i) mm = fmaxf(mm, red[i]);
        mm = fmaxf(mm, 1e-20f);
        red[8] = mm;
        sArr[row] = mm * (1.0f / 127.0f);
    }
    __syncthreads();
    const float inv = 127.0f / red[8];
#pragma unroll
    for (int i = 0; i < 8; ++i) {
        int c = tid + 256 * i;
        int8_t h, l; quant2(o[i], inv, h, l);
        q1[(size_t)row * D_DIM + c] = h;
        q2[(size_t)row * D_DIM + c] = l;
    }
}

// ===========================================================================
// int8 2-limb tensor-core GEMM — 512 threads / 16 warps (4 warps/SMSP),
// warp tile 32x32, acc = 64 regs/thread -> fits 128-reg cap at occ "full".
// CTA tile 128x128, BK=64 int8, 3-stage cp.async (96KB).
// ===========================================================================
#define ISTAGE 32768
#define ISM_A2 8192
#define ISM_B1 16384
#define ISM_B2 24576
#define I8_SMEM (3 * ISTAGE)

template<bool RELU, bool HAS_BIAS, bool HAS_RES>
__global__ __launch_bounds__(512, 1)
void gemm_i8(const int8_t* __restrict__ A1, const int8_t* __restrict__ A2,
             const int8_t* __restrict__ B1, const int8_t* __restrict__ B2,
             const float* __restrict__ sA, const float* __restrict__ sB,
             const float* __restrict__ bias, const float* __restrict__ res,
             float* __restrict__ Cf, int Nd, int Kd)
{
    extern __shared__ char smem[];
    const uint32_t sb = smem_u32(smem);
    const int tid  = threadIdx.x;
    const int warp = tid >> 5;       // 0..15
    const int lane = tid & 31;
    const int wm   = warp & 3;       // 0..3 rows (32 each)
    const int wn   = warp >> 2;      // 0..3 cols (32 each)
    const int bx = blockIdx.x, by = blockIdx.y;
    const int ktiles = Kd >> 6;

    // producer: 512 threads x 1 chunk of 16B per buffer
    const int r0 = tid >> 2;         // 0..127
    const int cc = tid & 3;
    const int pc = (cc + (r0 >> 1)) & 3;
    const size_t gA0 = (size_t)(by * 128 + r0) * Kd + cc * 16;
    const size_t gB0 = (size_t)(bx * 128 + r0) * Kd + cc * 16;
    const int8_t* pA1 = A1 + gA0;  const int8_t* pA2 = A2 + gA0;
    const int8_t* pB1 = B1 + gB0;  const int8_t* pB2 = B2 + gB0;
    const uint32_t dA0 = (uint32_t)(r0 * 64 + pc * 16);

#define ISSUE_I8(slot, u) do { \
    uint32_t s0_ = sb + (slot) * ISTAGE; int ko_ = (u) * 64; \
    cpa16(s0_ + dA0,          pA1 + ko_); \
    cpa16(s0_ + dA0 + ISM_A2, pA2 + ko_); \
    cpa16(s0_ + dA0 + ISM_B1, pB1 + ko_); \
    cpa16(s0_ + dA0 + ISM_B2, pB2 + ko_); \
} while (0)

    const int l15   = lane & 15;
    const int chalf = lane >> 4;
    const uint32_t pc0 = (uint32_t)((chalf + (l15 >> 1)) & 3);
    const uint32_t pc1 = (uint32_t)((2 + chalf + (l15 >> 1)) & 3);
    const uint32_t offA[2] = { (uint32_t)((wm * 32 + l15) * 64) + pc0 * 16,
                               (uint32_t)((wm * 32 + l15) * 64) + pc1 * 16 };
    const uint32_t offB0[2] = { (uint32_t)((wn * 32 + l15) * 64) + pc0 * 16,
                                (uint32_t)((wn * 32 + l15) * 64) + pc1 * 16 };
    const uint32_t offB1[2] = { (uint32_t)((wn * 32 + 16 + l15) * 64) + pc0 * 16,
                                (uint32_t)((wn * 32 + 16 + l15) * 64) + pc1 * 16 };

    int accH[2][4][4], accM[2][4][4];
#pragma unroll
    for (int mt = 0; mt < 2; ++mt)
#pragma unroll
        for (int nt = 0; nt < 4; ++nt)
#pragma unroll
            for (int e = 0; e < 4; ++e) { accH[mt][nt][e] = 0; accM[mt][nt][e] = 0; }

    ISSUE_I8(0, 0); CP_COMMIT();
    ISSUE_I8(1, 1); CP_COMMIT();

    for (int t = 0; t < ktiles; ++t) {
        CP_WAIT1();
        __syncthreads();
        {
            const int u = t + 2;
            if (u < ktiles) { ISSUE_I8(u % 3, u); }
            CP_COMMIT();
        }
        const uint32_t st = sb + (t % 3) * ISTAGE;
#pragma unroll
        for (int j = 0; j < 2; ++j) {
            uint32_t b1F[8], b2F[8];
            ldmx4(&b1F[0], st + ISM_B1 + offB0[j]);
            ldmx4(&b1F[4], st + ISM_B1 + offB1[j]);
            ldmx4(&b2F[0], st + ISM_B2 + offB0[j]);
            ldmx4(&b2F[4], st + ISM_B2 + offB1[j]);
#pragma unroll
            for (int mt = 0; mt < 2; ++mt) {
                uint32_t a1F[4], a2F[4];
                ldmx4(a1F, st + mt * 1024 + offA[j]);
                ldmx4(a2F, st + ISM_A2 + mt * 1024 + offA[j]);
#pragma unroll
                for (int nt = 0; nt < 4; ++nt) {
                    const int p = (nt >> 1) * 4 + (nt & 1);
                    const uint32_t b0h = b1F[p], b1h = b1F[p + 2];
                    const uint32_t b0l = b2F[p], b1l = b2F[p + 2];
                    mma_s8(accH[mt][nt], a1F, b0h, b1h);
                    mma_s8(accM[mt][nt], a2F, b0h, b1h);
                    mma_s8(accM[mt][nt], a1F, b0l, b1l);
                }
            }
        }
    }

    const int g  = lane >> 2;
    const int tg = lane & 3;
#pragma unroll
    for (int mt = 0; mt < 2; ++mt) {
        const int row = by * 128 + wm * 32 + mt * 16 + g;
        const float sa0 = sA[row], sa8 = sA[row + 8];
#pragma unroll
        for (int nt = 0; nt < 4; ++nt) {
            const int col = bx * 128 + wn * 32 + nt * 8 + 2 * tg;
            const float sb0 = sB[col], sb1 = sB[col + 1];
            float v0 = sa0 * sb0 * ((float)accH[mt][nt][0] + (float)accM[mt][nt][0] * 0.00390625f);
            float v1 = sa0 * sb1 * ((float)accH[mt][nt][1] + (float)accM[mt][nt][1] * 0.00390625f);
            float v2 = sa8 * sb0 * ((float)accH[mt][nt][2] + (float)accM[mt][nt][2] * 0.00390625f);
            float v3 = sa8 * sb1 * ((float)accH[mt][nt][3] + (float)accM[mt][nt][3] * 0.00390625f);
            if (HAS_BIAS) {
                float2 b2v = *(const float2*)(bias + col);
                v0 += b2v.x; v1 += b2v.y; v2 += b2v.x; v3 += b2v.y;
            }
            if (RELU) {
                v0 = fmaxf(v0, 0.f); v1 = fmaxf(v1, 0.f);
                v2 = fmaxf(v2, 0.f); v3 = fmaxf(v3, 0.f);
            }
            if (HAS_RES) {
                float2 ra = *(const float2*)(res + (size_t)row * Nd + col);
                float2 rb = *(const float2*)(res + (size_t)(row + 8) * Nd + col);
                v0 += ra.x; v1 += ra.y; v2 += rb.x; v3 += rb.y;
            }
            *(float2*)(Cf + (size_t)row * Nd + col)       = make_float2(v0, v1);
            *(float2*)(Cf + (size_t)(row + 8) * Nd + col) = make_float2(v2, v3);
        }
    }
#undef ISSUE_I8
}

// ===========================================================================
// Tensor-core flash attention (QUIRK layout) — unchanged from round 10
// ===========================================================================
#define AQ_H  0
#define AQ_L  18432
#define AK_H(bf) (36864 + (bf) * 18432)
#define AK_L(bf) (AK_H(bf) + 9216)
#define AVT(bf)  (73728 + (bf) * 18432)
#define APS_H 110592
#define APS_L 129024
#define ASQ   147456
#define ASK(bf) (147968 + (bf) * 256)
#define ATT_SMEM 148480

__global__ __launch_bounds__(256)
void attn_i8(const int8_t* __restrict__ Qq1, const int8_t* __restrict__ Qq2,
             const float* __restrict__ Qs,
             const int8_t* __restrict__ Kq1, const int8_t* __restrict__ Kq2,
             const float* __restrict__ Ks,
             const bf16* __restrict__ VT, float* __restrict__ O)
{
    extern __shared__ char smem[];
    const uint32_t sb = smem_u32(smem);
    float* sQf = (float*)(smem + ASQ);
    const int qt   = blockIdx.x;
    const int head = blockIdx.y;
    const int b    = blockIdx.z;
    const int tid  = threadIdx.x;
    const int warp = tid >> 5;
    const int lane = tid & 31;
    const int l15  = lane & 15;
    const int lhalf = lane >> 4;
    const int g  = lane >> 2;
    const int tg = lane & 3;
    const int mrow = warp * 16;
    const int ntiles = 2 * qt + 2;
    const int bh = b * NH + head;
    const size_t hbase = (size_t)bh * S_LEN * HD;
    const int i0 = qt * 128;
    const bf16* vth = VT + (size_t)bh * HD * S_LEN;

    if (tid < 128) sQf[tid] = Qs[(size_t)bh * S_LEN + i0 + tid];

#pragma unroll
    for (int i = 0; i < 4; ++i) {
        int id = tid + 256 * i;
        int r = id >> 3, c = (id & 7) * 16;
        cpa16(sb + AQ_H + r * 144 + c, Qq1 + hbase + (size_t)(i0 + r) * HD + c);
        cpa16(sb + AQ_L + r * 144 + c, Qq2 + hbase + (size_t)(i0 + r) * HD + c);
    }

#define ATT_ISSUE(bf_, jt_) do { \
    const size_t kj0_ = (size_t)(jt_) * 64; \
    for (int i_ = tid; i_ < 512; i_ += 256) { \
        int r_ = i_ >> 3, c_ = (i_ & 7) * 16; \
        cpa16(sb + AK_H(bf_) + r_ * 144 + c_, Kq1 + hbase + (kj0_ + r_) * HD + c_); \
        cpa16(sb + AK_L(bf_) + r_ * 144 + c_, Kq2 + hbase + (kj0_ + r_) * HD + c_); \
    } \
    for (int i_ = tid; i_ < 1024; i_ += 256) { \
        int r_ = i_ >> 3, c_ = (i_ & 7) * 16; \
        cpa16(sb + AVT(bf_) + r_ * 144 + c_, \
              (const char*)(vth + (size_t)r_ * S_LEN + kj0_) + c_); \
    } \
    if (tid < 64) ((float*)(smem + ASK(bf_)))[tid] = Ks[(size_t)bh * S_LEN + kj0_ + tid]; \
} while (0)

    ATT_ISSUE(0, 0); CP_COMMIT();
    ATT_ISSUE(1, 1); CP_COMMIT();

    float o_acc[16][4];
#pragma unroll
    for (int ot = 0; ot < 16; ++ot)
#pragma unroll
        for (int e = 0; e < 4; ++e) o_acc[ot][e] = 0.f;
    float m0 = -1e30f, m1 = -1e30f, l0 = 0.f, l1 = 0.f;
    const float inv_sqrt_d = 0.08838834764831845f;
    const float inv256 = 0.00390625f;
    const int i_g0 = i0 + mrow + g;
    const int i_g1 = i_g0 + 8;

    const uint32_t qbH = sb + AQ_H + (mrow + l15) * 144 + lhalf * 16;
    const uint32_t qbL = sb + AQ_L + (mrow + l15) * 144 + lhalf * 16;
    const uint32_t pbH = sb + APS_H + (mrow + l15) * 144 + lhalf * 16;
    const uint32_t pbL = sb + APS_L + (mrow + l15) * 144 + lhalf * 16;

    for (int jt = 0; jt < ntiles; ++jt) {
        const int buf = jt & 1;
        CP_WAIT1();
        __syncthreads();
        const float* sKf = (const float*)(smem + ASK(buf));

        int accH[8][4], accM[8][4];
#pragma unroll
        for (int nt = 0; nt < 8; ++nt)
#pragma unroll
            for (int e = 0; e < 4; ++e) { accH[nt][e] = 0; accM[nt][e] = 0; }

#pragma unroll
        for (int ks = 0; ks < 4; ++ks) {
            uint32_t aH[4], aL[4];
            ldmx4(aH, qbH + ks * 32);
            ldmx4(aL, qbL + ks * 32);
#pragma unroll
            for (int ng = 0; ng < 4; ++ng) {
                uint32_t bH4[4], bL4[4];
                const uint32_t kaddr = (uint32_t)((ng * 16 + l15) * 144) + lhalf * 16 + ks * 32;
                ldmx4(bH4, sb + AK_H(buf) + kaddr);
                ldmx4(bL4, sb + AK_L(buf) + kaddr);
                mma_s8(accH[2 * ng],     aH, bH4[0], bH4[2]);
                mma_s8(accM[2 * ng],     aL, bH4[0], bH4[2]);
                mma_s8(accM[2 * ng],     aH, bL4[0], bL4[2]);
                mma_s8(accH[2 * ng + 1], aH, bH4[1], bH4[3]);
                mma_s8(accM[2 * ng + 1], aL, bH4[1], bH4[3]);
                mma_s8(accM[2 * ng + 1], aH, bL4[1], bL4[3]);
            }
        }

        const float sq0 = sQf[mrow + g], sq1 = sQf[mrow + g + 8];
        const bool diag = (jt >= 2 * qt);
        float sv[8][4];
        float rm0 = -1e30f, rm1 = -1e30f;
#pragma unroll
        for (int nt = 0; nt < 8; ++nt) {
            const int col0 = nt * 8 + 2 * tg;
            const float sk0 = sKf[col0], sk1 = sKf[col0 + 1];
            float s00 = sq0 * sk0 * ((float)accH[nt][0] + (float)accM[nt][0] * inv256);
            float s01 = sq0 * sk1 * ((float)accH[nt][1] + (float)accM[nt][1] * inv256);
            float s10 = sq1 * sk0 * ((float)accH[nt][2] + (float)accM[nt][2] * inv256);
            float s11 = sq1 * sk1 * ((float)accH[nt][3] + (float)accM[nt][3] * inv256);
            if (diag) {
                const int j0g = jt * 64 + col0;
                if (j0g     > i_g0) s00 = -1e9f;
                if (j0g + 1 > i_g0) s01 = -1e9f;
                if (j0g     > i_g1) s10 = -1e9f;
                if (j0g + 1 > i_g1) s11 = -1e9f;
            }
            s00 *= inv_sqrt_d; s01 *= inv_sqrt_d; s10 *= inv_sqrt_d; s11 *= inv_sqrt_d;
            sv[nt][0] = s00; sv[nt][1] = s01; sv[nt][2] = s10; sv[nt][3] = s11;
            rm0 = fmaxf(rm0, fmaxf(s00, s01));
            rm1 = fmaxf(rm1, fmaxf(s10, s11));
        }
        rm0 = fmaxf(rm0, __shfl_xor_sync(0xffffffffu, rm0, 1));
        rm0 = fmaxf(rm0, __shfl_xor_sync(0xffffffffu, rm0, 2));
        rm1 = fmaxf(rm1, __shfl_xor_sync(0xffffffffu, rm1, 1));
        rm1 = fmaxf(rm1, __shfl_xor_sync(0xffffffffu, rm1, 2));
        const float mn0 = fmaxf(m0, rm0), mn1 = fmaxf(m1, rm1);
        const float cr0 = __expf(m0 - mn0), cr1 = __expf(m1 - mn1);
        m0 = mn0; m1 = mn1;
        float rs0 = 0.f, rs1 = 0.f;
#pragma unroll
        for (int nt = 0; nt < 8; ++nt) {
            float p00 = __expf(sv[nt][0] - mn0);
            float p01 = __expf(sv[nt][1] - mn0);
            float p10 = __expf(sv[nt][2] - mn1);
            float p11 = __expf(sv[nt][3] - mn1);
            rs0 += p00 + p01; rs1 += p10 + p11;
            bf16 h00 = __float2bfloat16_rn(p00), h01 = __float2bfloat16_rn(p01);
            bf16 h10 = __float2bfloat16_rn(p10), h11 = __float2bfloat16_rn(p11);
            bf16 l00b = __float2bfloat16_rn(p00 - __bfloat162float(h00));
            bf16 l01b = __float2bfloat16_rn(p01 - __bfloat162float(h01));
            bf16 l10b = __float2bfloat16_rn(p10 - __bfloat162float(h10));
            bf16 l11b = __float2bfloat16_rn(p11 - __bfloat162float(h11));
            const uint32_t cofs = (uint32_t)((nt * 8 + 2 * tg) * 2);
            *(__nv_bfloat162*)(smem + APS_H + (mrow + g) * 144 + cofs)     = __nv_bfloat162(h00, h01);
            *(__nv_bfloat162*)(smem + APS_H + (mrow + g + 8) * 144 + cofs) = __nv_bfloat162(h10, h11);
            *(__nv_bfloat162*)(smem + APS_L + (mrow + g) * 144 + cofs)     = __nv_bfloat162(l00b, l01b);
            *(__nv_bfloat162*)(smem + APS_L + (mrow + g + 8) * 144 + cofs) = __nv_bfloat162(l10b, l11b);
        }
        rs0 += __shfl_xor_sync(0xffffffffu, rs0, 1);
        rs0 += __shfl_xor_sync(0xffffffffu, rs0, 2);
        rs1 += __shfl_xor_sync(0xffffffffu, rs1, 1);
        rs1 += __shfl_xor_sync(0xffffffffu, rs1, 2);
        l0 = l0 * cr0 + rs0;
        l1 = l1 * cr1 + rs1;
#pragma unroll
        for (int ot = 0; ot < 16; ++ot) {
            o_acc[ot][0] *= cr0; o_acc[ot][1] *= cr0;
            o_acc[ot][2] *= cr1; o_acc[ot][3] *= cr1;
        }
        __syncwarp();

#pragma unroll
        for (int ks = 0; ks < 4; ++ks) {
            uint32_t aH[4], aL[4];
            ldmx4(aH, pbH + ks * 32);
            ldmx4(aL, pbL + ks * 32);
#pragma unroll
            for (int vg = 0; vg < 8; ++vg) {
                uint32_t vb[4];
                ldmx4(vb, sb + AVT(buf) + (uint32_t)((vg * 16 + l15) * 144) + lhalf * 16 + ks * 32);
                mma_bf16(o_acc[2 * vg],     aH, vb[0], vb[2]);
                mma_bf16(o_acc[2 * vg],     aL, vb[0], vb[2]);
                mma_bf16(o_acc[2 * vg + 1], aH, vb[1], vb[3]);
                mma_bf16(o_acc[2 * vg + 1], aL, vb[1], vb[3]);
            }
        }
        __syncthreads();
        if (jt + 2 < ntiles) { ATT_ISSUE(buf, jt + 2); }
        CP_COMMIT();
    }

    const float li0 = 1.0f / l0, li1 = 1.0f / l1;
    float* orow0 = O + ((size_t)b * S_LEN + i0 + mrow + g)     * D_DIM + head * HD;
    float* orow1 = O + ((size_t)b * S_LEN + i0 + mrow + g + 8) * D_DIM + head * HD;
#pragma unroll
    for (int ot = 0; ot < 16; ++ot) {
        const int col = ot * 8 + 2 * tg;
        *(float2*)(orow0 + col) = make_float2(o_acc[ot][0] * li0, o_acc[ot][1] * li0);
        *(float2*)(orow1 + col) = make_float2(o_acc[ot][2] * li1, o_acc[ot][3] * li1);
    }
#undef ATT_ISSUE
}

// ===========================================================================
// Launch
// ===========================================================================
extern "C" void kernel_launch(void* const* d_in, const int* in_sizes, int n_in,
                              void* d_out, int out_size)
{
    (void)in_sizes; (void)n_in; (void)out_size;
    const float* x    = (const float*)d_in[0];
    const float* Wq   = (const float*)d_in[2];
    const float* Wk   = (const float*)d_in[3];
    const float* Wv   = (const float*)d_in[4];
    const float* Wo   = (const float*)d_in[5];
    const float* ln1g = (const float*)d_in[6];
    const float* ln1b = (const float*)d_in[7];
    const float* W1   = (const float*)d_in[8];
    const float* b1   = (const float*)d_in[9];
    const float* W2   = (const float*)d_in[10];
    const float* b2   = (const float*)d_in[11];
    const float* ln2g = (const float*)d_in[12];
    const float* ln2b = (const float*)d_in[13];
    float* out = (float*)d_out;

    int8_t *hq1, *hq2, *atq1, *atq2, *ffq1, *ffq2;
    float *hs, *ats, *ffs;
    float *q, *k, *v, *attn, *x2, *ff;
    int8_t *qq1, *qq2, *kq1, *kq2;
    float *qsc, *ksc;
    bf16 *vt;
    int8_t *wqq1, *wqq2, *wkq1, *wkq2, *wvq1, *wvq2, *woq1, *woq2, *w1q1, *w1q2, *w2q1, *w2q2;
    float *wqam, *wqs, *wkam, *wks, *wvam, *wvs, *woam, *wos, *w1am, *w1s, *w2am, *w2s;
    cudaGetSymbolAddress((void**)&hq1,  g_h_q1);
    cudaGetSymbolAddress((void**)&hq2,  g_h_q2);
    cudaGetSymbolAddress((void**)&hs,   g_h_s);
    cudaGetSymbolAddress((void**)&q,    g_q);
    cudaGetSymbolAddress((void**)&k,    g_k);
    cudaGetSymbolAddress((void**)&v,    g_v);
    cudaGetSymbolAddress((void**)&attn, g_attn);
    cudaGetSymbolAddress((void**)&atq1, g_at_q1);
    cudaGetSymbolAddress((void**)&atq2, g_at_q2);
    cudaGetSymbolAddress((void**)&ats,  g_at_s);
    cudaGetSymbolAddress((void**)&x2,   g_x2);
    cudaGetSymbolAddress((void**)&ff,   g_ff);
    cudaGetSymbolAddress((void**)&ffq1, g_ff_q1);
    cudaGetSymbolAddress((void**)&ffq2, g_ff_q2);
    cudaGetSymbolAddress((void**)&ffs,  g_ff_s);
    cudaGetSymbolAddress((void**)&qq1,  g_q_q1);
    cudaGetSymbolAddress((void**)&qq2,  g_q_q2);
    cudaGetSymbolAddress((void**)&qsc,  g_q_sc);
    cudaGetSymbolAddress((void**)&kq1,  g_k_q1);
    cudaGetSymbolAddress((void**)&kq2,  g_k_q2);
    cudaGetSymbolAddress((void**)&ksc,  g_k_sc);
    cudaGetSymbolAddress((void**)&vt,   g_vt);
    cudaGetSymbolAddress((void**)&wqq1, g_wq_q1);
    cudaGetSymbolAddress((void**)&wqq2, g_wq_q2);
    cudaGetSymbolAddress((void**)&wqam, g_wq_am);
    cudaGetSymbolAddress((void**)&wqs,  g_wq_s);
    cudaGetSymbolAddress((void**)&wkq1, g_wk_q1);
    cudaGetSymbolAddress((void**)&wkq2, g_wk_q2);
    cudaGetSymbolAddress((void**)&wkam, g_wk_am);
    cudaGetSymbolAddress((void**)&wks,  g_wk_s);
    cudaGetSymbolAddress((void**)&wvq1, g_wv_q1);
    cudaGetSymbolAddress((void**)&wvq2, g_wv_q2);
    cudaGetSymbolAddress((void**)&wvam, g_wv_am);
    cudaGetSymbolAddress((void**)&wvs,  g_wv_s);
    cudaGetSymbolAddress((void**)&woq1, g_wo_q1);
    cudaGetSymbolAddress((void**)&woq2, g_wo_q2);
    cudaGetSymbolAddress((void**)&woam, g_wo_am);
    cudaGetSymbolAddress((void**)&wos,  g_wo_s);
    cudaGetSymbolAddress((void**)&w1q1, g_w1_q1);
    cudaGetSymbolAddress((void**)&w1q2, g_w1_q2);
    cudaGetSymbolAddress((void**)&w1am, g_w1_am);
    cudaGetSymbolAddress((void**)&w1s,  g_w1_s);
    cudaGetSymbolAddress((void**)&w2q1, g_w2_q1);
    cudaGetSymbolAddress((void**)&w2q2, g_w2_q2);
    cudaGetSymbolAddress((void**)&w2am, g_w2_am);
    cudaGetSymbolAddress((void**)&w2s,  g_w2_s);

    cudaFuncSetAttribute(attn_i8,
                         cudaFuncAttributeMaxDynamicSharedMemorySize, ATT_SMEM);
    cudaFuncSetAttribute(gemm_i8<false, false, false>,
                         cudaFuncAttributeMaxDynamicSharedMemorySize, I8_SMEM);
    cudaFuncSetAttribute(gemm_i8<false, false, true>,
                         cudaFuncAttributeMaxDynamicSharedMemorySize, I8_SMEM);
    cudaFuncSetAttribute(gemm_i8<true, true, false>,
                         cudaFuncAttributeMaxDynamicSharedMemorySize, I8_SMEM);
    cudaFuncSetAttribute(gemm_i8<false, true, true>,
                         cudaFuncAttributeMaxDynamicSharedMemorySize, I8_SMEM);

    const dim3 blk(256);
    const dim3 blkG(512);

    // ---- weight prep ----
    cudaMemsetAsync(wqam, 0, D_DIM * sizeof(float));
    cudaMemsetAsync(wkam, 0, D_DIM * sizeof(float));
    cudaMemsetAsync(wvam, 0, D_DIM * sizeof(float));
    cudaMemsetAsync(woam, 0, D_DIM * sizeof(float));
    cudaMemsetAsync(w1am, 0, M_FF * sizeof(float));
    cudaMemsetAsync(w2am, 0, D_DIM * sizeof(float));
    colamax_kernel<<<dim3(64, 64),  blk>>>(Wq, D_DIM, D_DIM, wqam);
    colamax_kernel<<<dim3(64, 64),  blk>>>(Wk, D_DIM, D_DIM, wkam);
    colamax_kernel<<<dim3(64, 64),  blk>>>(Wv, D_DIM, D_DIM, wvam);
    colamax_kernel<<<dim3(64, 64),  blk>>>(Wo, D_DIM, D_DIM, woam);
    colamax_kernel<<<dim3(M_FF / 32,  D_DIM / 32), blk>>>(W1, D_DIM, M_FF, w1am);
    colamax_kernel<<<dim3(D_DIM / 32, M_FF / 32),  blk>>>(W2, M_FF, D_DIM, w2am);
    transpose_quant_i8<<<dim3(64, 64),  blk>>>(Wq, wqam, wqq1, wqq2, wqs, D_DIM, D_DIM);
    transpose_quant_i8<<<dim3(64, 64),  blk>>>(Wk, wkam, wkq1, wkq2, wks, D_DIM, D_DIM);
    transpose_quant_i8<<<dim3(64, 64),  blk>>>(Wv, wvam, wvq1, wvq2, wvs, D_DIM, D_DIM);
    transpose_quant_i8<<<dim3(64, 64),  blk>>>(Wo, woam, woq1, woq2, wos, D_DIM, D_DIM);
    transpose_quant_i8<<<dim3(256, 64), blk>>>(W1, w1am, w1q1, w1q2, w1s, D_DIM, M_FF);
    transpose_quant_i8<<<dim3(64, 256), blk>>>(W2, w2am, w2q1, w2q2, w2s, M_FF, D_DIM);

    const dim3 gDD(D_DIM / 128, ROWS / 128);   // (16, 32)
    const dim3 gDM(M_FF / 128,  ROWS / 128);   // (64, 32)

    // ---- layer ----
    ln_quant_i8<<<ROWS, blk>>>(x, ln1g, ln1b, hq1, hq2, hs);
    gemm_i8<false, false, false><<<gDD, blkG, I8_SMEM>>>(
        hq1, hq2, wqq1, wqq2, hs, wqs, nullptr, nullptr, q, D_DIM, D_DIM);
    gemm_i8<false, false, false><<<gDD, blkG, I8_SMEM>>>(
        hq1, hq2, wkq1, wkq2, hs, wks, nullptr, nullptr, k, D_DIM, D_DIM);
    gemm_i8<false, false, false><<<gDD, blkG, I8_SMEM>>>(
        hq1, hq2, wvq1, wvq2, hs, wvs, nullptr, nullptr, v, D_DIM, D_DIM);
    quant_head_i8<<<ROWS, blk>>>(q, qq1, qq2, qsc);
    quant_head_i8<<<ROWS, blk>>>(k, kq1, kq2, ksc);
    vt_split<<<dim3(S_LEN / 32, HD / 32, B_SZ * NH), blk>>>(v, vt);
    attn_i8<<<dim3(S_LEN / 128, NH, B_SZ), blk, ATT_SMEM>>>(
        qq1, qq2, qsc, kq1, kq2, ksc, vt, attn);
    rowquant_i8<<<ROWS, blk>>>(attn, D_DIM, atq1, atq2, ats);
    gemm_i8<false, false, true><<<gDD, blkG, I8_SMEM>>>(
        atq1, atq2, woq1, woq2, ats, wos, nullptr, x, x2, D_DIM, D_DIM);
    ln_quant_i8<<<ROWS, blk>>>(x2, ln2g, ln2b, hq1, hq2, hs);
    gemm_i8<true, true, false><<<gDM, blkG, I8_SMEM>>>(
        hq1, hq2, w1q1, w1q2, hs, w1s, b1, nullptr, ff, M_FF, D_DIM);
    rowquant_i8<<<ROWS, blk>>>(ff, M_FF, ffq1, ffq2, ffs);
    gemm_i8<false, true, true><<<gDD, blkG, I8_SMEM>>>(
        ffq1, ffq2, w2q1, w2q2, ffs, w2s, b2, x2, out, D_DIM, M_FF);
}

// round 12
// speedup vs baseline: 4.0676x; 1.0141x over previous
#include <cuda_runtime.h>
#include <cuda_bf16.h>
#include <cstdint>
#include <math.h>

// Problem constants
#define S_LEN 2048
#define D_DIM 2048
#define B_SZ  2
#define NH    16
#define HD    128
#define M_FF  8192
#define ROWS  (B_SZ * S_LEN)   // 4096

typedef __nv_bfloat16 bf16;

// -------------------- scratch (device globals; no allocation allowed) -----
__device__ __align__(16) int8_t g_h_q1  [ROWS * D_DIM];
__device__ __align__(16) int8_t g_h_q2  [ROWS * D_DIM];
__device__            float  g_h_s   [ROWS];
__device__ __align__(16) float g_attn  [ROWS * D_DIM];
__device__ __align__(16) int8_t g_at_q1 [ROWS * D_DIM];
__device__ __align__(16) int8_t g_at_q2 [ROWS * D_DIM];
__device__            float  g_at_s  [ROWS];
__device__ __align__(16) float g_x2    [ROWS * D_DIM];
__device__ __align__(16) float g_ff    [ROWS * M_FF];
__device__ __align__(16) int8_t g_ff_q1 [ROWS * M_FF];
__device__ __align__(16) int8_t g_ff_q2 [ROWS * M_FF];
__device__            float  g_ff_s  [ROWS];
// attention operands (flat quirk layout; scales at [row*16+seg] == [bh*S+j])
__device__ __align__(16) int8_t g_q_q1  [ROWS * D_DIM];
__device__ __align__(16) int8_t g_q_q2  [ROWS * D_DIM];
__device__            float  g_q_sc  [ROWS * NH];
__device__ __align__(16) int8_t g_k_q1  [ROWS * D_DIM];
__device__ __align__(16) int8_t g_k_q2  [ROWS * D_DIM];
__device__            float  g_k_sc  [ROWS * NH];
__device__ __align__(16) bf16  g_vbf   [ROWS * D_DIM];             // V bf16 (packed)
__device__ __align__(16) bf16  g_vt    [B_SZ * NH * HD * S_LEN];   // [bh][c][j]
// int8 2-limb weights ([N][K]); Wq+Wk stacked for combined QK GEMM
__device__ __align__(16) int8_t g_wqk_q1 [2 * D_DIM * D_DIM];
__device__ __align__(16) int8_t g_wqk_q2 [2 * D_DIM * D_DIM];
__device__            float  g_wqk_s  [2 * D_DIM];
__device__            float  g_wq_am [D_DIM];
__device__            float  g_wk_am [D_DIM];
__device__ __align__(16) int8_t g_wv_q1 [D_DIM * D_DIM];
__device__ __align__(16) int8_t g_wv_q2 [D_DIM * D_DIM];
__device__            float  g_wv_am [D_DIM];
__device__            float  g_wv_s  [D_DIM];
__device__ __align__(16) int8_t g_wo_q1 [D_DIM * D_DIM];
__device__ __align__(16) int8_t g_wo_q2 [D_DIM * D_DIM];
__device__            float  g_wo_am [D_DIM];
__device__            float  g_wo_s  [D_DIM];
__device__ __align__(16) int8_t g_w1_q1 [M_FF * D_DIM];
__device__ __align__(16) int8_t g_w1_q2 [M_FF * D_DIM];
__device__            float  g_w1_am [M_FF];
__device__            float  g_w1_s  [M_FF];
__device__ __align__(16) int8_t g_w2_q1 [D_DIM * M_FF];
__device__ __align__(16) int8_t g_w2_q2 [D_DIM * M_FF];
__device__            float  g_w2_am [D_DIM];
__device__            float  g_w2_s  [D_DIM];

// ===========================================================================
// helpers
// ===========================================================================
__device__ __forceinline__ uint32_t smem_u32(const void* p) {
    uint32_t a;
    asm("{ .reg .u64 t; cvta.to.shared.u64 t, %1; cvt.u32.u64 %0, t; }" : "=r"(a) : "l"(p));
    return a;
}
__device__ __forceinline__ void cpa16(uint32_t dst, const void* src) {
    asm volatile("cp.async.cg.shared.global [%0], [%1], 16;" :: "r"(dst), "l"(src));
}
#define CP_COMMIT() asm volatile("cp.async.commit_group;" ::: "memory")
#define CP_WAIT1()  asm volatile("cp.async.wait_group 1;" ::: "memory")
#define CP_WAIT0()  asm volatile("cp.async.wait_group 0;" ::: "memory")

__device__ __forceinline__ void ldmx4(uint32_t* r, uint32_t addr) {
    asm volatile("ldmatrix.sync.aligned.m8n8.x4.shared.b16 {%0,%1,%2,%3}, [%4];"
        : "=r"(r[0]), "=r"(r[1]), "=r"(r[2]), "=r"(r[3]) : "r"(addr));
}
__device__ __forceinline__ void mma_bf16(float* d, const uint32_t* a, uint32_t b0, uint32_t b1) {
    asm volatile(
        "mma.sync.aligned.m16n8k16.row.col.f32.bf16.bf16.f32 "
        "{%0,%1,%2,%3},{%4,%5,%6,%7},{%8,%9},{%0,%1,%2,%3};"
        : "+f"(d[0]), "+f"(d[1]), "+f"(d[2]), "+f"(d[3])
        : "r"(a[0]), "r"(a[1]), "r"(a[2]), "r"(a[3]), "r"(b0), "r"(b1));
}
__device__ __forceinline__ void mma_s8(int* d, const uint32_t* a, uint32_t b0, uint32_t b1) {
    asm volatile(
        "mma.sync.aligned.m16n8k32.row.col.s32.s8.s8.s32 "
        "{%0,%1,%2,%3},{%4,%5,%6,%7},{%8,%9},{%0,%1,%2,%3};"
        : "+r"(d[0]), "+r"(d[1]), "+r"(d[2]), "+r"(d[3])
        : "r"(a[0]), "r"(a[1]), "r"(a[2]), "r"(a[3]), "r"(b0), "r"(b1));
}
__device__ __forceinline__ void quant2(float v, float inv_s, int8_t& h, int8_t& l) {
    float q  = v * inv_s;
    float q1 = rintf(q);
    float q2 = rintf((q - q1) * 256.0f);
    q2 = fminf(fmaxf(q2, -127.0f), 127.0f);
    h = (int8_t)(int)q1;
    l = (int8_t)(int)q2;
}

// ===========================================================================
// per-column absmax
// ===========================================================================
__global__ __launch_bounds__(256)
void colamax_kernel(const float* __restrict__ in, int R, int C, float* __restrict__ amax)
{
    __shared__ float sm_[8][33];
    const int tx = threadIdx.x & 31;
    const int ty = threadIdx.x >> 5;
    const int bx = blockIdx.x * 32, by = blockIdx.y * 32;
    float m = 0.f;
#pragma unroll
    for (int j = 0; j < 4; ++j)
        m = fmaxf(m, fabsf(in[(size_t)(by + ty + 8 * j) * C + bx + tx]));
    sm_[ty][tx] = m;
    __syncthreads();
    if (ty == 0) {
        float mm = sm_[0][tx];
#pragma unroll
        for (int r = 1; r < 8; ++r) mm = fmaxf(mm, sm_[r][tx]);
        atomicMax((unsigned int*)&amax[bx + tx], __float_as_uint(mm));
    }
}

// ===========================================================================
// transpose + int8 2-limb quant (weights)
// ===========================================================================
__global__ __launch_bounds__(256)
void transpose_quant_i8(const float* __restrict__ in, const float* __restrict__ amax,
                        int8_t* __restrict__ q1o, int8_t* __restrict__ q2o,
                        float* __restrict__ sOut, int R, int C)
{
    __shared__ float tile[32][33];
    const int tx = threadIdx.x & 31;
    const int ty = threadIdx.x >> 5;
    const int bx = blockIdx.x * 32, by = blockIdx.y * 32;
#pragma unroll
    for (int j = 0; j < 32; j += 8)
        tile[ty + j][tx] = in[(size_t)(by + ty + j) * C + bx + tx];
    __syncthreads();
#pragma unroll
    for (int j = 0; j < 32; j += 8) {
        const int orow = bx + ty + j;
        float am = fmaxf(amax[orow], 1e-20f);
        float s  = am * (1.0f / 127.0f);
        float inv = 127.0f / am;
        if (tx == 0) sOut[orow] = s;
        float v = tile[tx][ty + j];
        int8_t h, l; quant2(v, inv, h, l);
        size_t o = (size_t)orow * R + by + tx;
        q1o[o] = h; q2o[o] = l;
    }
}

// ===========================================================================
// per-row int8 2-limb quant (attn, ff)
// ===========================================================================
__global__ __launch_bounds__(256)
void rowquant_i8(const float* __restrict__ in, int Kd,
                 int8_t* __restrict__ q1, int8_t* __restrict__ q2, float* __restrict__ s)
{
    __shared__ float red[9];
    const int row = blockIdx.x;
    const int tid = threadIdx.x;
    const float* r = in + (size_t)row * Kd;
    float m = 0.f;
    for (int c = tid; c < Kd; c += 256) m = fmaxf(m, fabsf(r[c]));
#pragma unroll
    for (int d = 16; d > 0; d >>= 1) m = fmaxf(m, __shfl_xor_sync(0xffffffffu, m, d));
    if ((tid & 31) == 0) red[tid >> 5] = m;
    __syncthreads();
    if (tid == 0) {
        float mm = red[0];
#pragma unroll
        for (int i = 1; i < 8; ++i) mm = fmaxf(mm, red[i]);
        mm = fmaxf(mm, 1e-20f);
        red[8] = mm;
        s[row] = mm * (1.0f / 127.0f);
    }
    __syncthreads();
    const float inv = 127.0f / red[8];
    for (int c = tid; c < Kd; c += 256) {
        int8_t h, l; quant2(r[c], inv, h, l);
        q1[(size_t)row * Kd + c] = h;
        q2[(size_t)row * Kd + c] = l;
    }
}

// ===========================================================================
// V^T split: pure bf16 transpose. vt[bh][c][j] = v_flat_bf16[bh*262144 + j*128 + c]
// ===========================================================================
__global__ __launch_bounds__(256)
void vt_split(const bf16* __restrict__ v, bf16* __restrict__ vt)
{
    __shared__ bf16 tile[32][34];
    const int tx = threadIdx.x & 31;
    const int ty = threadIdx.x >> 5;
    const int bh = blockIdx.z;
    const int j0 = blockIdx.x * 32, c0 = blockIdx.y * 32;
    const bf16* vb = v + (size_t)bh * S_LEN * HD;
#pragma unroll
    for (int jj = 0; jj < 32; jj += 8)
        tile[ty + jj][tx] = vb[(size_t)(j0 + ty + jj) * HD + c0 + tx];
    __syncthreads();
#pragma unroll
    for (int jj = 0; jj < 32; jj += 8)
        vt[((size_t)bh * HD + c0 + ty + jj) * S_LEN + j0 + tx] = tile[tx][ty + jj];
}

// ===========================================================================
// LayerNorm + int8 2-limb quant
// ===========================================================================
__global__ __launch_bounds__(256)
void ln_quant_i8(const float* __restrict__ x, const float* __restrict__ gam,
                 const float* __restrict__ bet, int8_t* __restrict__ q1,
                 int8_t* __restrict__ q2, float* __restrict__ sArr)
{
    __shared__ float red[9];
    const int row = blockIdx.x;
    const int tid = threadIdx.x;
    const float* xr = x + (size_t)row * D_DIM;

    float v[8];
    float sum = 0.f;
#pragma unroll
    for (int i = 0; i < 8; ++i) { v[i] = xr[tid + 256 * i]; sum += v[i]; }
#pragma unroll
    for (int d = 16; d > 0; d >>= 1) sum += __shfl_xor_sync(0xffffffffu, sum, d);
    if ((tid & 31) == 0) red[tid >> 5] = sum;
    __syncthreads();
    float tot = 0.f;
#pragma unroll
    for (int i = 0; i < 8; ++i) tot += red[i];
    const float mean = tot * (1.0f / (float)D_DIM);

    float s2 = 0.f;
#pragma unroll
    for (int i = 0; i < 8; ++i) { float d = v[i] - mean; s2 += d * d; }
    __syncthreads();
#pragma unroll
    for (int d = 16; d > 0; d >>= 1) s2 += __shfl_xor_sync(0xffffffffu, s2, d);
    if ((tid & 31) == 0) red[tid >> 5] = s2;
    __syncthreads();
    tot = 0.f;
#pragma unroll
    for (int i = 0; i < 8; ++i) tot += red[i];
    const float rstd = rsqrtf(tot * (1.0f / (float)D_DIM) + 1e-5f);

    float o[8];
    float am = 0.f;
#pragma unroll
    for (int i = 0; i < 8; ++i) {
        int c = tid + 256 * i;
        o[i] = (v[i] - mean) * rstd * gam[c] + bet[c];
        am = fmaxf(am, fabsf(o[i]));
    }
    __syncthreads();
#pragma unroll
    for (int d = 16; d > 0; d >>= 1) am = fmaxf(am, __shfl_xor_sync(0xffffffffu, am, d));
    if ((tid & 31) == 0) red[tid >> 5] = am;
    __syncthreads();
    if (tid == 0) {
        float mm = red[0];
#pragma unroll
        for (int i = 1; i < 8; ++i) mm = fmaxf(mm, red[i]);
        mm = fmaxf(mm, 1e-20f);
        red[8] = mm;
        sArr[row] = mm * (1.0f / 127.0f);
    }
    __syncthreads();
    const float inv = 127.0f / red[8];
#pragma unroll
    for (int i = 0; i < 8; ++i) {
        int c = tid + 256 * i;
        int8_t h, l; quant2(o[i], inv, h, l);
        q1[(size_t)row * D_DIM + c] = h;
        q2[(size_t)row * D_DIM + c] = l;
    }
}

// ===========================================================================
// int8 2-limb tensor-core GEMM — 512 threads / 16 warps, warp tile 32x32.
// EPI: 0 = fp32 out (+bias/relu/res), 1 = quantizing epilogue (QK: int8 2-limb
// + per-(row,128col) scales, seg = bx), 2 = bf16 out (V).
// ===========================================================================
#define ISTAGE 32768
#define ISM_A2 8192
#define ISM_B1 16384
#define ISM_B2 24576
#define I8_SMEM (3 * ISTAGE)

template<int EPI, bool RELU, bool HAS_BIAS, bool HAS_RES>
__global__ __launch_bounds__(512, 1)
void gemm_i8(const int8_t* __restrict__ A1, const int8_t* __restrict__ A2,
             const int8_t* __restrict__ B1, const int8_t* __restrict__ B2,
             const float* __restrict__ sA, const float* __restrict__ sB,
             const float* __restrict__ bias, const float* __restrict__ res,
             float* __restrict__ Cf, bf16* __restrict__ Obf,
             int8_t* __restrict__ oq1a, int8_t* __restrict__ oq2a, float* __restrict__ osca,
             int8_t* __restrict__ oq1b, int8_t* __restrict__ oq2b, float* __restrict__ oscb,
             int Nd, int Kd)
{
    extern __shared__ char smem[];
    const uint32_t sb = smem_u32(smem);
    const int tid  = threadIdx.x;
    const int warp = tid >> 5;
    const int lane = tid & 31;
    const int wm   = warp & 3;
    const int wn   = warp >> 2;
    const int bx = blockIdx.x, by = blockIdx.y;
    const int ktiles = Kd >> 6;

    const int r0 = tid >> 2;
    const int cc = tid & 3;
    const int pc = (cc + (r0 >> 1)) & 3;
    const size_t gA0 = (size_t)(by * 128 + r0) * Kd + cc * 16;
    const size_t gB0 = (size_t)(bx * 128 + r0) * Kd + cc * 16;
    const int8_t* pA1 = A1 + gA0;  const int8_t* pA2 = A2 + gA0;
    const int8_t* pB1 = B1 + gB0;  const int8_t* pB2 = B2 + gB0;
    const uint32_t dA0 = (uint32_t)(r0 * 64 + pc * 16);

#define ISSUE_I8(slot, u) do { \
    uint32_t s0_ = sb + (slot) * ISTAGE; int ko_ = (u) * 64; \
    cpa16(s0_ + dA0,          pA1 + ko_); \
    cpa16(s0_ + dA0 + ISM_A2, pA2 + ko_); \
    cpa16(s0_ + dA0 + ISM_B1, pB1 + ko_); \
    cpa16(s0_ + dA0 + ISM_B2, pB2 + ko_); \
} while (0)

    const int l15   = lane & 15;
    const int chalf = lane >> 4;
    const uint32_t pc0 = (uint32_t)((chalf + (l15 >> 1)) & 3);
    const uint32_t pc1 = (uint32_t)((2 + chalf + (l15 >> 1)) & 3);
    const uint32_t offA[2] = { (uint32_t)((wm * 32 + l15) * 64) + pc0 * 16,
                               (uint32_t)((wm * 32 + l15) * 64) + pc1 * 16 };
    const uint32_t offB0[2] = { (uint32_t)((wn * 32 + l15) * 64) + pc0 * 16,
                                (uint32_t)((wn * 32 + l15) * 64) + pc1 * 16 };
    const uint32_t offB1[2] = { (uint32_t)((wn * 32 + 16 + l15) * 64) + pc0 * 16,
                                (uint32_t)((wn * 32 + 16 + l15) * 64) + pc1 * 16 };

    int accH[2][4][4], accM[2][4][4];
#pragma unroll
    for (int mt = 0; mt < 2; ++mt)
#pragma unroll
        for (int nt = 0; nt < 4; ++nt)
#pragma unroll
            for (int e = 0; e < 4; ++e) { accH[mt][nt][e] = 0; accM[mt][nt][e] = 0; }

    ISSUE_I8(0, 0); CP_COMMIT();
    ISSUE_I8(1, 1); CP_COMMIT();

    for (int t = 0; t < ktiles; ++t) {
        CP_WAIT1();
        __syncthreads();
        {
            const int u = t + 2;
            if (u < ktiles) { ISSUE_I8(u % 3, u); }
            CP_COMMIT();
        }
        const uint32_t st = sb + (t % 3) * ISTAGE;
#pragma unroll
        for (int j = 0; j < 2; ++j) {
            uint32_t b1F[8], b2F[8];
            ldmx4(&b1F[0], st + ISM_B1 + offB0[j]);
            ldmx4(&b1F[4], st + ISM_B1 + offB1[j]);
            ldmx4(&b2F[0], st + ISM_B2 + offB0[j]);
            ldmx4(&b2F[4], st + ISM_B2 + offB1[j]);
#pragma unroll
            for (int mt = 0; mt < 2; ++mt) {
                uint32_t a1F[4], a2F[4];
                ldmx4(a1F, st + mt * 1024 + offA[j]);
                ldmx4(a2F, st + ISM_A2 + mt * 1024 + offA[j]);
#pragma unroll
                for (int nt = 0; nt < 4; ++nt) {
                    const int p = (nt >> 1) * 4 + (nt & 1);
                    const uint32_t b0h = b1F[p], b1h = b1F[p + 2];
                    const uint32_t b0l = b2F[p], b1l = b2F[p + 2];
                    mma_s8(accH[mt][nt], a1F, b0h, b1h);
                    mma_s8(accM[mt][nt], a2F, b0h, b1h);
                    mma_s8(accM[mt][nt], a1F, b0l, b1l);
                }
            }
        }
    }

    const int g  = lane >> 2;
    const int tg = lane & 3;
    const float i256 = 0.00390625f;

    if (EPI == 1) {
        // quantizing epilogue (QK): per-row absmax over this CTA's 128 cols
        CP_WAIT0();
        __syncthreads();
        float* rmaxf = (float*)smem;
        if (tid < 128) rmaxf[tid] = 0.f;
        __syncthreads();
#pragma unroll
        for (int mt = 0; mt < 2; ++mt) {
            const int lrow = wm * 32 + mt * 16 + g;
            const int grow = by * 128 + lrow;
            const float sa0 = sA[grow], sa8 = sA[grow + 8];
            float am0 = 0.f, am1 = 0.f;
#pragma unroll
            for (int nt = 0; nt < 4; ++nt) {
                const int colg = bx * 128 + wn * 32 + nt * 8 + 2 * tg;
                const float sb0 = sB[colg], sb1 = sB[colg + 1];
                float v0 = sa0 * sb0 * ((float)accH[mt][nt][0] + (float)accM[mt][nt][0] * i256);
                float v1 = sa0 * sb1 * ((float)accH[mt][nt][1] + (float)accM[mt][nt][1] * i256);
                float v2 = sa8 * sb0 * ((float)accH[mt][nt][2] + (float)accM[mt][nt][2] * i256);
                float v3 = sa8 * sb1 * ((float)accH[mt][nt][3] + (float)accM[mt][nt][3] * i256);
                am0 = fmaxf(am0, fmaxf(fabsf(v0), fabsf(v1)));
                am1 = fmaxf(am1, fmaxf(fabsf(v2), fabsf(v3)));
            }
            atomicMax((unsigned int*)&rmaxf[lrow],     __float_as_uint(am0));
            atomicMax((unsigned int*)&rmaxf[lrow + 8], __float_as_uint(am1));
        }
        __syncthreads();
        const int seg = (bx < 16) ? bx : (bx - 16);
        int8_t* o1 = (bx < 16) ? oq1a : oq1b;
        int8_t* o2 = (bx < 16) ? oq2a : oq2b;
        float*  osc = (bx < 16) ? osca : oscb;
#pragma unroll
        for (int mt = 0; mt < 2; ++mt) {
            const int lrow = wm * 32 + mt * 16 + g;
            const size_t grow = (size_t)(by * 128 + lrow);
            const float sa0 = sA[grow], sa8 = sA[grow + 8];
            const float am0 = fmaxf(rmaxf[lrow], 1e-20f);
            const float am1 = fmaxf(rmaxf[lrow + 8], 1e-20f);
            const float inv0 = 127.0f / am0, inv1 = 127.0f / am1;
            if (wn == 0 && tg == 0) {
                osc[grow * 16 + seg]       = am0 * (1.0f / 127.0f);
                osc[(grow + 8) * 16 + seg] = am1 * (1.0f / 127.0f);
            }
#pragma unroll
            for (int nt = 0; nt < 4; ++nt) {
                const int colg = bx * 128 + wn * 32 + nt * 8 + 2 * tg;
                const int colo = seg * 128 + wn * 32 + nt * 8 + 2 * tg;
                const float sb0 = sB[colg], sb1 = sB[colg + 1];
                float v0 = sa0 * sb0 * ((float)accH[mt][nt][0] + (float)accM[mt][nt][0] * i256);
                float v1 = sa0 * sb1 * ((float)accH[mt][nt][1] + (float)accM[mt][nt][1] * i256);
                float v2 = sa8 * sb0 * ((float)accH[mt][nt][2] + (float)accM[mt][nt][2] * i256);
                float v3 = sa8 * sb1 * ((float)accH[mt][nt][3] + (float)accM[mt][nt][3] * i256);
                int8_t h0, l0, h1, l1;
                quant2(v0, inv0, h0, l0); quant2(v1, inv0, h1, l1);
                *(char2*)(o1 + grow * D_DIM + colo) = make_char2(h0, h1);
                *(char2*)(o2 + grow * D_DIM + colo) = make_char2(l0, l1);
                quant2(v2, inv1, h0, l0); quant2(v3, inv1, h1, l1);
                *(char2*)(o1 + (grow + 8) * D_DIM + colo) = make_char2(h0, h1);
                *(char2*)(o2 + (grow + 8) * D_DIM + colo) = make_char2(l0, l1);
            }
        }
        return;
    }

#pragma unroll
    for (int mt = 0; mt < 2; ++mt) {
        const int row = by * 128 + wm * 32 + mt * 16 + g;
        const float sa0 = sA[row], sa8 = sA[row + 8];
#pragma unroll
        for (int nt = 0; nt < 4; ++nt) {
            const int col = bx * 128 + wn * 32 + nt * 8 + 2 * tg;
            const float sb0 = sB[col], sb1 = sB[col + 1];
            float v0 = sa0 * sb0 * ((float)accH[mt][nt][0] + (float)accM[mt][nt][0] * i256);
            float v1 = sa0 * sb1 * ((float)accH[mt][nt][1] + (float)accM[mt][nt][1] * i256);
            float v2 = sa8 * sb0 * ((float)accH[mt][nt][2] + (float)accM[mt][nt][2] * i256);
            float v3 = sa8 * sb1 * ((float)accH[mt][nt][3] + (float)accM[mt][nt][3] * i256);
            if (EPI == 2) {
                *(__nv_bfloat162*)(Obf + (size_t)row * Nd + col) =
                    __nv_bfloat162(__float2bfloat16_rn(v0), __float2bfloat16_rn(v1));
                *(__nv_bfloat162*)(Obf + (size_t)(row + 8) * Nd + col) =
                    __nv_bfloat162(__float2bfloat16_rn(v2), __float2bfloat16_rn(v3));
            } else {
                if (HAS_BIAS) {
                    float2 b2v = *(const float2*)(bias + col);
                    v0 += b2v.x; v1 += b2v.y; v2 += b2v.x; v3 += b2v.y;
                }
                if (RELU) {
                    v0 = fmaxf(v0, 0.f); v1 = fmaxf(v1, 0.f);
                    v2 = fmaxf(v2, 0.f); v3 = fmaxf(v3, 0.f);
                }
                if (HAS_RES) {
                    float2 ra = *(const float2*)(res + (size_t)row * Nd + col);
                    float2 rb = *(const float2*)(res + (size_t)(row + 8) * Nd + col);
                    v0 += ra.x; v1 += ra.y; v2 += rb.x; v3 += rb.y;
                }
                *(float2*)(Cf + (size_t)row * Nd + col)       = make_float2(v0, v1);
                *(float2*)(Cf + (size_t)(row + 8) * Nd + col) = make_float2(v2, v3);
            }
        }
    }
#undef ISSUE_I8
}

// ===========================================================================
// Tensor-core flash attention (QUIRK layout) — unchanged from round 11
// ===========================================================================
#define AQ_H  0
#define AQ_L  18432
#define AK_H(bf) (36864 + (bf) * 18432)
#define AK_L(bf) (AK_H(bf) + 9216)
#define AVT(bf)  (73728 + (bf) * 18432)
#define APS_H 110592
#define APS_L 129024
#define ASQ   147456
#define ASK(bf) (147968 + (bf) * 256)
#define ATT_SMEM 148480

__global__ __launch_bounds__(256)
void attn_i8(const int8_t* __restrict__ Qq1, const int8_t* __restrict__ Qq2,
             const float* __restrict__ Qs,
             const int8_t* __restrict__ Kq1, const int8_t* __restrict__ Kq2,
             const float* __restrict__ Ks,
             const bf16* __restrict__ VT, float* __restrict__ O)
{
    extern __shared__ char smem[];
    const uint32_t sb = smem_u32(smem);
    float* sQf = (float*)(smem + ASQ);
    const int qt   = blockIdx.x;
    const int head = blockIdx.y;
    const int b    = blockIdx.z;
    const int tid  = threadIdx.x;
    const int warp = tid >> 5;
    const int lane = tid & 31;
    const int l15  = lane & 15;
    const int lhalf = lane >> 4;
    const int g  = lane >> 2;
    const int tg = lane & 3;
    const int mrow = warp * 16;
    const int ntiles = 2 * qt + 2;
    const int bh = b * NH + head;
    const size_t hbase = (size_t)bh * S_LEN * HD;
    const int i0 = qt * 128;
    const bf16* vth = VT + (size_t)bh * HD * S_LEN;

    if (tid < 128) sQf[tid] = Qs[(size_t)bh * S_LEN + i0 + tid];

#pragma unroll
    for (int i = 0; i < 4; ++i) {
        int id = tid + 256 * i;
        int r = id >> 3, c = (id & 7) * 16;
        cpa16(sb + AQ_H + r * 144 + c, Qq1 + hbase + (size_t)(i0 + r) * HD + c);
        cpa16(sb + AQ_L + r * 144 + c, Qq2 + hbase + (size_t)(i0 + r) * HD + c);
    }

#define ATT_ISSUE(bf_, jt_) do { \
    const size_t kj0_ = (size_t)(jt_) * 64; \
    for (int i_ = tid; i_ < 512; i_ += 256) { \
        int r_ = i_ >> 3, c_ = (i_ & 7) * 16; \
        cpa16(sb + AK_H(bf_) + r_ * 144 + c_, Kq1 + hbase + (kj0_ + r_) * HD + c_); \
        cpa16(sb + AK_L(bf_) + r_ * 144 + c_, Kq2 + hbase + (kj0_ + r_) * HD + c_); \
    } \
    for (int i_ = tid; i_ < 1024; i_ += 256) { \
        int r_ = i_ >> 3, c_ = (i_ & 7) * 16; \
        cpa16(sb + AVT(bf_) + r_ * 144 + c_, \
              (const char*)(vth + (size_t)r_ * S_LEN + kj0_) + c_); \
    } \
    if (tid < 64) ((float*)(smem + ASK(bf_)))[tid] = Ks[(size_t)bh * S_LEN + kj0_ + tid]; \
} while (0)

    ATT_ISSUE(0, 0); CP_COMMIT();
    ATT_ISSUE(1, 1); CP_COMMIT();

    float o_acc[16][4];
#pragma unroll
    for (int ot = 0; ot < 16; ++ot)
#pragma unroll
        for (int e = 0; e < 4; ++e) o_acc[ot][e] = 0.f;
    float m0 = -1e30f, m1 = -1e30f, l0 = 0.f, l1 = 0.f;
    const float inv_sqrt_d = 0.08838834764831845f;
    const float inv256 = 0.00390625f;
    const int i_g0 = i0 + mrow + g;
    const int i_g1 = i_g0 + 8;

    const uint32_t qbH = sb + AQ_H + (mrow + l15) * 144 + lhalf * 16;
    const uint32_t qbL = sb + AQ_L + (mrow + l15) * 144 + lhalf * 16;
    const uint32_t pbH = sb + APS_H + (mrow + l15) * 144 + lhalf * 16;
    const uint32_t pbL = sb + APS_L + (mrow + l15) * 144 + lhalf * 16;

    for (int jt = 0; jt < ntiles; ++jt) {
        const int buf = jt & 1;
        CP_WAIT1();
        __syncthreads();
        const float* sKf = (const float*)(smem + ASK(buf));

        int accH[8][4], accM[8][4];
#pragma unroll
        for (int nt = 0; nt < 8; ++nt)
#pragma unroll
            for (int e = 0; e < 4; ++e) { accH[nt][e] = 0; accM[nt][e] = 0; }

#pragma unroll
        for (int ks = 0; ks < 4; ++ks) {
            uint32_t aH[4], aL[4];
            ldmx4(aH, qbH + ks * 32);
            ldmx4(aL, qbL + ks * 32);
#pragma unroll
            for (int ng = 0; ng < 4; ++ng) {
                uint32_t bH4[4], bL4[4];
                const uint32_t kaddr = (uint32_t)((ng * 16 + l15) * 144) + lhalf * 16 + ks * 32;
                ldmx4(bH4, sb + AK_H(buf) + kaddr);
                ldmx4(bL4, sb + AK_L(buf) + kaddr);
                mma_s8(accH[2 * ng],     aH, bH4[0], bH4[2]);
                mma_s8(accM[2 * ng],     aL, bH4[0], bH4[2]);
                mma_s8(accM[2 * ng],     aH, bL4[0], bL4[2]);
                mma_s8(accH[2 * ng + 1], aH, bH4[1], bH4[3]);
                mma_s8(accM[2 * ng + 1], aL, bH4[1], bH4[3]);
                mma_s8(accM[2 * ng + 1], aH, bL4[1], bL4[3]);
            }
        }

        const float sq0 = sQf[mrow + g], sq1 = sQf[mrow + g + 8];
        const bool diag = (jt >= 2 * qt);
        float sv[8][4];
        float rm0 = -1e30f, rm1 = -1e30f;
#pragma unroll
        for (int nt = 0; nt < 8; ++nt) {
            const int col0 = nt * 8 + 2 * tg;
            const float sk0 = sKf[col0], sk1 = sKf[col0 + 1];
            float s00 = sq0 * sk0 * ((float)accH[nt][0] + (float)accM[nt][0] * inv256);
            float s01 = sq0 * sk1 * ((float)accH[nt][1] + (float)accM[nt][1] * inv256);
            float s10 = sq1 * sk0 * ((float)accH[nt][2] + (float)accM[nt][2] * inv256);
            float s11 = sq1 * sk1 * ((float)accH[nt][3] + (float)accM[nt][3] * inv256);
            if (diag) {
                const int j0g = jt * 64 + col0;
                if (j0g     > i_g0) s00 = -1e9f;
                if (j0g + 1 > i_g0) s01 = -1e9f;
                if (j0g     > i_g1) s10 = -1e9f;
                if (j0g + 1 > i_g1) s11 = -1e9f;
            }
            s00 *= inv_sqrt_d; s01 *= inv_sqrt_d; s10 *= inv_sqrt_d; s11 *= inv_sqrt_d;
            sv[nt][0] = s00; sv[nt][1] = s01; sv[nt][2] = s10; sv[nt][3] = s11;
            rm0 = fmaxf(rm0, fmaxf(s00, s01));
            rm1 = fmaxf(rm1, fmaxf(s10, s11));
        }
        rm0 = fmaxf(rm0, __shfl_xor_sync(0xffffffffu, rm0, 1));
        rm0 = fmaxf(rm0, __shfl_xor_sync(0xffffffffu, rm0, 2));
        rm1 = fmaxf(rm1, __shfl_xor_sync(0xffffffffu, rm1, 1));
        rm1 = fmaxf(rm1, __shfl_xor_sync(0xffffffffu, rm1, 2));
        const float mn0 = fmaxf(m0, rm0), mn1 = fmaxf(m1, rm1);
        const float cr0 = __expf(m0 - mn0), cr1 = __expf(m1 - mn1);
        m0 = mn0; m1 = mn1;
        float rs0 = 0.f, rs1 = 0.f;
#pragma unroll
        for (int nt = 0; nt < 8; ++nt) {
            float p00 = __expf(sv[nt][0] - mn0);
            float p01 = __expf(sv[nt][1] - mn0);
            float p10 = __expf(sv[nt][2] - mn1);
            float p11 = __expf(sv[nt][3] - mn1);
            rs0 += p00 + p01; rs1 += p10 + p11;
            bf16 h00 = __float2bfloat16_rn(p00), h01 = __float2bfloat16_rn(p01);
            bf16 h10 = __float2bfloat16_rn(p10), h11 = __float2bfloat16_rn(p11);
            bf16 l00b = __float2bfloat16_rn(p00 - __bfloat162float(h00));
            bf16 l01b = __float2bfloat16_rn(p01 - __bfloat162float(h01));
            bf16 l10b = __float2bfloat16_rn(p10 - __bfloat162float(h10));
            bf16 l11b = __float2bfloat16_rn(p11 - __bfloat162float(h11));
            const uint32_t cofs = (uint32_t)((nt * 8 + 2 * tg) * 2);
            *(__nv_bfloat162*)(smem + APS_H + (mrow + g) * 144 + cofs)     = __nv_bfloat162(h00, h01);
            *(__nv_bfloat162*)(smem + APS_H + (mrow + g + 8) * 144 + cofs) = __nv_bfloat162(h10, h11);
            *(__nv_bfloat162*)(smem + APS_L + (mrow + g) * 144 + cofs)     = __nv_bfloat162(l00b, l01b);
            *(__nv_bfloat162*)(smem + APS_L + (mrow + g + 8) * 144 + cofs) = __nv_bfloat162(l10b, l11b);
        }
        rs0 += __shfl_xor_sync(0xffffffffu, rs0, 1);
        rs0 += __shfl_xor_sync(0xffffffffu, rs0, 2);
        rs1 += __shfl_xor_sync(0xffffffffu, rs1, 1);
        rs1 += __shfl_xor_sync(0xffffffffu, rs1, 2);
        l0 = l0 * cr0 + rs0;
        l1 = l1 * cr1 + rs1;
#pragma unroll
        for (int ot = 0; ot < 16; ++ot) {
            o_acc[ot][0] *= cr0; o_acc[ot][1] *= cr0;
            o_acc[ot][2] *= cr1; o_acc[ot][3] *= cr1;
        }
        __syncwarp();

#pragma unroll
        for (int ks = 0; ks < 4; ++ks) {
            uint32_t aH[4], aL[4];
            ldmx4(aH, pbH + ks * 32);
            ldmx4(aL, pbL + ks * 32);
#pragma unroll
            for (int vg = 0; vg < 8; ++vg) {
                uint32_t vb[4];
                ldmx4(vb, sb + AVT(buf) + (uint32_t)((vg * 16 + l15) * 144) + lhalf * 16 + ks * 32);
                mma_bf16(o_acc[2 * vg],     aH, vb[0], vb[2]);
                mma_bf16(o_acc[2 * vg],     aL, vb[0], vb[2]);
                mma_bf16(o_acc[2 * vg + 1], aH, vb[1], vb[3]);
                mma_bf16(o_acc[2 * vg + 1], aL, vb[1], vb[3]);
            }
        }
        __syncthreads();
        if (jt + 2 < ntiles) { ATT_ISSUE(buf, jt + 2); }
        CP_COMMIT();
    }

    const float li0 = 1.0f / l0, li1 = 1.0f / l1;
    float* orow0 = O + ((size_t)b * S_LEN + i0 + mrow + g)     * D_DIM + head * HD;
    float* orow1 = O + ((size_t)b * S_LEN + i0 + mrow + g + 8) * D_DIM + head * HD;
#pragma unroll
    for (int ot = 0; ot < 16; ++ot) {
        const int col = ot * 8 + 2 * tg;
        *(float2*)(orow0 + col) = make_float2(o_acc[ot][0] * li0, o_acc[ot][1] * li0);
        *(float2*)(orow1 + col) = make_float2(o_acc[ot][2] * li1, o_acc[ot][3] * li1);
    }
#undef ATT_ISSUE
}

// ===========================================================================
// Launch
// ===========================================================================
extern "C" void kernel_launch(void* const* d_in, const int* in_sizes, int n_in,
                              void* d_out, int out_size)
{
    (void)in_sizes; (void)n_in; (void)out_size;
    const float* x    = (const float*)d_in[0];
    const float* Wq   = (const float*)d_in[2];
    const float* Wk   = (const float*)d_in[3];
    const float* Wv   = (const float*)d_in[4];
    const float* Wo   = (const float*)d_in[5];
    const float* ln1g = (const float*)d_in[6];
    const float* ln1b = (const float*)d_in[7];
    const float* W1   = (const float*)d_in[8];
    const float* b1   = (const float*)d_in[9];
    const float* W2   = (const float*)d_in[10];
    const float* b2   = (const float*)d_in[11];
    const float* ln2g = (const float*)d_in[12];
    const float* ln2b = (const float*)d_in[13];
    float* out = (float*)d_out;

    int8_t *hq1, *hq2, *atq1, *atq2, *ffq1, *ffq2;
    float *hs, *ats, *ffs;
    float *attn, *x2, *ff;
    int8_t *qq1, *qq2, *kq1, *kq2;
    float *qsc, *ksc;
    bf16 *vbf, *vt;
    int8_t *wqkq1, *wqkq2, *wvq1, *wvq2, *woq1, *woq2, *w1q1, *w1q2, *w2q1, *w2q2;
    float *wqks, *wqam, *wkam, *wvam, *wvs, *woam, *wos, *w1am, *w1s, *w2am, *w2s;
    cudaGetSymbolAddress((void**)&hq1,  g_h_q1);
    cudaGetSymbolAddress((void**)&hq2,  g_h_q2);
    cudaGetSymbolAddress((void**)&hs,   g_h_s);
    cudaGetSymbolAddress((void**)&attn, g_attn);
    cudaGetSymbolAddress((void**)&atq1, g_at_q1);
    cudaGetSymbolAddress((void**)&atq2, g_at_q2);
    cudaGetSymbolAddress((void**)&ats,  g_at_s);
    cudaGetSymbolAddress((void**)&x2,   g_x2);
    cudaGetSymbolAddress((void**)&ff,   g_ff);
    cudaGetSymbolAddress((void**)&ffq1, g_ff_q1);
    cudaGetSymbolAddress((void**)&ffq2, g_ff_q2);
    cudaGetSymbolAddress((void**)&ffs,  g_ff_s);
    cudaGetSymbolAddress((void**)&qq1,  g_q_q1);
    cudaGetSymbolAddress((void**)&qq2,  g_q_q2);
    cudaGetSymbolAddress((void**)&qsc,  g_q_sc);
    cudaGetSymbolAddress((void**)&kq1,  g_k_q1);
    cudaGetSymbolAddress((void**)&kq2,  g_k_q2);
    cudaGetSymbolAddress((void**)&ksc,  g_k_sc);
    cudaGetSymbolAddress((void**)&vbf,  g_vbf);
    cudaGetSymbolAddress((void**)&vt,   g_vt);
    cudaGetSymbolAddress((void**)&wqkq1, g_wqk_q1);
    cudaGetSymbolAddress((void**)&wqkq2, g_wqk_q2);
    cudaGetSymbolAddress((void**)&wqks,  g_wqk_s);
    cudaGetSymbolAddress((void**)&wqam,  g_wq_am);
    cudaGetSymbolAddress((void**)&wkam,  g_wk_am);
    cudaGetSymbolAddress((void**)&wvq1, g_wv_q1);
    cudaGetSymbolAddress((void**)&wvq2, g_wv_q2);
    cudaGetSymbolAddress((void**)&wvam, g_wv_am);
    cudaGetSymbolAddress((void**)&wvs,  g_wv_s);
    cudaGetSymbolAddress((void**)&woq1, g_wo_q1);
    cudaGetSymbolAddress((void**)&woq2, g_wo_q2);
    cudaGetSymbolAddress((void**)&woam, g_wo_am);
    cudaGetSymbolAddress((void**)&wos,  g_wo_s);
    cudaGetSymbolAddress((void**)&w1q1, g_w1_q1);
    cudaGetSymbolAddress((void**)&w1q2, g_w1_q2);
    cudaGetSymbolAddress((void**)&w1am, g_w1_am);
    cudaGetSymbolAddress((void**)&w1s,  g_w1_s);
    cudaGetSymbolAddress((void**)&w2q1, g_w2_q1);
    cudaGetSymbolAddress((void**)&w2q2, g_w2_q2);
    cudaGetSymbolAddress((void**)&w2am, g_w2_am);
    cudaGetSymbolAddress((void**)&w2s,  g_w2_s);

    cudaFuncSetAttribute(attn_i8,
                         cudaFuncAttributeMaxDynamicSharedMemorySize, ATT_SMEM);
    cudaFuncSetAttribute(gemm_i8<0, false, false, true>,
                         cudaFuncAttributeMaxDynamicSharedMemorySize, I8_SMEM);
    cudaFuncSetAttribute(gemm_i8<0, true, true, false>,
                         cudaFuncAttributeMaxDynamicSharedMemorySize, I8_SMEM);
    cudaFuncSetAttribute(gemm_i8<0, false, true, true>,
                         cudaFuncAttributeMaxDynamicSharedMemorySize, I8_SMEM);
    cudaFuncSetAttribute(gemm_i8<1, false, false, false>,
                         cudaFuncAttributeMaxDynamicSharedMemorySize, I8_SMEM);
    cudaFuncSetAttribute(gemm_i8<2, false, false, false>,
                         cudaFuncAttributeMaxDynamicSharedMemorySize, I8_SMEM);

    const dim3 blk(256);
    const dim3 blkG(512);

    // ---- weight prep ----
    cudaMemsetAsync(wqam, 0, D_DIM * sizeof(float));
    cudaMemsetAsync(wkam, 0, D_DIM * sizeof(float));
    cudaMemsetAsync(wvam, 0, D_DIM * sizeof(float));
    cudaMemsetAsync(woam, 0, D_DIM * sizeof(float));
    cudaMemsetAsync(w1am, 0, M_FF * sizeof(float));
    cudaMemsetAsync(w2am, 0, D_DIM * sizeof(float));
    colamax_kernel<<<dim3(64, 64),  blk>>>(Wq, D_DIM, D_DIM, wqam);
    colamax_kernel<<<dim3(64, 64),  blk>>>(Wk, D_DIM, D_DIM, wkam);
    colamax_kernel<<<dim3(64, 64),  blk>>>(Wv, D_DIM, D_DIM, wvam);
    colamax_kernel<<<dim3(64, 64),  blk>>>(Wo, D_DIM, D_DIM, woam);
    colamax_kernel<<<dim3(M_FF / 32,  D_DIM / 32), blk>>>(W1, D_DIM, M_FF, w1am);
    colamax_kernel<<<dim3(D_DIM / 32, M_FF / 32),  blk>>>(W2, M_FF, D_DIM, w2am);
    // Wq -> rows 0..2047, Wk -> rows 2048..4095 of the stacked QK weight
    transpose_quant_i8<<<dim3(64, 64),  blk>>>(Wq, wqam, wqkq1, wqkq2, wqks, D_DIM, D_DIM);
    transpose_quant_i8<<<dim3(64, 64),  blk>>>(Wk, wkam,
        wqkq1 + (size_t)D_DIM * D_DIM, wqkq2 + (size_t)D_DIM * D_DIM,
        wqks + D_DIM, D_DIM, D_DIM);
    transpose_quant_i8<<<dim3(64, 64),  blk>>>(Wv, wvam, wvq1, wvq2, wvs, D_DIM, D_DIM);
    transpose_quant_i8<<<dim3(64, 64),  blk>>>(Wo, woam, woq1, woq2, wos, D_DIM, D_DIM);
    transpose_quant_i8<<<dim3(256, 64), blk>>>(W1, w1am, w1q1, w1q2, w1s, D_DIM, M_FF);
    transpose_quant_i8<<<dim3(64, 256), blk>>>(W2, w2am, w2q1, w2q2, w2s, M_FF, D_DIM);

    const dim3 gQK(32, 32);                    // N=4096 combined
    const dim3 gDD(D_DIM / 128, ROWS / 128);   // (16, 32)
    const dim3 gDM(M_FF / 128,  ROWS / 128);   // (64, 32)

    // ---- layer ----
    ln_quant_i8<<<ROWS, blk>>>(x, ln1g, ln1b, hq1, hq2, hs);
    // QK combined GEMM with fused per-segment quantization epilogue
    gemm_i8<1, false, false, false><<<gQK, blkG, I8_SMEM>>>(
        hq1, hq2, wqkq1, wqkq2, hs, wqks, nullptr, nullptr, nullptr, nullptr,
        qq1, qq2, qsc, kq1, kq2, ksc, 2 * D_DIM, D_DIM);
    // V GEMM -> bf16
    gemm_i8<2, false, false, false><<<gDD, blkG, I8_SMEM>>>(
        hq1, hq2, wvq1, wvq2, hs, wvs, nullptr, nullptr, nullptr, vbf,
        nullptr, nullptr, nullptr, nullptr, nullptr, nullptr, D_DIM, D_DIM);
    vt_split<<<dim3(S_LEN / 32, HD / 32, B_SZ * NH), blk>>>(vbf, vt);
    attn_i8<<<dim3(S_LEN / 128, NH, B_SZ), blk, ATT_SMEM>>>(
        qq1, qq2, qsc, kq1, kq2, ksc, vt, attn);
    rowquant_i8<<<ROWS, blk>>>(attn, D_DIM, atq1, atq2, ats);
    gemm_i8<0, false, false, true><<<gDD, blkG, I8_SMEM>>>(
        atq1, atq2, woq1, woq2, ats, wos, nullptr, x, x2, nullptr,
        nullptr, nullptr, nullptr, nullptr, nullptr, nullptr, D_DIM, D_DIM);
    ln_quant_i8<<<ROWS, blk>>>(x2, ln2g, ln2b, hq1, hq2, hs);
    gemm_i8<0, true, true, false><<<gDM, blkG, I8_SMEM>>>(
        hq1, hq2, w1q1, w1q2, hs, w1s, b1, nullptr, ff, nullptr,
        nullptr, nullptr, nullptr, nullptr, nullptr, nullptr, M_FF, D_DIM);
    rowquant_i8<<<ROWS, blk>>>(ff, M_FF, ffq1, ffq2, ffs);
    gemm_i8<0, false, true, true><<<gDD, blkG, I8_SMEM>>>(
        ffq1, ffq2, w2q1, w2q2, ffs, w2s, b2, x2, out, nullptr,
        nullptr, nullptr, nullptr, nullptr, nullptr, nullptr, D_DIM, M_FF);
}